// round 1
// baseline (speedup 1.0000x reference)
#include <cuda_runtime.h>
#include <math.h>

#define S_  4
#define E_  8
#define D_  384
#define H1_ 160
#define H2_ 128
#define H3_ 96
#define N_  40000
#define TM  64                       // atoms per tile
#define KT  16                       // k-chunk for weight staging
#define AST 65                       // padded m-stride for k-major activation buffers
#define NT  ((N_ + TM - 1) / TM)     // 625 tiles per species
#define NB  ((N_ + 255) / 256)       // 157 blocks for bucketing passes

typedef unsigned long long ull;

// ---------------- device scratch (no allocations allowed) ----------------
__device__ int   g_is64;
__device__ int   g_blockCnt[NB * S_];
__device__ int   g_blockOff[NB * S_];
__device__ int   g_count[S_];
__device__ int   g_idx[S_ * N_];
__device__ float g_partial[NT * S_];

// ---------------- packed fp32x2 helpers (FFMA2) ----------------
static __device__ __forceinline__ ull pack2(float lo, float hi) {
    ull r; asm("mov.b64 %0, {%1, %2};" : "=l"(r) : "f"(lo), "f"(hi)); return r;
}
static __device__ __forceinline__ ull ffma2(ull a, ull b, ull c) {
    ull d; asm("fma.rn.f32x2 %0, %1, %2, %3;" : "=l"(d) : "l"(a), "l"(b), "l"(c)); return d;
}
static __device__ __forceinline__ float2 unpk(ull v) {
    float2 f; asm("mov.b64 {%0, %1}, %2;" : "=f"(f.x), "=f"(f.y) : "l"(v)); return f;
}
static __device__ __forceinline__ float celu_f(float x) {
    return x > 0.f ? x : 0.1f * expm1f(x * 10.f);   // alpha = 0.1
}

// ---------------- pass 0: zero partials + detect int64 vs int32 species ----------------
__global__ void k_init(const ull* spq) {
    int tid = threadIdx.x;
    for (int i = tid; i < NT * S_; i += 256) g_partial[i] = 0.f;
    if (tid < 32) {
        ull v = spq[tid];
        int hiNZ = ((v >> 32) != 0ull) ? 1 : 0;
        int any = __any_sync(0xffffffffu, hiNZ);
        if (tid == 0) g_is64 = any ? 0 : 1;   // int64 species always have hi word 0
    }
}

// ---------------- pass 1: per-block species histogram ----------------
__global__ void k_count(const int* sp) {
    int tid = threadIdx.x, b = blockIdx.x;
    int n = b * 256 + tid;
    int shift = g_is64;                       // int64 -> read low 32-bit word at index 2n
    int spv = -1;
    if (n < N_) spv = sp[(size_t)n << shift];
    __shared__ int wc[8][4];
    if (tid < 32) wc[tid >> 2][tid & 3] = 0;
    __syncthreads();
    unsigned mm = __match_any_sync(0xffffffffu, spv);
    int lane = tid & 31, w = tid >> 5;
    if (spv >= 0 && lane == (__ffs(mm) - 1)) wc[w][spv] = __popc(mm);
    __syncthreads();
    if (tid < 4) {
        int s = 0;
        for (int ww = 0; ww < 8; ww++) s += wc[ww][tid];
        g_blockCnt[b * 4 + tid] = s;
    }
}

// ---------------- pass 2: exclusive scan over block histograms (deterministic) ----------------
__global__ void k_scan() {
    __shared__ int c[NB * 4];
    __shared__ int o[NB * 4];
    int tid = threadIdx.x;
    for (int i = tid; i < NB * 4; i += 256) c[i] = g_blockCnt[i];
    __syncthreads();
    if (tid == 0) {
        int r0 = 0, r1 = 0, r2 = 0, r3 = 0;
        for (int b = 0; b < NB; b++) {
            o[b * 4 + 0] = r0; r0 += c[b * 4 + 0];
            o[b * 4 + 1] = r1; r1 += c[b * 4 + 1];
            o[b * 4 + 2] = r2; r2 += c[b * 4 + 2];
            o[b * 4 + 3] = r3; r3 += c[b * 4 + 3];
        }
        g_count[0] = r0; g_count[1] = r1; g_count[2] = r2; g_count[3] = r3;
    }
    __syncthreads();
    for (int i = tid; i < NB * 4; i += 256) g_blockOff[i] = o[i];
}

// ---------------- pass 3: deterministic scatter into species-sorted index lists ----------------
__global__ void k_scatter(const int* sp) {
    int tid = threadIdx.x, b = blockIdx.x;
    int n = b * 256 + tid;
    int shift = g_is64;
    int spv = -1;
    if (n < N_) spv = sp[(size_t)n << shift];
    __shared__ int wc[8][4];
    __shared__ int woff[8][4];
    if (tid < 32) wc[tid >> 2][tid & 3] = 0;
    __syncthreads();
    unsigned mm = __match_any_sync(0xffffffffu, spv);
    int lane = tid & 31, w = tid >> 5;
    int rank = __popc(mm & ((1u << lane) - 1u));
    if (spv >= 0 && lane == (__ffs(mm) - 1)) wc[w][spv] = __popc(mm);
    __syncthreads();
    if (tid < 4) {
        int run = g_blockOff[b * 4 + tid];
        for (int ww = 0; ww < 8; ww++) { woff[ww][tid] = run; run += wc[ww][tid]; }
    }
    __syncthreads();
    if (spv >= 0) g_idx[spv * N_ + woff[w][spv] + rank] = n;
}

// ---------------- GEMM layer, A resident in SMEM (k-major, stride AST) ----------------
// 256 threads = 16(tx: col groups) x 16(ty: atom groups). Per thread: 4 atoms x NPT cols.
// Accumulators packed over column pairs -> weight pairs load as LDS.64, math is FFMA2.
template<int K, int NOUT, int NPT>
static __device__ __forceinline__ void layer_smem(
    const float* As, float* Os,
    const float* __restrict__ Wg, const float* __restrict__ bg,
    float* Wt, int tid, bool docelu)
{
    constexpr int NC = NPT / 2;
    const int tx = tid & 15, ty = tid >> 4;
    const int m0 = ty * 4, col0 = tx * NPT;

    ull acc[4][NC];
#pragma unroll
    for (int c = 0; c < NC; c++) {
        ull b2 = pack2(bg[col0 + 2 * c], bg[col0 + 2 * c + 1]);
#pragma unroll
        for (int j = 0; j < 4; j++) acc[j][c] = b2;
    }

    for (int kc = 0; kc < K; kc += KT) {
        __syncthreads();
        for (int i = tid; i < KT * NOUT; i += 256) Wt[i] = Wg[kc * NOUT + i];
        __syncthreads();
#pragma unroll
        for (int kk = 0; kk < KT; kk++) {
            const float* arow = As + (kc + kk) * AST + m0;
            ull a2[4];
#pragma unroll
            for (int j = 0; j < 4; j++) { float a = arow[j]; a2[j] = pack2(a, a); }
            const ull* wrow = (const ull*)(Wt + kk * NOUT + col0);
#pragma unroll
            for (int c = 0; c < NC; c++) {
                ull w2 = wrow[c];
#pragma unroll
                for (int j = 0; j < 4; j++) acc[j][c] = ffma2(a2[j], w2, acc[j][c]);
            }
        }
    }
    __syncthreads();
#pragma unroll
    for (int c = 0; c < NC; c++)
#pragma unroll
        for (int j = 0; j < 4; j++) {
            float2 v = unpk(acc[j][c]);
            if (docelu) { v.x = celu_f(v.x); v.y = celu_f(v.y); }
            Os[(col0 + 2 * c) * AST + m0 + j]     = v.x;
            Os[(col0 + 2 * c + 1) * AST + m0 + j] = v.y;
        }
}

// ---------------- layer 1: A gathered from gmem in KT-chunks ----------------
static __device__ __forceinline__ void layer1(
    const float* __restrict__ aev, const int* sidx,
    float* Xa, float* Os,
    const float* __restrict__ Wg, const float* __restrict__ bg,
    float* Wt, int tid)
{
    constexpr int NPT = 10, NC = 5, NOUT = H1_;
    const int tx = tid & 15, ty = tid >> 4;
    const int m0 = ty * 4, col0 = tx * NPT;
    const int smm = tid >> 2;             // staging atom 0..63
    const int skq = (tid & 3) * 4;        // staging k sub-offset {0,4,8,12}
    const float* arowg = aev + (size_t)sidx[smm] * D_ + skq;

    ull acc[4][NC];
#pragma unroll
    for (int c = 0; c < NC; c++) {
        ull b2 = pack2(bg[col0 + 2 * c], bg[col0 + 2 * c + 1]);
#pragma unroll
        for (int j = 0; j < 4; j++) acc[j][c] = b2;
    }

    for (int kc = 0; kc < D_; kc += KT) {
        __syncthreads();
        {   // gather X chunk [KT x TM], transposed k-major into Xa
            float4 v = *(const float4*)(arowg + kc);
            Xa[(skq + 0) * AST + smm] = v.x;
            Xa[(skq + 1) * AST + smm] = v.y;
            Xa[(skq + 2) * AST + smm] = v.z;
            Xa[(skq + 3) * AST + smm] = v.w;
        }
        for (int i = tid; i < KT * NOUT; i += 256) Wt[i] = Wg[kc * NOUT + i];
        __syncthreads();
#pragma unroll
        for (int kk = 0; kk < KT; kk++) {
            const float* arow = Xa + kk * AST + m0;
            ull a2[4];
#pragma unroll
            for (int j = 0; j < 4; j++) { float a = arow[j]; a2[j] = pack2(a, a); }
            const ull* wrow = (const ull*)(Wt + kk * NOUT + col0);
#pragma unroll
            for (int c = 0; c < NC; c++) {
                ull w2 = wrow[c];
#pragma unroll
                for (int j = 0; j < 4; j++) acc[j][c] = ffma2(a2[j], w2, acc[j][c]);
            }
        }
    }
    __syncthreads();
#pragma unroll
    for (int c = 0; c < NC; c++)
#pragma unroll
        for (int j = 0; j < 4; j++) {
            float2 v = unpk(acc[j][c]);
            v.x = celu_f(v.x); v.y = celu_f(v.y);
            Os[(col0 + 2 * c) * AST + m0 + j]     = v.x;
            Os[(col0 + 2 * c + 1) * AST + m0 + j] = v.y;
        }
}

// ---------------- main fused MLP kernel ----------------
// grid = (NT, S). Each block: 64 atoms of one species, loops all 8 ensemble members.
#define SMEM_FLOATS (H1_ * AST + H2_ * AST + KT * AST + KT * H1_ + H3_ + TM + TM)
#define SMEM_BYTES  (SMEM_FLOATS * 4)

__global__ void __launch_bounds__(256, 2) k_main(
    const float* __restrict__ aev,
    const float* __restrict__ W1, const float* __restrict__ b1,
    const float* __restrict__ W2, const float* __restrict__ b2,
    const float* __restrict__ W3, const float* __restrict__ b3,
    const float* __restrict__ W4, const float* __restrict__ b4)
{
    const int s = blockIdx.y, t = blockIdx.x, tid = threadIdx.x;
    const int cnt  = g_count[s];
    const int base = t * TM;
    if (base >= cnt) return;
    const int nvalid = min(TM, cnt - base);

    extern __shared__ float smf[];
    float* R1  = smf;                 // [H1][AST], reused as H3 output
    float* R2  = R1 + H1_ * AST;      // [H2][AST]
    float* Xa  = R2 + H2_ * AST;      // [KT][AST] gather staging
    float* Wt  = Xa + KT * AST;       // [KT][<=H1] weight staging
    float* w4s = Wt + KT * H1_;       // [H3]
    float* eat = w4s + H3_;           // [TM]
    int*  sidx = (int*)(eat + TM);    // [TM]

    if (tid < TM) {
        int p = base + tid; if (p >= cnt) p = cnt - 1;   // clamp tail to a valid atom
        sidx[tid] = g_idx[s * N_ + p];
    }
    __syncthreads();

    float blockSum = 0.f;

    for (int e = 0; e < E_; e++) {
        const int se = s * E_ + e;
        layer1(aev, sidx, Xa, R1,
               W1 + (size_t)se * D_ * H1_, b1 + (size_t)se * H1_, Wt, tid);
        layer_smem<H1_, H2_, 8>(R1, R2,
               W2 + (size_t)se * H1_ * H2_, b2 + (size_t)se * H2_, Wt, tid, true);
        layer_smem<H2_, H3_, 6>(R2, R1,
               W3 + (size_t)se * H2_ * H3_, b3 + (size_t)se * H3_, Wt, tid, true);

        // ---- layer 4: per-atom dot(h3[96], w4) + b4 ----
        if (tid < H3_) w4s[tid] = W4[(size_t)se * H3_ + tid];
        __syncthreads();
        {
            int m = tid >> 2, q = tid & 3;     // 4 threads per atom, 24 k each
            float ss = 0.f;
            const float* hc = R1 + (q * 24) * AST + m;
#pragma unroll
            for (int k = 0; k < 24; k++) ss += hc[k * AST] * w4s[q * 24 + k];
            ss += __shfl_xor_sync(0xffffffffu, ss, 1);
            ss += __shfl_xor_sync(0xffffffffu, ss, 2);
            if (q == 0) eat[m] = (m < nvalid) ? (ss + b4[se]) : 0.f;
        }
        __syncthreads();
        if (tid < 32) {
            float v = eat[tid] + eat[tid + 32];
            for (int o = 16; o; o >>= 1) v += __shfl_down_sync(0xffffffffu, v, o);
            if (tid == 0) blockSum += v;
        }
        __syncthreads();   // R1/R2 reused next ensemble member
    }

    if (tid == 0) g_partial[s * NT + t] = blockSum;
}

// ---------------- final deterministic reduction ----------------
__global__ void k_reduce(float* out) {
    __shared__ double sb[256];
    int tid = threadIdx.x;
    double s = 0.0;
    for (int i = tid; i < NT * S_; i += 256) s += (double)g_partial[i];
    sb[tid] = s;
    __syncthreads();
    for (int st = 128; st; st >>= 1) {
        if (tid < st) sb[tid] += sb[tid + st];
        __syncthreads();
    }
    if (tid == 0) out[0] = (float)(sb[0] * (1.0 / E_));
}

// ---------------- launch ----------------
extern "C" void kernel_launch(void* const* d_in, const int* in_sizes, int n_in,
                              void* d_out, int out_size)
{
    const void*  sp  = d_in[0];
    const float* aev = (const float*)d_in[1];
    const float* W1  = (const float*)d_in[2];
    const float* b1  = (const float*)d_in[3];
    const float* W2  = (const float*)d_in[4];
    const float* b2  = (const float*)d_in[5];
    const float* W3  = (const float*)d_in[6];
    const float* b3  = (const float*)d_in[7];
    const float* W4  = (const float*)d_in[8];
    const float* b4  = (const float*)d_in[9];

    cudaFuncSetAttribute(k_main, cudaFuncAttributeMaxDynamicSharedMemorySize, SMEM_BYTES);

    k_init<<<1, 256>>>((const ull*)sp);
    k_count<<<NB, 256>>>((const int*)sp);
    k_scan<<<1, 256>>>();
    k_scatter<<<NB, 256>>>((const int*)sp);

    dim3 grid(NT, S_);
    k_main<<<grid, 256, SMEM_BYTES>>>(aev, W1, b1, W2, b2, W3, b3, W4, b4);

    k_reduce<<<1, 256>>>((float*)d_out);
}

// round 2
// speedup vs baseline: 1.1842x; 1.1842x over previous
#include <cuda_runtime.h>
#include <math.h>

#define S_  4
#define E_  8
#define D_  384
#define H1_ 160
#define H2_ 128
#define H3_ 96
#define N_  40000
#define TM  128                      // atoms per tile
#define KT  16                       // k-chunk for staging
#define MS  132                      // padded m-stride (mult of 4 for LDS.128)
#define NT  ((N_ + TM - 1) / TM)     // 313 tiles (worst case one species)
#define NB  ((N_ + 255) / 256)       // 157 blocks for bucketing passes
#define NPART (NT * S_ * 2)

typedef unsigned long long ull;

// ---------------- device scratch (no allocations allowed) ----------------
__device__ int   g_is64;
__device__ int   g_blockCnt[NB * S_];
__device__ int   g_blockOff[NB * S_];
__device__ int   g_count[S_];
__device__ int   g_idx[S_ * N_];
__device__ float g_partial[NPART];

// ---------------- packed fp32x2 helpers (FFMA2) ----------------
static __device__ __forceinline__ ull pack2(float lo, float hi) {
    ull r; asm("mov.b64 %0, {%1, %2};" : "=l"(r) : "f"(lo), "f"(hi)); return r;
}
static __device__ __forceinline__ ull ffma2(ull a, ull b, ull c) {
    ull d; asm("fma.rn.f32x2 %0, %1, %2, %3;" : "=l"(d) : "l"(a), "l"(b), "l"(c)); return d;
}
static __device__ __forceinline__ float2 unpk(ull v) {
    float2 f; asm("mov.b64 {%0, %1}, %2;" : "=f"(f.x), "=f"(f.y) : "l"(v)); return f;
}
static __device__ __forceinline__ float celu_f(float x) {
    return x > 0.f ? x : 0.1f * expm1f(x * 10.f);   // alpha = 0.1
}

// ---------------- pass 0: zero partials + detect int64 vs int32 species ----------------
__global__ void k_init(const ull* spq) {
    int tid = threadIdx.x;
    for (int i = tid; i < NPART; i += 256) g_partial[i] = 0.f;
    if (tid < 32) {
        ull v = spq[tid];
        int hiNZ = ((v >> 32) != 0ull) ? 1 : 0;
        int any = __any_sync(0xffffffffu, hiNZ);
        if (tid == 0) g_is64 = any ? 0 : 1;   // int64 species always have hi word 0
    }
}

// ---------------- pass 1: per-block species histogram ----------------
__global__ void k_count(const int* sp) {
    int tid = threadIdx.x, b = blockIdx.x;
    int n = b * 256 + tid;
    int shift = g_is64;
    int spv = -1;
    if (n < N_) spv = sp[(size_t)n << shift];
    __shared__ int wc[8][4];
    if (tid < 32) wc[tid >> 2][tid & 3] = 0;
    __syncthreads();
    unsigned mm = __match_any_sync(0xffffffffu, spv);
    int lane = tid & 31, w = tid >> 5;
    if (spv >= 0 && lane == (__ffs(mm) - 1)) wc[w][spv] = __popc(mm);
    __syncthreads();
    if (tid < 4) {
        int s = 0;
        for (int ww = 0; ww < 8; ww++) s += wc[ww][tid];
        g_blockCnt[b * 4 + tid] = s;
    }
}

// ---------------- pass 2: exclusive scan over block histograms ----------------
__global__ void k_scan() {
    __shared__ int c[NB * 4];
    __shared__ int o[NB * 4];
    int tid = threadIdx.x;
    for (int i = tid; i < NB * 4; i += 256) c[i] = g_blockCnt[i];
    __syncthreads();
    if (tid == 0) {
        int r0 = 0, r1 = 0, r2 = 0, r3 = 0;
        for (int b = 0; b < NB; b++) {
            o[b * 4 + 0] = r0; r0 += c[b * 4 + 0];
            o[b * 4 + 1] = r1; r1 += c[b * 4 + 1];
            o[b * 4 + 2] = r2; r2 += c[b * 4 + 2];
            o[b * 4 + 3] = r3; r3 += c[b * 4 + 3];
        }
        g_count[0] = r0; g_count[1] = r1; g_count[2] = r2; g_count[3] = r3;
    }
    __syncthreads();
    for (int i = tid; i < NB * 4; i += 256) g_blockOff[i] = o[i];
}

// ---------------- pass 3: deterministic scatter ----------------
__global__ void k_scatter(const int* sp) {
    int tid = threadIdx.x, b = blockIdx.x;
    int n = b * 256 + tid;
    int shift = g_is64;
    int spv = -1;
    if (n < N_) spv = sp[(size_t)n << shift];
    __shared__ int wc[8][4];
    __shared__ int woff[8][4];
    if (tid < 32) wc[tid >> 2][tid & 3] = 0;
    __syncthreads();
    unsigned mm = __match_any_sync(0xffffffffu, spv);
    int lane = tid & 31, w = tid >> 5;
    int rank = __popc(mm & ((1u << lane) - 1u));
    if (spv >= 0 && lane == (__ffs(mm) - 1)) wc[w][spv] = __popc(mm);
    __syncthreads();
    if (tid < 4) {
        int run = g_blockOff[b * 4 + tid];
        for (int ww = 0; ww < 8; ww++) { woff[ww][tid] = run; run += wc[ww][tid]; }
    }
    __syncthreads();
    if (spv >= 0) g_idx[spv * N_ + woff[w][spv] + rank] = n;
}

// ============== GEMM layer (A in SMEM, k-major, stride MS) ==============
// 256 threads = 8(tx) x 32(ty). Per thread: 4 atoms (m0=ty*4) x C column-pairs.
// Weights staged double-buffered in pair-transposed layout:
//   pair p stored at u = (p%C)*8 + p/C  ->  thread tx reads pairs tx*C+c at u=c*8+tx
//   => LDS.64 consecutive across tx => conflict-free.
template<int K, int NOUT, int C>
static __device__ __forceinline__ void layer_ff(
    const float* __restrict__ As, float* __restrict__ Os,
    const float* __restrict__ Wg, const float* __restrict__ bg,
    float* WtA, float* WtB, int tid, bool docelu)
{
    constexpr int NCH = K / KT;
    constexpr int WPT = KT * NOUT / 256;
    const int tx = tid & 7, ty = tid >> 3;
    const int m0 = ty * 4;
    const int pc0 = tx * C;

    ull acc[4][C];
#pragma unroll
    for (int c = 0; c < C; c++) {
        ull b2 = pack2(bg[2 * (pc0 + c)], bg[2 * (pc0 + c) + 1]);
#pragma unroll
        for (int j = 0; j < 4; j++) acc[j][c] = b2;
    }

    float wr[WPT];
#pragma unroll
    for (int i = 0; i < WPT; i++) wr[i] = Wg[tid + i * 256];
#pragma unroll
    for (int i = 0; i < WPT; i++) {
        int idx = tid + i * 256, kk = idx / NOUT, j = idx % NOUT;
        int p = j >> 1, r = j & 1, u = (p % C) * 8 + p / C;
        WtA[kk * NOUT + u * 2 + r] = wr[i];
    }
    __syncthreads();

    for (int kc = 0; kc < NCH; kc++) {
        const float* Wt = (kc & 1) ? WtB : WtA;
        float* Wn = (kc & 1) ? WtA : WtB;
        if (kc + 1 < NCH) {
#pragma unroll
            for (int i = 0; i < WPT; i++)
                wr[i] = Wg[(kc + 1) * KT * NOUT + tid + i * 256];
        }
#pragma unroll 2
        for (int kk = 0; kk < KT; kk++) {
            const float4 av = *(const float4*)(As + (kc * KT + kk) * MS + m0);
            ull a0 = pack2(av.x, av.x), a1 = pack2(av.y, av.y);
            ull a2 = pack2(av.z, av.z), a3 = pack2(av.w, av.w);
            const ull* wrow = (const ull*)(Wt + kk * NOUT);
#pragma unroll
            for (int c = 0; c < C; c++) {
                ull w2 = wrow[c * 8 + tx];
                acc[0][c] = ffma2(a0, w2, acc[0][c]);
                acc[1][c] = ffma2(a1, w2, acc[1][c]);
                acc[2][c] = ffma2(a2, w2, acc[2][c]);
                acc[3][c] = ffma2(a3, w2, acc[3][c]);
            }
        }
        if (kc + 1 < NCH) {
#pragma unroll
            for (int i = 0; i < WPT; i++) {
                int idx = tid + i * 256, kk2 = idx / NOUT, j = idx % NOUT;
                int p = j >> 1, r = j & 1, u = (p % C) * 8 + p / C;
                Wn[kk2 * NOUT + u * 2 + r] = wr[i];
            }
        }
        __syncthreads();
    }

#pragma unroll
    for (int c = 0; c < C; c++) {
        int col = 2 * (pc0 + c);
#pragma unroll
        for (int j = 0; j < 4; j++) {
            float2 v = unpk(acc[j][c]);
            if (docelu) { v.x = celu_f(v.x); v.y = celu_f(v.y); }
            Os[col * MS + m0 + j]       = v.x;
            Os[(col + 1) * MS + m0 + j] = v.y;
        }
    }
}

// ============== layer 1: A gathered from gmem, double-buffered ==============
static __device__ __forceinline__ void layer1_ff(
    const float* __restrict__ aev, const int* sidx,
    float* XaA, float* XaB, float* __restrict__ Os,
    const float* __restrict__ Wg, const float* __restrict__ bg,
    float* WtA, float* WtB, int tid)
{
    constexpr int NOUT = H1_, C = 10;
    constexpr int NCH = D_ / KT;             // 24
    constexpr int WPT = KT * NOUT / 256;     // 10
    const int tx = tid & 7, ty = tid >> 3;
    const int m0 = ty * 4;
    const int pc0 = tx * C;
    const int am = tid >> 1, ko = (tid & 1) * 8;   // gather role: atom, k sub-offset
    const float* ap = aev + (size_t)sidx[am] * D_ + ko;

    ull acc[4][C];
#pragma unroll
    for (int c = 0; c < C; c++) {
        ull b2 = pack2(bg[2 * (pc0 + c)], bg[2 * (pc0 + c) + 1]);
#pragma unroll
        for (int j = 0; j < 4; j++) acc[j][c] = b2;
    }

    float wr[WPT];
    float4 x0, x1;
#pragma unroll
    for (int i = 0; i < WPT; i++) wr[i] = Wg[tid + i * 256];
    x0 = *(const float4*)(ap);
    x1 = *(const float4*)(ap + 4);
#pragma unroll
    for (int i = 0; i < WPT; i++) {
        int idx = tid + i * 256, kk = idx / NOUT, j = idx % NOUT;
        int p = j >> 1, r = j & 1, u = (p % C) * 8 + p / C;
        WtA[kk * NOUT + u * 2 + r] = wr[i];
    }
    XaA[(ko + 0) * MS + am] = x0.x; XaA[(ko + 1) * MS + am] = x0.y;
    XaA[(ko + 2) * MS + am] = x0.z; XaA[(ko + 3) * MS + am] = x0.w;
    XaA[(ko + 4) * MS + am] = x1.x; XaA[(ko + 5) * MS + am] = x1.y;
    XaA[(ko + 6) * MS + am] = x1.z; XaA[(ko + 7) * MS + am] = x1.w;
    __syncthreads();

    for (int kc = 0; kc < NCH; kc++) {
        const float* Wt = (kc & 1) ? WtB : WtA;
        float* Wn = (kc & 1) ? WtA : WtB;
        const float* Xa = (kc & 1) ? XaB : XaA;
        float* Xn = (kc & 1) ? XaA : XaB;
        if (kc + 1 < NCH) {
#pragma unroll
            for (int i = 0; i < WPT; i++)
                wr[i] = Wg[(kc + 1) * KT * NOUT + tid + i * 256];
            x0 = *(const float4*)(ap + (kc + 1) * KT);
            x1 = *(const float4*)(ap + (kc + 1) * KT + 4);
        }
#pragma unroll 2
        for (int kk = 0; kk < KT; kk++) {
            const float4 av = *(const float4*)(Xa + kk * MS + m0);
            ull a0 = pack2(av.x, av.x), a1 = pack2(av.y, av.y);
            ull a2 = pack2(av.z, av.z), a3 = pack2(av.w, av.w);
            const ull* wrow = (const ull*)(Wt + kk * NOUT);
#pragma unroll
            for (int c = 0; c < C; c++) {
                ull w2 = wrow[c * 8 + tx];
                acc[0][c] = ffma2(a0, w2, acc[0][c]);
                acc[1][c] = ffma2(a1, w2, acc[1][c]);
                acc[2][c] = ffma2(a2, w2, acc[2][c]);
                acc[3][c] = ffma2(a3, w2, acc[3][c]);
            }
        }
        if (kc + 1 < NCH) {
#pragma unroll
            for (int i = 0; i < WPT; i++) {
                int idx = tid + i * 256, kk2 = idx / NOUT, j = idx % NOUT;
                int p = j >> 1, r = j & 1, u = (p % C) * 8 + p / C;
                Wn[kk2 * NOUT + u * 2 + r] = wr[i];
            }
            Xn[(ko + 0) * MS + am] = x0.x; Xn[(ko + 1) * MS + am] = x0.y;
            Xn[(ko + 2) * MS + am] = x0.z; Xn[(ko + 3) * MS + am] = x0.w;
            Xn[(ko + 4) * MS + am] = x1.x; Xn[(ko + 5) * MS + am] = x1.y;
            Xn[(ko + 6) * MS + am] = x1.z; Xn[(ko + 7) * MS + am] = x1.w;
        }
        __syncthreads();
    }

#pragma unroll
    for (int c = 0; c < C; c++) {
        int col = 2 * (pc0 + c);
#pragma unroll
        for (int j = 0; j < 4; j++) {
            float2 v = unpk(acc[j][c]);
            v.x = celu_f(v.x); v.y = celu_f(v.y);
            Os[col * MS + m0 + j]       = v.x;
            Os[(col + 1) * MS + m0 + j] = v.y;
        }
    }
}

// ---------------- main fused MLP kernel ----------------
// grid = (NT, S, 2). Each block: 128 atoms of one species, 4 ensemble members.
#define SMEM_FLOATS (H1_ * MS + H2_ * MS + 2 * KT * MS + 2 * KT * H1_ + H3_ + TM + TM)
#define SMEM_BYTES  (SMEM_FLOATS * 4)

__global__ void __launch_bounds__(256, 1) k_main(
    const float* __restrict__ aev,
    const float* __restrict__ W1, const float* __restrict__ b1,
    const float* __restrict__ W2, const float* __restrict__ b2,
    const float* __restrict__ W3, const float* __restrict__ b3,
    const float* __restrict__ W4, const float* __restrict__ b4)
{
    const int s = blockIdx.y, t = blockIdx.x, z = blockIdx.z, tid = threadIdx.x;
    const int cnt  = g_count[s];
    const int base = t * TM;
    if (base >= cnt) return;
    const int nvalid = min(TM, cnt - base);

    extern __shared__ float smf[];
    float* R1  = smf;                 // [H1][MS], reused as H3 output
    float* R2  = R1 + H1_ * MS;       // [H2][MS]
    float* XaA = R2 + H2_ * MS;       // [KT][MS] gather buffers
    float* XaB = XaA + KT * MS;
    float* WtA = XaB + KT * MS;       // [KT][<=H1] weight buffers
    float* WtB = WtA + KT * H1_;
    float* w4s = WtB + KT * H1_;      // [H3]
    float* eat = w4s + H3_;           // [TM]
    int*  sidx = (int*)(eat + TM);    // [TM]

    if (tid < TM) {
        int p = base + tid; if (p >= cnt) p = cnt - 1;   // clamp tail
        sidx[tid] = g_idx[s * N_ + p];
    }
    __syncthreads();

    float blockSum = 0.f;

    for (int ei = 0; ei < 4; ei++) {
        const int e = z * 4 + ei;
        const int se = s * E_ + e;
        layer1_ff(aev, sidx, XaA, XaB, R1,
                  W1 + (size_t)se * D_ * H1_, b1 + (size_t)se * H1_, WtA, WtB, tid);
        layer_ff<H1_, H2_, 8>(R1, R2,
                  W2 + (size_t)se * H1_ * H2_, b2 + (size_t)se * H2_, WtA, WtB, tid, true);
        layer_ff<H2_, H3_, 6>(R2, R1,
                  W3 + (size_t)se * H2_ * H3_, b3 + (size_t)se * H3_, WtA, WtB, tid, true);

        // ---- layer 4: per-atom dot(h3[96], w4) + b4 ----
        if (tid < H3_) w4s[tid] = W4[(size_t)se * H3_ + tid];
        __syncthreads();
        {
            int m = tid >> 1, q = tid & 1;     // 2 threads per atom, 48 k each
            float ss = 0.f;
            const float* hc = R1 + (q * 48) * MS + m;
#pragma unroll
            for (int k = 0; k < 48; k++) ss += hc[k * MS] * w4s[q * 48 + k];
            ss += __shfl_xor_sync(0xffffffffu, ss, 1);
            if (q == 0) eat[m] = (m < nvalid) ? (ss + b4[se]) : 0.f;
        }
        __syncthreads();
        if (tid < 32) {
            float v = eat[tid] + eat[tid + 32] + eat[tid + 64] + eat[tid + 96];
            for (int o = 16; o; o >>= 1) v += __shfl_down_sync(0xffffffffu, v, o);
            if (tid == 0) blockSum += v;
        }
        __syncthreads();   // R1/R2 reused next ensemble member
    }

    if (tid == 0) g_partial[(s * NT + t) * 2 + z] = blockSum;
}

// ---------------- final deterministic reduction ----------------
__global__ void k_reduce(float* out) {
    __shared__ double sb[256];
    int tid = threadIdx.x;
    double s = 0.0;
    for (int i = tid; i < NPART; i += 256) s += (double)g_partial[i];
    sb[tid] = s;
    __syncthreads();
    for (int st = 128; st; st >>= 1) {
        if (tid < st) sb[tid] += sb[tid + st];
        __syncthreads();
    }
    if (tid == 0) out[0] = (float)(sb[0] * (1.0 / E_));
}

// ---------------- launch ----------------
extern "C" void kernel_launch(void* const* d_in, const int* in_sizes, int n_in,
                              void* d_out, int out_size)
{
    const void*  sp  = d_in[0];
    const float* aev = (const float*)d_in[1];
    const float* W1  = (const float*)d_in[2];
    const float* b1  = (const float*)d_in[3];
    const float* W2  = (const float*)d_in[4];
    const float* b2  = (const float*)d_in[5];
    const float* W3  = (const float*)d_in[6];
    const float* b3  = (const float*)d_in[7];
    const float* W4  = (const float*)d_in[8];
    const float* b4  = (const float*)d_in[9];

    cudaFuncSetAttribute(k_main, cudaFuncAttributeMaxDynamicSharedMemorySize, SMEM_BYTES);

    k_init<<<1, 256>>>((const ull*)sp);
    k_count<<<NB, 256>>>((const int*)sp);
    k_scan<<<1, 256>>>();
    k_scatter<<<NB, 256>>>((const int*)sp);

    dim3 grid(NT, S_, 2);
    k_main<<<grid, 256, SMEM_BYTES>>>(aev, W1, b1, W2, b2, W3, b3, W4, b4);

    k_reduce<<<1, 256>>>((float*)d_out);
}

// round 3
// speedup vs baseline: 1.1873x; 1.0026x over previous
#include <cuda_runtime.h>
#include <math.h>

#define S_  4
#define E_  8
#define D_  384
#define H1_ 160
#define H2_ 128
#define H3_ 96
#define N_  40000
#define TM  128                      // atoms per tile
#define KT  16                       // k-chunk for staging
#define MS  132                      // padded m-stride (mult of 4 for LDS.128)
#define NT  ((N_ + TM - 1) / TM)     // 313 tiles (worst case one species)
#define NB  ((N_ + 255) / 256)       // 157 blocks for bucketing passes
#define NPART (NT * S_ * 2)

typedef unsigned long long ull;

// ---------------- device scratch (no allocations allowed) ----------------
__device__ int   g_is64;
__device__ int   g_blockCnt[NB * S_];
__device__ int   g_blockOff[NB * S_];
__device__ int   g_count[S_];
__device__ int   g_idx[S_ * N_];
__device__ float g_partial[NPART];

// ---------------- packed fp32x2 helpers (FFMA2) ----------------
static __device__ __forceinline__ ull pack2(float lo, float hi) {
    ull r; asm("mov.b64 %0, {%1, %2};" : "=l"(r) : "f"(lo), "f"(hi)); return r;
}
static __device__ __forceinline__ ull ffma2(ull a, ull b, ull c) {
    ull d; asm("fma.rn.f32x2 %0, %1, %2, %3;" : "=l"(d) : "l"(a), "l"(b), "l"(c)); return d;
}
static __device__ __forceinline__ float2 unpk(ull v) {
    float2 f; asm("mov.b64 {%0, %1}, %2;" : "=f"(f.x), "=f"(f.y) : "l"(v)); return f;
}
static __device__ __forceinline__ float celu_f(float x) {
    return x > 0.f ? x : 0.1f * expm1f(x * 10.f);   // alpha = 0.1
}

// ---------------- pass 0: zero partials + detect int64 vs int32 species ----------------
__global__ void k_init(const ull* spq) {
    int tid = threadIdx.x;
    for (int i = tid; i < NPART; i += 256) g_partial[i] = 0.f;
    if (tid < 32) {
        ull v = spq[tid];
        int hiNZ = ((v >> 32) != 0ull) ? 1 : 0;
        int any = __any_sync(0xffffffffu, hiNZ);
        if (tid == 0) g_is64 = any ? 0 : 1;   // int64 species always have hi word 0
    }
}

// ---------------- pass 1: per-block species histogram ----------------
__global__ void k_count(const int* sp) {
    int tid = threadIdx.x, b = blockIdx.x;
    int n = b * 256 + tid;
    int shift = g_is64;
    int spv = -1;
    if (n < N_) spv = sp[(size_t)n << shift];
    __shared__ int wc[8][4];
    if (tid < 32) wc[tid >> 2][tid & 3] = 0;
    __syncthreads();
    unsigned mm = __match_any_sync(0xffffffffu, spv);
    int lane = tid & 31, w = tid >> 5;
    if (spv >= 0 && lane == (__ffs(mm) - 1)) wc[w][spv] = __popc(mm);
    __syncthreads();
    if (tid < 4) {
        int s = 0;
        for (int ww = 0; ww < 8; ww++) s += wc[ww][tid];
        g_blockCnt[b * 4 + tid] = s;
    }
}

// ---------------- pass 2: exclusive scan over block histograms ----------------
__global__ void k_scan() {
    __shared__ int c[NB * 4];
    __shared__ int o[NB * 4];
    int tid = threadIdx.x;
    for (int i = tid; i < NB * 4; i += 256) c[i] = g_blockCnt[i];
    __syncthreads();
    if (tid == 0) {
        int r0 = 0, r1 = 0, r2 = 0, r3 = 0;
        for (int b = 0; b < NB; b++) {
            o[b * 4 + 0] = r0; r0 += c[b * 4 + 0];
            o[b * 4 + 1] = r1; r1 += c[b * 4 + 1];
            o[b * 4 + 2] = r2; r2 += c[b * 4 + 2];
            o[b * 4 + 3] = r3; r3 += c[b * 4 + 3];
        }
        g_count[0] = r0; g_count[1] = r1; g_count[2] = r2; g_count[3] = r3;
    }
    __syncthreads();
    for (int i = tid; i < NB * 4; i += 256) g_blockOff[i] = o[i];
}

// ---------------- pass 3: deterministic scatter ----------------
__global__ void k_scatter(const int* sp) {
    int tid = threadIdx.x, b = blockIdx.x;
    int n = b * 256 + tid;
    int shift = g_is64;
    int spv = -1;
    if (n < N_) spv = sp[(size_t)n << shift];
    __shared__ int wc[8][4];
    __shared__ int woff[8][4];
    if (tid < 32) wc[tid >> 2][tid & 3] = 0;
    __syncthreads();
    unsigned mm = __match_any_sync(0xffffffffu, spv);
    int lane = tid & 31, w = tid >> 5;
    int rank = __popc(mm & ((1u << lane) - 1u));
    if (spv >= 0 && lane == (__ffs(mm) - 1)) wc[w][spv] = __popc(mm);
    __syncthreads();
    if (tid < 4) {
        int run = g_blockOff[b * 4 + tid];
        for (int ww = 0; ww < 8; ww++) { woff[ww][tid] = run; run += wc[ww][tid]; }
    }
    __syncthreads();
    if (spv >= 0) g_idx[spv * N_ + woff[w][spv] + rank] = n;
}

// ============== GEMM layer (A in SMEM, k-major, stride MS) ==============
// 256 threads = 8(tx) x 32(ty). Per thread: 4 atoms (m0=ty*4) x C column-pairs.
// Weights staged double-buffered in pair-transposed layout:
//   pair p stored at u = (p%C)*8 + p/C  ->  thread tx reads pairs tx*C+c at u=c*8+tx
//   => LDS.64 consecutive across tx => conflict-free.
template<int K, int NOUT, int C>
static __device__ __forceinline__ void layer_ff(
    const float* __restrict__ As, float* __restrict__ Os,
    const float* __restrict__ Wg, const float* __restrict__ bg,
    float* WtA, float* WtB, int tid, bool docelu)
{
    constexpr int NCH = K / KT;
    constexpr int WPT = KT * NOUT / 256;
    const int tx = tid & 7, ty = tid >> 3;
    const int m0 = ty * 4;
    const int pc0 = tx * C;

    ull acc[4][C];
#pragma unroll
    for (int c = 0; c < C; c++) {
        ull b2 = pack2(bg[2 * (pc0 + c)], bg[2 * (pc0 + c) + 1]);
#pragma unroll
        for (int j = 0; j < 4; j++) acc[j][c] = b2;
    }

    float wr[WPT];
#pragma unroll
    for (int i = 0; i < WPT; i++) wr[i] = Wg[tid + i * 256];
#pragma unroll
    for (int i = 0; i < WPT; i++) {
        int idx = tid + i * 256, kk = idx / NOUT, j = idx % NOUT;
        int p = j >> 1, r = j & 1, u = (p % C) * 8 + p / C;
        WtA[kk * NOUT + u * 2 + r] = wr[i];
    }
    __syncthreads();

    for (int kc = 0; kc < NCH; kc++) {
        const float* Wt = (kc & 1) ? WtB : WtA;
        float* Wn = (kc & 1) ? WtA : WtB;
        if (kc + 1 < NCH) {
#pragma unroll
            for (int i = 0; i < WPT; i++)
                wr[i] = Wg[(kc + 1) * KT * NOUT + tid + i * 256];
        }
#pragma unroll 2
        for (int kk = 0; kk < KT; kk++) {
            const float4 av = *(const float4*)(As + (kc * KT + kk) * MS + m0);
            ull a0 = pack2(av.x, av.x), a1 = pack2(av.y, av.y);
            ull a2 = pack2(av.z, av.z), a3 = pack2(av.w, av.w);
            const ull* wrow = (const ull*)(Wt + kk * NOUT);
#pragma unroll
            for (int c = 0; c < C; c++) {
                ull w2 = wrow[c * 8 + tx];
                acc[0][c] = ffma2(a0, w2, acc[0][c]);
                acc[1][c] = ffma2(a1, w2, acc[1][c]);
                acc[2][c] = ffma2(a2, w2, acc[2][c]);
                acc[3][c] = ffma2(a3, w2, acc[3][c]);
            }
        }
        if (kc + 1 < NCH) {
#pragma unroll
            for (int i = 0; i < WPT; i++) {
                int idx = tid + i * 256, kk2 = idx / NOUT, j = idx % NOUT;
                int p = j >> 1, r = j & 1, u = (p % C) * 8 + p / C;
                Wn[kk2 * NOUT + u * 2 + r] = wr[i];
            }
        }
        __syncthreads();
    }

#pragma unroll
    for (int c = 0; c < C; c++) {
        int col = 2 * (pc0 + c);
#pragma unroll
        for (int j = 0; j < 4; j++) {
            float2 v = unpk(acc[j][c]);
            if (docelu) { v.x = celu_f(v.x); v.y = celu_f(v.y); }
            Os[col * MS + m0 + j]       = v.x;
            Os[(col + 1) * MS + m0 + j] = v.y;
        }
    }
}

// ============== layer 1: A gathered from gmem, double-buffered ==============
static __device__ __forceinline__ void layer1_ff(
    const float* __restrict__ aev, const int* sidx,
    float* XaA, float* XaB, float* __restrict__ Os,
    const float* __restrict__ Wg, const float* __restrict__ bg,
    float* WtA, float* WtB, int tid)
{
    constexpr int NOUT = H1_, C = 10;
    constexpr int NCH = D_ / KT;             // 24
    constexpr int WPT = KT * NOUT / 256;     // 10
    const int tx = tid & 7, ty = tid >> 3;
    const int m0 = ty * 4;
    const int pc0 = tx * C;
    const int am = tid >> 1, ko = (tid & 1) * 8;   // gather role: atom, k sub-offset
    const float* ap = aev + (size_t)sidx[am] * D_ + ko;

    ull acc[4][C];
#pragma unroll
    for (int c = 0; c < C; c++) {
        ull b2 = pack2(bg[2 * (pc0 + c)], bg[2 * (pc0 + c) + 1]);
#pragma unroll
        for (int j = 0; j < 4; j++) acc[j][c] = b2;
    }

    float wr[WPT];
    float4 x0, x1;
#pragma unroll
    for (int i = 0; i < WPT; i++) wr[i] = Wg[tid + i * 256];
    x0 = *(const float4*)(ap);
    x1 = *(const float4*)(ap + 4);
#pragma unroll
    for (int i = 0; i < WPT; i++) {
        int idx = tid + i * 256, kk = idx / NOUT, j = idx % NOUT;
        int p = j >> 1, r = j & 1, u = (p % C) * 8 + p / C;
        WtA[kk * NOUT + u * 2 + r] = wr[i];
    }
    XaA[(ko + 0) * MS + am] = x0.x; XaA[(ko + 1) * MS + am] = x0.y;
    XaA[(ko + 2) * MS + am] = x0.z; XaA[(ko + 3) * MS + am] = x0.w;
    XaA[(ko + 4) * MS + am] = x1.x; XaA[(ko + 5) * MS + am] = x1.y;
    XaA[(ko + 6) * MS + am] = x1.z; XaA[(ko + 7) * MS + am] = x1.w;
    __syncthreads();

    for (int kc = 0; kc < NCH; kc++) {
        const float* Wt = (kc & 1) ? WtB : WtA;
        float* Wn = (kc & 1) ? WtA : WtB;
        const float* Xa = (kc & 1) ? XaB : XaA;
        float* Xn = (kc & 1) ? XaA : XaB;
        if (kc + 1 < NCH) {
#pragma unroll
            for (int i = 0; i < WPT; i++)
                wr[i] = Wg[(kc + 1) * KT * NOUT + tid + i * 256];
            x0 = *(const float4*)(ap + (kc + 1) * KT);
            x1 = *(const float4*)(ap + (kc + 1) * KT + 4);
        }
#pragma unroll 2
        for (int kk = 0; kk < KT; kk++) {
            const float4 av = *(const float4*)(Xa + kk * MS + m0);
            ull a0 = pack2(av.x, av.x), a1 = pack2(av.y, av.y);
            ull a2 = pack2(av.z, av.z), a3 = pack2(av.w, av.w);
            const ull* wrow = (const ull*)(Wt + kk * NOUT);
#pragma unroll
            for (int c = 0; c < C; c++) {
                ull w2 = wrow[c * 8 + tx];
                acc[0][c] = ffma2(a0, w2, acc[0][c]);
                acc[1][c] = ffma2(a1, w2, acc[1][c]);
                acc[2][c] = ffma2(a2, w2, acc[2][c]);
                acc[3][c] = ffma2(a3, w2, acc[3][c]);
            }
        }
        if (kc + 1 < NCH) {
#pragma unroll
            for (int i = 0; i < WPT; i++) {
                int idx = tid + i * 256, kk2 = idx / NOUT, j = idx % NOUT;
                int p = j >> 1, r = j & 1, u = (p % C) * 8 + p / C;
                Wn[kk2 * NOUT + u * 2 + r] = wr[i];
            }
            Xn[(ko + 0) * MS + am] = x0.x; Xn[(ko + 1) * MS + am] = x0.y;
            Xn[(ko + 2) * MS + am] = x0.z; Xn[(ko + 3) * MS + am] = x0.w;
            Xn[(ko + 4) * MS + am] = x1.x; Xn[(ko + 5) * MS + am] = x1.y;
            Xn[(ko + 6) * MS + am] = x1.z; Xn[(ko + 7) * MS + am] = x1.w;
        }
        __syncthreads();
    }

#pragma unroll
    for (int c = 0; c < C; c++) {
        int col = 2 * (pc0 + c);
#pragma unroll
        for (int j = 0; j < 4; j++) {
            float2 v = unpk(acc[j][c]);
            v.x = celu_f(v.x); v.y = celu_f(v.y);
            Os[col * MS + m0 + j]       = v.x;
            Os[(col + 1) * MS + m0 + j] = v.y;
        }
    }
}

// ---------------- main fused MLP kernel ----------------
// grid = (NT, S, 2). Each block: 128 atoms of one species, 4 ensemble members.
#define SMEM_FLOATS (H1_ * MS + H2_ * MS + 2 * KT * MS + 2 * KT * H1_ + H3_ + TM + TM)
#define SMEM_BYTES  (SMEM_FLOATS * 4)

__global__ void __launch_bounds__(256, 1) k_main(
    const float* __restrict__ aev,
    const float* __restrict__ W1, const float* __restrict__ b1,
    const float* __restrict__ W2, const float* __restrict__ b2,
    const float* __restrict__ W3, const float* __restrict__ b3,
    const float* __restrict__ W4, const float* __restrict__ b4)
{
    const int s = blockIdx.y, t = blockIdx.x, z = blockIdx.z, tid = threadIdx.x;
    const int cnt  = g_count[s];
    const int base = t * TM;
    if (base >= cnt) return;
    const int nvalid = min(TM, cnt - base);

    extern __shared__ float smf[];
    float* R1  = smf;                 // [H1][MS], reused as H3 output
    float* R2  = R1 + H1_ * MS;       // [H2][MS]
    float* XaA = R2 + H2_ * MS;       // [KT][MS] gather buffers
    float* XaB = XaA + KT * MS;
    float* WtA = XaB + KT * MS;       // [KT][<=H1] weight buffers
    float* WtB = WtA + KT * H1_;
    float* w4s = WtB + KT * H1_;      // [H3]
    float* eat = w4s + H3_;           // [TM]
    int*  sidx = (int*)(eat + TM);    // [TM]

    if (tid < TM) {
        int p = base + tid; if (p >= cnt) p = cnt - 1;   // clamp tail
        sidx[tid] = g_idx[s * N_ + p];
    }
    __syncthreads();

    float blockSum = 0.f;

    for (int ei = 0; ei < 4; ei++) {
        const int e = z * 4 + ei;
        const int se = s * E_ + e;
        layer1_ff(aev, sidx, XaA, XaB, R1,
                  W1 + (size_t)se * D_ * H1_, b1 + (size_t)se * H1_, WtA, WtB, tid);
        layer_ff<H1_, H2_, 8>(R1, R2,
                  W2 + (size_t)se * H1_ * H2_, b2 + (size_t)se * H2_, WtA, WtB, tid, true);
        layer_ff<H2_, H3_, 6>(R2, R1,
                  W3 + (size_t)se * H2_ * H3_, b3 + (size_t)se * H3_, WtA, WtB, tid, true);

        // ---- layer 4: per-atom dot(h3[96], w4) + b4 ----
        if (tid < H3_) w4s[tid] = W4[(size_t)se * H3_ + tid];
        __syncthreads();
        {
            int m = tid >> 1, q = tid & 1;     // 2 threads per atom, 48 k each
            float ss = 0.f;
            const float* hc = R1 + (q * 48) * MS + m;
#pragma unroll
            for (int k = 0; k < 48; k++) ss += hc[k * MS] * w4s[q * 48 + k];
            ss += __shfl_xor_sync(0xffffffffu, ss, 1);
            if (q == 0) eat[m] = (m < nvalid) ? (ss + b4[se]) : 0.f;
        }
        __syncthreads();
        if (tid < 32) {
            float v = eat[tid] + eat[tid + 32] + eat[tid + 64] + eat[tid + 96];
            for (int o = 16; o; o >>= 1) v += __shfl_down_sync(0xffffffffu, v, o);
            if (tid == 0) blockSum += v;
        }
        __syncthreads();   // R1/R2 reused next ensemble member
    }

    if (tid == 0) g_partial[(s * NT + t) * 2 + z] = blockSum;
}

// ---------------- final deterministic reduction ----------------
__global__ void k_reduce(float* out) {
    __shared__ double sb[256];
    int tid = threadIdx.x;
    double s = 0.0;
    for (int i = tid; i < NPART; i += 256) s += (double)g_partial[i];
    sb[tid] = s;
    __syncthreads();
    for (int st = 128; st; st >>= 1) {
        if (tid < st) sb[tid] += sb[tid + st];
        __syncthreads();
    }
    if (tid == 0) out[0] = (float)(sb[0] * (1.0 / E_));
}

// ---------------- launch ----------------
extern "C" void kernel_launch(void* const* d_in, const int* in_sizes, int n_in,
                              void* d_out, int out_size)
{
    const void*  sp  = d_in[0];
    const float* aev = (const float*)d_in[1];
    const float* W1  = (const float*)d_in[2];
    const float* b1  = (const float*)d_in[3];
    const float* W2  = (const float*)d_in[4];
    const float* b2  = (const float*)d_in[5];
    const float* W3  = (const float*)d_in[6];
    const float* b3  = (const float*)d_in[7];
    const float* W4  = (const float*)d_in[8];
    const float* b4  = (const float*)d_in[9];

    cudaFuncSetAttribute(k_main, cudaFuncAttributeMaxDynamicSharedMemorySize, SMEM_BYTES);

    k_init<<<1, 256>>>((const ull*)sp);
    k_count<<<NB, 256>>>((const int*)sp);
    k_scan<<<1, 256>>>();
    k_scatter<<<NB, 256>>>((const int*)sp);

    dim3 grid(NT, S_, 2);
    k_main<<<grid, 256, SMEM_BYTES>>>(aev, W1, b1, W2, b2, W3, b3, W4, b4);

    k_reduce<<<1, 256>>>((float*)d_out);
}

// round 5
// speedup vs baseline: 1.9125x; 1.6108x over previous
#include <cuda_runtime.h>
#include <cuda_bf16.h>
#include <cstdint>
#include <math.h>

#define S_  4
#define E_  8
#define D_  384
#define H1_ 160
#define H2_ 128
#define H3_ 96
#define N_  40000
#define TM  128
#define NTT 313
#define NB  ((N_ + 255) / 256)
#define NPART (NTT * S_ * 4)
#define MAXT 320

typedef unsigned long long ull;
typedef uint32_t u32;
typedef unsigned short u16;

// ---------------- gmem image geometry ----------------
// A tiles: 6 chunks x [128][72] fp32 (k valid 0..63)
#define ACH   36864
#define ASE   (6 * ACH)            // 221184
// Weights per (s,e):
//  W1 @0:      6 chunks x 46080 (hi 23040 | lo 23040), [160][72] halves each
//  W2 @276480: chunks @ +0,+36864,+73728; c0/c1 [128][72] (hi|lo 18432), c2 [128][40] (hi|lo 10240)
//  W3 @370688: 2 chunks x 27648 (hi|lo 13824), [96][72]
#define W1OFF 0
#define W2OFF 276480
#define W3OFF 370688
#define WSE   425984

__device__ int   g_is64;
__device__ int   g_blockCnt[NB * S_];
__device__ int   g_blockOff[NB * S_];
__device__ int   g_count[S_];
__device__ int   g_tbase[S_];
__device__ int   g_idx[S_ * N_];
__device__ float g_partial[NPART];
__device__ __align__(1024) unsigned char g_Wimg[(size_t)32 * WSE];
__device__ __align__(1024) unsigned char g_Aimg[(size_t)MAXT * ASE];

// ---------------- helpers ----------------
static __device__ __forceinline__ float celu_f(float x) {
    return x > 0.f ? x : 0.1f * expm1f(x * 10.f);
}
static __device__ __forceinline__ u32 s2u(const void* p) {
    u32 a;
    asm("{ .reg .u64 t; cvta.to.shared.u64 t, %1; cvt.u32.u64 %0, t; }" : "=r"(a) : "l"(p));
    return a;
}
static __device__ __forceinline__ void split2(float v, u16& h, u16& l) {
    __nv_bfloat16 hb = __float2bfloat16(v);
    float hf = __bfloat162float(hb);
    __nv_bfloat16 lb = __float2bfloat16(v - hf);
    h = __bfloat16_as_ushort(hb);
    l = __bfloat16_as_ushort(lb);
}
// fp32 pair -> packed bf16x2 hi part + residual lo part
static __device__ __forceinline__ void splitpair(float x, float y, u32& h, u32& l) {
    u32 hh;
    asm("cvt.rn.bf16x2.f32 %0, %1, %2;" : "=r"(hh) : "f"(y), "f"(x));
    float xh = __uint_as_float(hh << 16);
    float yh = __uint_as_float(hh & 0xffff0000u);
    asm("cvt.rn.bf16x2.f32 %0, %1, %2;" : "=r"(l) : "f"(y - yh), "f"(x - xh));
    h = hh;
}
static __device__ __forceinline__ void mma16816(float* c,
        u32 a0, u32 a1, u32 a2, u32 a3, u32 b0, u32 b1) {
    asm volatile(
        "mma.sync.aligned.m16n8k16.row.col.f32.bf16.bf16.f32 "
        "{%0,%1,%2,%3},{%4,%5,%6,%7},{%8,%9},{%0,%1,%2,%3};"
        : "+f"(c[0]), "+f"(c[1]), "+f"(c[2]), "+f"(c[3])
        : "r"(a0), "r"(a1), "r"(a2), "r"(a3), "r"(b0), "r"(b1));
}
#define CPA16(d, s) asm volatile("cp.async.cg.shared.global [%0], [%1], 16;" :: "r"(d), "l"(s) : "memory")
#define CPCOMMIT()  asm volatile("cp.async.commit_group;" ::: "memory")
#define CPWAIT(n)   asm volatile("cp.async.wait_group %0;" :: "n"(n) : "memory")

// ---------------- bucketing ----------------
__global__ void k_init(const ull* spq) {
    int tid = threadIdx.x;
    for (int i = tid; i < NPART; i += 256) g_partial[i] = 0.f;
    if (tid < 32) {
        ull v = spq[tid];
        int hiNZ = ((v >> 32) != 0ull) ? 1 : 0;
        int any = __any_sync(0xffffffffu, hiNZ);
        if (tid == 0) g_is64 = any ? 0 : 1;
    }
}
__global__ void k_count(const int* sp) {
    int tid = threadIdx.x, b = blockIdx.x;
    int n = b * 256 + tid;
    int shift = g_is64;
    int spv = -1;
    if (n < N_) spv = sp[(size_t)n << shift];
    __shared__ int wc[8][4];
    if (tid < 32) wc[tid >> 2][tid & 3] = 0;
    __syncthreads();
    unsigned mm = __match_any_sync(0xffffffffu, spv);
    int lane = tid & 31, w = tid >> 5;
    if (spv >= 0 && lane == (__ffs(mm) - 1)) wc[w][spv] = __popc(mm);
    __syncthreads();
    if (tid < 4) {
        int s = 0;
        for (int ww = 0; ww < 8; ww++) s += wc[ww][tid];
        g_blockCnt[b * 4 + tid] = s;
    }
}
__global__ void k_scan() {
    __shared__ int c[NB * 4];
    __shared__ int o[NB * 4];
    int tid = threadIdx.x;
    for (int i = tid; i < NB * 4; i += 256) c[i] = g_blockCnt[i];
    __syncthreads();
    if (tid == 0) {
        int r0 = 0, r1 = 0, r2 = 0, r3 = 0;
        for (int b = 0; b < NB; b++) {
            o[b * 4 + 0] = r0; r0 += c[b * 4 + 0];
            o[b * 4 + 1] = r1; r1 += c[b * 4 + 1];
            o[b * 4 + 2] = r2; r2 += c[b * 4 + 2];
            o[b * 4 + 3] = r3; r3 += c[b * 4 + 3];
        }
        g_count[0] = r0; g_count[1] = r1; g_count[2] = r2; g_count[3] = r3;
        int tb = 0;
        g_tbase[0] = 0;  tb += (r0 + TM - 1) / TM;
        g_tbase[1] = tb; tb += (r1 + TM - 1) / TM;
        g_tbase[2] = tb; tb += (r2 + TM - 1) / TM;
        g_tbase[3] = tb;
    }
    __syncthreads();
    for (int i = tid; i < NB * 4; i += 256) g_blockOff[i] = o[i];
}
__global__ void k_scatter(const int* sp) {
    int tid = threadIdx.x, b = blockIdx.x;
    int n = b * 256 + tid;
    int shift = g_is64;
    int spv = -1;
    if (n < N_) spv = sp[(size_t)n << shift];
    __shared__ int wc[8][4];
    __shared__ int woff[8][4];
    if (tid < 32) wc[tid >> 2][tid & 3] = 0;
    __syncthreads();
    unsigned mm = __match_any_sync(0xffffffffu, spv);
    int lane = tid & 31, w = tid >> 5;
    int rank = __popc(mm & ((1u << lane) - 1u));
    if (spv >= 0 && lane == (__ffs(mm) - 1)) wc[w][spv] = __popc(mm);
    __syncthreads();
    if (tid < 4) {
        int run = g_blockOff[b * 4 + tid];
        for (int ww = 0; ww < 8; ww++) { woff[ww][tid] = run; run += wc[ww][tid]; }
    }
    __syncthreads();
    if (spv >= 0) g_idx[spv * N_ + woff[w][spv] + rank] = n;
}

// ---------------- weight image prep ----------------
__global__ void k_wprep(const float* __restrict__ W1, const float* __restrict__ W2,
                        const float* __restrict__ W3) {
    int se = blockIdx.x, tid = threadIdx.x;
    unsigned char* base = g_Wimg + (size_t)se * WSE;
    for (int i = tid; i < D_ * H1_; i += 256) {            // W1 [k][n] -> [n][72] per 64-chunk
        int n = i % H1_, k = i / H1_;
        u16 h, l; split2(W1[((size_t)se * D_ + k) * H1_ + n], h, l);
        int c = k >> 6, kl = k & 63;
        u16* p = (u16*)(base + W1OFF + c * 46080);
        p[n * 72 + kl] = h;
        p[11520 + n * 72 + kl] = l;                        // +23040 B
    }
    for (int i = tid; i < H1_ * H2_; i += 256) {           // W2 k=160
        int n = i % H2_, k = i / H2_;
        u16 h, l; split2(W2[((size_t)se * H1_ + k) * H2_ + n], h, l);
        int c = k >> 6, kl = k & 63;
        int str = (c == 2) ? 40 : 72, hlw = (c == 2) ? 5120 : 9216;
        int coff = (c == 0) ? 0 : (c == 1 ? 36864 : 73728);
        u16* p = (u16*)(base + W2OFF + coff);
        p[n * str + kl] = h;
        p[hlw + n * str + kl] = l;
    }
    for (int i = tid; i < H2_ * H3_; i += 256) {           // W3 k=128
        int n = i % H3_, k = i / H3_;
        u16 h, l; split2(W3[((size_t)se * H2_ + k) * H3_ + n], h, l);
        int c = k >> 6, kl = k & 63;
        u16* p = (u16*)(base + W3OFF + c * 27648);
        p[n * 72 + kl] = h;
        p[6912 + n * 72 + kl] = l;                         // +13824 B
    }
}

// ---------------- A image prep ----------------
__global__ void k_aprep(const float* __restrict__ aev) {
    int t = blockIdx.x, s = blockIdx.y, tid = threadIdx.x;
    int cnt = g_count[s];
    int ntl = (cnt + TM - 1) / TM;
    if (t >= ntl) return;
    int gt = g_tbase[s] + t;
    __shared__ int sidx[TM];
    if (tid < TM) {
        int p = t * TM + tid; if (p >= cnt) p = cnt - 1;
        sidx[tid] = g_idx[s * N_ + p];
    }
    __syncthreads();
    float* base = (float*)(g_Aimg + (size_t)gt * ASE);
    for (int i = tid; i < TM * D_; i += 256) {
        int m = i / D_, k = i % D_;
        float v = aev[(size_t)sidx[m] * D_ + k];
        int c = k >> 6, kl = k & 63;
        base[c * 9216 + m * 72 + kl] = v;                  // chunk = 36864 B = 9216 floats
    }
}

// ---------------- fragment GEMM over one staged chunk ----------------
template<int NT>
static __device__ __forceinline__ void chunk_mma(
    float (*acc)[NT][4],
    const float* As, int astr,
    const u16* Wh, const u16* Wl, int wstr,
    int ksteps, int mbase, int nbase, int g, int q)
{
    for (int ks = 0; ks < ksteps; ks++) {
        const int k0 = ks * 16;
        u32 ah[2][4], al[2][4];
#pragma unroll
        for (int mt = 0; mt < 2; mt++) {
            const float* ap = As + (mbase + mt * 16 + g) * astr + k0 + q * 2;
            float2 p0 = *(const float2*)(ap);
            float2 p1 = *(const float2*)(ap + 8 * astr);
            float2 p2 = *(const float2*)(ap + 8);
            float2 p3 = *(const float2*)(ap + 8 * astr + 8);
            splitpair(p0.x, p0.y, ah[mt][0], al[mt][0]);
            splitpair(p1.x, p1.y, ah[mt][1], al[mt][1]);
            splitpair(p2.x, p2.y, ah[mt][2], al[mt][2]);
            splitpair(p3.x, p3.y, ah[mt][3], al[mt][3]);
        }
#pragma unroll
        for (int nt = 0; nt < NT; nt++) {
            int nr = nbase + nt * 8 + g;
            const u16* wp = Wh + nr * wstr + k0 + q * 2;
            const u16* wq = Wl + nr * wstr + k0 + q * 2;
            u32 bh0 = *(const u32*)(wp);
            u32 bh1 = *(const u32*)(wp + 8);
            u32 bl0 = *(const u32*)(wq);
            u32 bl1 = *(const u32*)(wq + 8);
            mma16816(acc[0][nt], ah[0][0], ah[0][1], ah[0][2], ah[0][3], bh0, bh1);
            mma16816(acc[1][nt], ah[1][0], ah[1][1], ah[1][2], ah[1][3], bh0, bh1);
            mma16816(acc[0][nt], al[0][0], al[0][1], al[0][2], al[0][3], bh0, bh1);
            mma16816(acc[1][nt], al[1][0], al[1][1], al[1][2], al[1][3], bh0, bh1);
            mma16816(acc[0][nt], ah[0][0], ah[0][1], ah[0][2], ah[0][3], bl0, bl1);
            mma16816(acc[1][nt], ah[1][0], ah[1][1], ah[1][2], ah[1][3], bl0, bl1);
        }
    }
}

// ---------------- main kernel ----------------
// SMEM: L1 stages @0 (2 x 82944 = A 36864 | Wh 23040 | Wl 23040)
//       H1 chunks @ {0, 36864, 73728} ([128][72],[128][72],[128][40] fp32)
//       W stage bufs @ 98304, 135168 (36864 each)
//       H2 chunks @ {0, 36864}
//       misc @ 172032: b1s 160 | b2s 128 | b3s 96 | w4s 96 | part 256 floats
#define STG1  82944
#define WB0   98304
#define WB1   135168
#define MISCO 172032
#define SMEMB (MISCO + 3072)

__global__ void __launch_bounds__(256, 1) k_main(
    const float* __restrict__ b1, const float* __restrict__ b2,
    const float* __restrict__ b3, const float* __restrict__ W4,
    const float* __restrict__ b4)
{
    extern __shared__ __align__(16) unsigned char sm[];
    const int s = blockIdx.y, t = blockIdx.x, z = blockIdx.z, tid = threadIdx.x;
    const int cnt = g_count[s];
    const int ntl = (cnt + TM - 1) / TM;
    if (t >= ntl) return;
    const int nvalid = min(TM, cnt - t * TM);
    const int gt = g_tbase[s] + t;
    const int lane = tid & 31, w = tid >> 5;
    const int wm = w & 3, wn = w >> 2, g = lane >> 2, q = lane & 3;
    const int mbase = wm * 32;
    const u32 sb = s2u(sm);
    float* b1s = (float*)(sm + MISCO);
    float* b2s = b1s + 160;
    float* b3s = b2s + 128;
    float* w4s = b3s + 96;
    float* part = w4s + 96;

    const unsigned char* Ab = g_Aimg + (size_t)gt * ASE;
    float blockSum = 0.f;

    for (int ei = 0; ei < 2; ei++) {
        const int se = s * E_ + z * 2 + ei;
        const unsigned char* Wb = g_Wimg + (size_t)se * WSE;
        if (tid < 160) b1s[tid] = b1[se * H1_ + tid];
        if (tid < 128) b2s[tid] = b2[se * H2_ + tid];
        if (tid < 96) { b3s[tid] = b3[se * H3_ + tid]; w4s[tid] = W4[se * H3_ + tid]; }

        // ================= Layer 1 (K=384, N=160) =================
        float acc1[2][10][4];
#pragma unroll
        for (int a = 0; a < 2; a++)
#pragma unroll
            for (int b = 0; b < 10; b++)
#pragma unroll
                for (int c = 0; c < 4; c++) acc1[a][b][c] = 0.f;

        auto cpyL1 = [&](int c, int bf) {
            u32 dst = sb + (bf ? STG1 : 0);
            const unsigned char* gA = Ab + c * ACH;
            for (int i = tid * 16; i < ACH; i += 4096) CPA16(dst + i, gA + i);
            const unsigned char* gW = Wb + W1OFF + c * 46080;
            for (int i = tid * 16; i < 46080; i += 4096) CPA16(dst + ACH + i, gW + i);
            CPCOMMIT();
        };
        cpyL1(0, 0); cpyL1(1, 1);
        for (int kc = 0; kc < 6; kc++) {
            if (kc == 5) { CPWAIT(0); } else { CPWAIT(1); }
            __syncthreads();
            const unsigned char* st = sm + ((kc & 1) ? STG1 : 0);
            chunk_mma<10>(acc1, (const float*)st, 72,
                          (const u16*)(st + ACH), (const u16*)(st + ACH + 23040), 72,
                          4, mbase, wn * 80, g, q);
            __syncthreads();
            if (kc < 4) cpyL1(kc + 2, kc & 1);
        }
        // epilogue -> H1
        {
            const int h1off[3] = {0, 36864, 73728};
#pragma unroll
            for (int mt = 0; mt < 2; mt++)
#pragma unroll
                for (int nt = 0; nt < 10; nt++) {
                    int n0 = wn * 80 + nt * 8 + q * 2;
                    int cb = n0 >> 6, off = n0 & 63;
                    int str = (cb == 2) ? 40 : 72;
                    float* Hc = (float*)(sm + h1off[cb]);
                    int row = mbase + mt * 16 + g;
                    float2 v;
                    v.x = celu_f(acc1[mt][nt][0] + b1s[n0]);
                    v.y = celu_f(acc1[mt][nt][1] + b1s[n0 + 1]);
                    *(float2*)&Hc[row * str + off] = v;
                    v.x = celu_f(acc1[mt][nt][2] + b1s[n0]);
                    v.y = celu_f(acc1[mt][nt][3] + b1s[n0 + 1]);
                    *(float2*)&Hc[(row + 8) * str + off] = v;
                }
        }
        __syncthreads();

        // ================= Layer 2 (K=160, N=128) =================
        float acc2[2][8][4];
#pragma unroll
        for (int a = 0; a < 2; a++)
#pragma unroll
            for (int b = 0; b < 8; b++)
#pragma unroll
                for (int c = 0; c < 4; c++) acc2[a][b][c] = 0.f;

        auto cpyW = [&](const unsigned char* src, int bytes, u32 dstoff) {
            for (int i = tid * 16; i < bytes; i += 4096) CPA16(sb + dstoff + i, src + i);
            CPCOMMIT();
        };
        cpyW(Wb + W2OFF, 36864, WB0);
        cpyW(Wb + W2OFF + 36864, 36864, WB1);
        {
            const int h1off[3] = {0, 36864, 73728};
            for (int kc = 0; kc < 3; kc++) {
                if (kc == 2) { CPWAIT(0); } else { CPWAIT(1); }
                __syncthreads();
                const unsigned char* wb = sm + ((kc & 1) ? WB1 : WB0);
                int str = (kc == 2) ? 40 : 72;
                int hl = (kc == 2) ? 10240 : 18432;
                int ks = (kc == 2) ? 2 : 4;
                chunk_mma<8>(acc2, (const float*)(sm + h1off[kc]), str,
                             (const u16*)wb, (const u16*)(wb + hl), str,
                             ks, mbase, wn * 64, g, q);
                __syncthreads();
                if (kc == 0) cpyW(Wb + W2OFF + 73728, 20480, WB0);
            }
        }
        // epilogue -> H2 @ {0, 36864}
#pragma unroll
        for (int mt = 0; mt < 2; mt++)
#pragma unroll
            for (int nt = 0; nt < 8; nt++) {
                int n0 = wn * 64 + nt * 8 + q * 2;
                int cb = n0 >> 6, off = n0 & 63;
                float* Hc = (float*)(sm + cb * 36864);
                int row = mbase + mt * 16 + g;
                float2 v;
                v.x = celu_f(acc2[mt][nt][0] + b2s[n0]);
                v.y = celu_f(acc2[mt][nt][1] + b2s[n0 + 1]);
                *(float2*)&Hc[row * 72 + off] = v;
                v.x = celu_f(acc2[mt][nt][2] + b2s[n0]);
                v.y = celu_f(acc2[mt][nt][3] + b2s[n0 + 1]);
                *(float2*)&Hc[(row + 8) * 72 + off] = v;
            }
        __syncthreads();

        // ================= Layer 3 (K=128, N=96) =================
        float acc3[2][6][4];
#pragma unroll
        for (int a = 0; a < 2; a++)
#pragma unroll
            for (int b = 0; b < 6; b++)
#pragma unroll
                for (int c = 0; c < 4; c++) acc3[a][b][c] = 0.f;

        cpyW(Wb + W3OFF, 27648, WB0);
        cpyW(Wb + W3OFF + 27648, 27648, WB1);
        for (int kc = 0; kc < 2; kc++) {
            if (kc == 1) { CPWAIT(0); } else { CPWAIT(1); }
            __syncthreads();
            const unsigned char* wb = sm + ((kc & 1) ? WB1 : WB0);
            chunk_mma<6>(acc3, (const float*)(sm + kc * 36864), 72,
                         (const u16*)wb, (const u16*)(wb + 13824), 72,
                         4, mbase, wn * 48, g, q);
            __syncthreads();
        }
        // ================= fused L3-epilogue + Layer 4 =================
        {
            float p00 = 0.f, p01 = 0.f, p10 = 0.f, p11 = 0.f;
#pragma unroll
            for (int nt = 0; nt < 6; nt++) {
                int n0 = wn * 48 + nt * 8 + q * 2;
                float w0 = w4s[n0], w1 = w4s[n0 + 1];
                float bb0 = b3s[n0], bb1 = b3s[n0 + 1];
                p00 += celu_f(acc3[0][nt][0] + bb0) * w0 + celu_f(acc3[0][nt][1] + bb1) * w1;
                p01 += celu_f(acc3[0][nt][2] + bb0) * w0 + celu_f(acc3[0][nt][3] + bb1) * w1;
                p10 += celu_f(acc3[1][nt][0] + bb0) * w0 + celu_f(acc3[1][nt][1] + bb1) * w1;
                p11 += celu_f(acc3[1][nt][2] + bb0) * w0 + celu_f(acc3[1][nt][3] + bb1) * w1;
            }
            p00 += __shfl_xor_sync(0xffffffffu, p00, 1); p00 += __shfl_xor_sync(0xffffffffu, p00, 2);
            p01 += __shfl_xor_sync(0xffffffffu, p01, 1); p01 += __shfl_xor_sync(0xffffffffu, p01, 2);
            p10 += __shfl_xor_sync(0xffffffffu, p10, 1); p10 += __shfl_xor_sync(0xffffffffu, p10, 2);
            p11 += __shfl_xor_sync(0xffffffffu, p11, 1); p11 += __shfl_xor_sync(0xffffffffu, p11, 2);
            if (q == 0) {
                part[wn * 128 + mbase + g]      = p00;
                part[wn * 128 + mbase + g + 8]  = p01;
                part[wn * 128 + mbase + 16 + g]     = p10;
                part[wn * 128 + mbase + 16 + g + 8] = p11;
            }
        }
        __syncthreads();
        if (tid < 128) {
            float en = part[tid] + part[128 + tid] + b4[se];
            part[tid] = (tid < nvalid) ? en : 0.f;
        }
        __syncthreads();
        if (tid < 32) {
            float v = part[tid] + part[tid + 32] + part[tid + 64] + part[tid + 96];
            for (int o = 16; o; o >>= 1) v += __shfl_down_sync(0xffffffffu, v, o);
            if (tid == 0) blockSum += v;
        }
        __syncthreads();
    }
    if (tid == 0) g_partial[(s * NTT + t) * 4 + z] = blockSum;
}

// ---------------- final reduction ----------------
__global__ void k_reduce(float* out) {
    __shared__ double sb[256];
    int tid = threadIdx.x;
    double s = 0.0;
    for (int i = tid; i < NPART; i += 256) s += (double)g_partial[i];
    sb[tid] = s;
    __syncthreads();
    for (int st = 128; st; st >>= 1) {
        if (tid < st) sb[tid] += sb[tid + st];
        __syncthreads();
    }
    if (tid == 0) out[0] = (float)(sb[0] * (1.0 / E_));
}

// ---------------- launch ----------------
extern "C" void kernel_launch(void* const* d_in, const int* in_sizes, int n_in,
                              void* d_out, int out_size)
{
    const void*  sp  = d_in[0];
    const float* aev = (const float*)d_in[1];
    const float* W1  = (const float*)d_in[2];
    const float* b1  = (const float*)d_in[3];
    const float* W2  = (const float*)d_in[4];
    const float* b2  = (const float*)d_in[5];
    const float* W3  = (const float*)d_in[6];
    const float* b3  = (const float*)d_in[7];
    const float* W4  = (const float*)d_in[8];
    const float* b4  = (const float*)d_in[9];

    cudaFuncSetAttribute(k_main, cudaFuncAttributeMaxDynamicSharedMemorySize, SMEMB);

    k_init<<<1, 256>>>((const ull*)sp);
    k_count<<<NB, 256>>>((const int*)sp);
    k_scan<<<1, 256>>>();
    k_scatter<<<NB, 256>>>((const int*)sp);
    k_wprep<<<32, 256>>>(W1, W2, W3);
    dim3 ga(NTT, S_);
    k_aprep<<<ga, 256>>>(aev);
    dim3 gm(NTT, S_, 4);
    k_main<<<gm, 256, SMEMB>>>(b1, b2, b3, W4, b4);
    k_reduce<<<1, 256>>>((float*)d_out);
}

// round 6
// speedup vs baseline: 2.1228x; 1.1100x over previous
#include <cuda_runtime.h>
#include <cuda_bf16.h>
#include <cstdint>
#include <math.h>

#define S_  4
#define E_  8
#define D_  384
#define H1_ 160
#define H2_ 128
#define H3_ 96
#define N_  40000
#define TM  128
#define NTT 313
#define NB  ((N_ + 255) / 256)
#define NPART (NTT * S_ * 4)
#define MAXT 320

typedef unsigned long long ull;
typedef uint32_t u32;
typedef unsigned short u16;

// ---------------- gmem image geometry ----------------
// A tiles: 6 chunks x (Ah [128][72]u16 18432 B | Al 18432 B)
#define ACH   36864
#define ASE   (6 * ACH)
// Weights per (s,e) (u16 images, [n][k-chunk] stride 72/40):
#define W1OFF 0
#define W2OFF 276480
#define W3OFF 370688
#define WSE   425984

__device__ int   g_is64;
__device__ int   g_blockCnt[NB * S_];
__device__ int   g_blockOff[NB * S_];
__device__ int   g_count[S_];
__device__ int   g_tbase[S_];
__device__ int   g_idx[S_ * N_];
__device__ float g_partial[NPART];
__device__ __align__(1024) unsigned char g_Wimg[(size_t)32 * WSE];
__device__ __align__(1024) unsigned char g_Aimg[(size_t)MAXT * ASE];

// ---------------- helpers ----------------
static __device__ __forceinline__ float celu_f(float x) {
    return x > 0.f ? x : 0.1f * expm1f(x * 10.f);
}
static __device__ __forceinline__ u32 s2u(const void* p) {
    u32 a;
    asm("{ .reg .u64 t; cvta.to.shared.u64 t, %1; cvt.u32.u64 %0, t; }" : "=r"(a) : "l"(p));
    return a;
}
static __device__ __forceinline__ void split2(float v, u16& h, u16& l) {
    __nv_bfloat16 hb = __float2bfloat16(v);
    float hf = __bfloat162float(hb);
    __nv_bfloat16 lb = __float2bfloat16(v - hf);
    h = __bfloat16_as_ushort(hb);
    l = __bfloat16_as_ushort(lb);
}
// fp32 pair -> packed bf16x2 hi + residual bf16x2 lo (x in low half, y in high)
static __device__ __forceinline__ void splitpair(float x, float y, u32& h, u32& l) {
    u32 hh;
    asm("cvt.rn.bf16x2.f32 %0, %1, %2;" : "=r"(hh) : "f"(y), "f"(x));
    float xh = __uint_as_float(hh << 16);
    float yh = __uint_as_float(hh & 0xffff0000u);
    asm("cvt.rn.bf16x2.f32 %0, %1, %2;" : "=r"(l) : "f"(y - yh), "f"(x - xh));
    h = hh;
}
static __device__ __forceinline__ void mma16816(float* c,
        u32 a0, u32 a1, u32 a2, u32 a3, u32 b0, u32 b1) {
    asm volatile(
        "mma.sync.aligned.m16n8k16.row.col.f32.bf16.bf16.f32 "
        "{%0,%1,%2,%3},{%4,%5,%6,%7},{%8,%9},{%0,%1,%2,%3};"
        : "+f"(c[0]), "+f"(c[1]), "+f"(c[2]), "+f"(c[3])
        : "r"(a0), "r"(a1), "r"(a2), "r"(a3), "r"(b0), "r"(b1));
}
#define CPA16(d, s) asm volatile("cp.async.cg.shared.global [%0], [%1], 16;" :: "r"(d), "l"(s) : "memory")
#define CPCOMMIT()  asm volatile("cp.async.commit_group;" ::: "memory")
#define CPWAIT(n)   asm volatile("cp.async.wait_group %0;" :: "n"(n) : "memory")

// ---------------- bucketing ----------------
__global__ void k_init(const ull* spq) {
    int tid = threadIdx.x;
    for (int i = tid; i < NPART; i += 256) g_partial[i] = 0.f;
    if (tid < 32) {
        ull v = spq[tid];
        int hiNZ = ((v >> 32) != 0ull) ? 1 : 0;
        int any = __any_sync(0xffffffffu, hiNZ);
        if (tid == 0) g_is64 = any ? 0 : 1;
    }
}
__global__ void k_count(const int* sp) {
    int tid = threadIdx.x, b = blockIdx.x;
    int n = b * 256 + tid;
    int shift = g_is64;
    int spv = -1;
    if (n < N_) spv = sp[(size_t)n << shift];
    __shared__ int wc[8][4];
    if (tid < 32) wc[tid >> 2][tid & 3] = 0;
    __syncthreads();
    unsigned mm = __match_any_sync(0xffffffffu, spv);
    int lane = tid & 31, w = tid >> 5;
    if (spv >= 0 && lane == (__ffs(mm) - 1)) wc[w][spv] = __popc(mm);
    __syncthreads();
    if (tid < 4) {
        int s = 0;
        for (int ww = 0; ww < 8; ww++) s += wc[ww][tid];
        g_blockCnt[b * 4 + tid] = s;
    }
}
__global__ void k_scan() {
    __shared__ int c[NB * 4];
    __shared__ int o[NB * 4];
    int tid = threadIdx.x;
    for (int i = tid; i < NB * 4; i += 256) c[i] = g_blockCnt[i];
    __syncthreads();
    if (tid == 0) {
        int r0 = 0, r1 = 0, r2 = 0, r3 = 0;
        for (int b = 0; b < NB; b++) {
            o[b * 4 + 0] = r0; r0 += c[b * 4 + 0];
            o[b * 4 + 1] = r1; r1 += c[b * 4 + 1];
            o[b * 4 + 2] = r2; r2 += c[b * 4 + 2];
            o[b * 4 + 3] = r3; r3 += c[b * 4 + 3];
        }
        g_count[0] = r0; g_count[1] = r1; g_count[2] = r2; g_count[3] = r3;
        int tb = 0;
        g_tbase[0] = 0;  tb += (r0 + TM - 1) / TM;
        g_tbase[1] = tb; tb += (r1 + TM - 1) / TM;
        g_tbase[2] = tb; tb += (r2 + TM - 1) / TM;
        g_tbase[3] = tb;
    }
    __syncthreads();
    for (int i = tid; i < NB * 4; i += 256) g_blockOff[i] = o[i];
}
__global__ void k_scatter(const int* sp) {
    int tid = threadIdx.x, b = blockIdx.x;
    int n = b * 256 + tid;
    int shift = g_is64;
    int spv = -1;
    if (n < N_) spv = sp[(size_t)n << shift];
    __shared__ int wc[8][4];
    __shared__ int woff[8][4];
    if (tid < 32) wc[tid >> 2][tid & 3] = 0;
    __syncthreads();
    unsigned mm = __match_any_sync(0xffffffffu, spv);
    int lane = tid & 31, w = tid >> 5;
    int rank = __popc(mm & ((1u << lane) - 1u));
    if (spv >= 0 && lane == (__ffs(mm) - 1)) wc[w][spv] = __popc(mm);
    __syncthreads();
    if (tid < 4) {
        int run = g_blockOff[b * 4 + tid];
        for (int ww = 0; ww < 8; ww++) { woff[ww][tid] = run; run += wc[ww][tid]; }
    }
    __syncthreads();
    if (spv >= 0) g_idx[spv * N_ + woff[w][spv] + rank] = n;
}

// ---------------- weight image prep (grid (32, 8)) ----------------
__global__ void k_wprep(const float* __restrict__ W1, const float* __restrict__ W2,
                        const float* __restrict__ W3) {
    int se = blockIdx.x;
    int tid0 = threadIdx.x + blockIdx.y * 256;
    const int step = 256 * 8;
    unsigned char* base = g_Wimg + (size_t)se * WSE;
    for (int i = tid0; i < D_ * H1_; i += step) {
        int n = i % H1_, k = i / H1_;
        u16 h, l; split2(W1[((size_t)se * D_ + k) * H1_ + n], h, l);
        int c = k >> 6, kl = k & 63;
        u16* p = (u16*)(base + W1OFF + c * 46080);
        p[n * 72 + kl] = h;
        p[11520 + n * 72 + kl] = l;
    }
    for (int i = tid0; i < H1_ * H2_; i += step) {
        int n = i % H2_, k = i / H2_;
        u16 h, l; split2(W2[((size_t)se * H1_ + k) * H2_ + n], h, l);
        int c = k >> 6, kl = k & 63;
        int str = (c == 2) ? 40 : 72, hlw = (c == 2) ? 5120 : 9216;
        int coff = (c == 0) ? 0 : (c == 1 ? 36864 : 73728);
        u16* p = (u16*)(base + W2OFF + coff);
        p[n * str + kl] = h;
        p[hlw + n * str + kl] = l;
    }
    for (int i = tid0; i < H2_ * H3_; i += step) {
        int n = i % H3_, k = i / H3_;
        u16 h, l; split2(W3[((size_t)se * H2_ + k) * H3_ + n], h, l);
        int c = k >> 6, kl = k & 63;
        u16* p = (u16*)(base + W3OFF + c * 27648);
        p[n * 72 + kl] = h;
        p[6912 + n * 72 + kl] = l;
    }
}

// ---------------- A image prep: gather + split to bf16 hi/lo ----------------
__global__ void k_aprep(const float* __restrict__ aev) {
    int t = blockIdx.x, s = blockIdx.y, tid = threadIdx.x;
    int cnt = g_count[s];
    int ntl = (cnt + TM - 1) / TM;
    if (t >= ntl) return;
    int gt = g_tbase[s] + t;
    __shared__ int sidx[TM];
    if (tid < TM) {
        int p = t * TM + tid; if (p >= cnt) p = cnt - 1;
        sidx[tid] = g_idx[s * N_ + p];
    }
    __syncthreads();
    unsigned char* base = g_Aimg + (size_t)gt * ASE;
    for (int i = tid; i < TM * (D_ / 2); i += 256) {
        int m = i / (D_ / 2), k = (i % (D_ / 2)) * 2;
        float2 v = *(const float2*)(aev + (size_t)sidx[m] * D_ + k);
        u32 h, l; splitpair(v.x, v.y, h, l);
        int c = k >> 6, kl = k & 63;
        u16* ch = (u16*)(base + c * ACH);
        *(u32*)(ch + m * 72 + kl) = h;
        *(u32*)(ch + 9216 + m * 72 + kl) = l;
    }
}

// ---------------- fragment GEMM, pre-split bf16 A, term-major ----------------
template<int NT>
static __device__ __forceinline__ void chunk_mma(
    float (*acc)[NT][4],
    const u16* Ah, const u16* Al, int astr,
    const u16* Wh, const u16* Wl, int wstr,
    int ksteps, int mbase, int nbase, int g, int q)
{
    for (int ks = 0; ks < ksteps; ks++) {
        const int k0 = ks * 16;
        u32 ah[2][4], al[2][4];
#pragma unroll
        for (int mt = 0; mt < 2; mt++) {
            const u16* ap = Ah + (mbase + mt * 16 + g) * astr + k0 + q * 2;
            const u16* aq = Al + (mbase + mt * 16 + g) * astr + k0 + q * 2;
            ah[mt][0] = *(const u32*)(ap);
            ah[mt][1] = *(const u32*)(ap + 8 * astr);
            ah[mt][2] = *(const u32*)(ap + 8);
            ah[mt][3] = *(const u32*)(ap + 8 * astr + 8);
            al[mt][0] = *(const u32*)(aq);
            al[mt][1] = *(const u32*)(aq + 8 * astr);
            al[mt][2] = *(const u32*)(aq + 8);
            al[mt][3] = *(const u32*)(aq + 8 * astr + 8);
        }
        u32 bh[NT][2];
#pragma unroll
        for (int nt = 0; nt < NT; nt++) {           // term 1: hi*hi
            const u16* wp = Wh + (nbase + nt * 8 + g) * wstr + k0 + q * 2;
            bh[nt][0] = *(const u32*)(wp);
            bh[nt][1] = *(const u32*)(wp + 8);
            mma16816(acc[0][nt], ah[0][0], ah[0][1], ah[0][2], ah[0][3], bh[nt][0], bh[nt][1]);
            mma16816(acc[1][nt], ah[1][0], ah[1][1], ah[1][2], ah[1][3], bh[nt][0], bh[nt][1]);
        }
#pragma unroll
        for (int nt = 0; nt < NT; nt++) {           // term 2: lo*hi (bh cached)
            mma16816(acc[0][nt], al[0][0], al[0][1], al[0][2], al[0][3], bh[nt][0], bh[nt][1]);
            mma16816(acc[1][nt], al[1][0], al[1][1], al[1][2], al[1][3], bh[nt][0], bh[nt][1]);
        }
#pragma unroll
        for (int nt = 0; nt < NT; nt++) {           // term 3: hi*lo
            const u16* wq = Wl + (nbase + nt * 8 + g) * wstr + k0 + q * 2;
            u32 bl0 = *(const u32*)(wq);
            u32 bl1 = *(const u32*)(wq + 8);
            mma16816(acc[0][nt], ah[0][0], ah[0][1], ah[0][2], ah[0][3], bl0, bl1);
            mma16816(acc[1][nt], ah[1][0], ah[1][1], ah[1][2], ah[1][3], bl0, bl1);
        }
    }
}

// ---------------- main kernel ----------------
#define STG1  82944
#define WB0   98304
#define WB1   135168
#define MISCO 172032
#define SMEMB (MISCO + 3072)

__global__ void __launch_bounds__(256, 1) k_main(
    const float* __restrict__ b1, const float* __restrict__ b2,
    const float* __restrict__ b3, const float* __restrict__ W4,
    const float* __restrict__ b4)
{
    extern __shared__ __align__(16) unsigned char sm[];
    const int s = blockIdx.y, t = blockIdx.x, z = blockIdx.z, tid = threadIdx.x;
    const int cnt = g_count[s];
    const int ntl = (cnt + TM - 1) / TM;
    if (t >= ntl) return;
    const int nvalid = min(TM, cnt - t * TM);
    const int gt = g_tbase[s] + t;
    const int lane = tid & 31, w = tid >> 5;
    const int wm = w & 3, wn = w >> 2, g = lane >> 2, q = lane & 3;
    const int mbase = wm * 32;
    const u32 sb = s2u(sm);
    float* b1s = (float*)(sm + MISCO);
    float* b2s = b1s + 160;
    float* b3s = b2s + 128;
    float* w4s = b3s + 96;
    float* part = w4s + 96;

    const unsigned char* Ab = g_Aimg + (size_t)gt * ASE;
    float blockSum = 0.f;

    const int h1off[3]  = {0, 36864, 73728};
    const int h1half[3] = {9216, 9216, 5120};     // u16 elements
    const int h1str[3]  = {72, 72, 40};

    for (int ei = 0; ei < 2; ei++) {
        const int se = s * E_ + z * 2 + ei;
        const unsigned char* Wb = g_Wimg + (size_t)se * WSE;
        if (tid < 160) b1s[tid] = b1[se * H1_ + tid];
        if (tid < 128) b2s[tid] = b2[se * H2_ + tid];
        if (tid < 96) { b3s[tid] = b3[se * H3_ + tid]; w4s[tid] = W4[se * H3_ + tid]; }

        // ================= Layer 1 (K=384, N=160) =================
        float acc1[2][10][4];
#pragma unroll
        for (int a = 0; a < 2; a++)
#pragma unroll
            for (int b = 0; b < 10; b++)
#pragma unroll
                for (int c = 0; c < 4; c++) acc1[a][b][c] = 0.f;

        auto cpyL1 = [&](int c, int bf) {
            u32 dst = sb + (bf ? STG1 : 0);
            const unsigned char* gA = Ab + c * ACH;
            for (int i = tid * 16; i < ACH; i += 4096) CPA16(dst + i, gA + i);
            const unsigned char* gW = Wb + W1OFF + c * 46080;
            for (int i = tid * 16; i < 46080; i += 4096) CPA16(dst + ACH + i, gW + i);
            CPCOMMIT();
        };
        cpyL1(0, 0); cpyL1(1, 1);
        for (int kc = 0; kc < 6; kc++) {
            if (kc == 5) { CPWAIT(0); } else { CPWAIT(1); }
            __syncthreads();
            const unsigned char* st = sm + ((kc & 1) ? STG1 : 0);
            chunk_mma<10>(acc1, (const u16*)st, (const u16*)st + 9216, 72,
                          (const u16*)(st + ACH), (const u16*)(st + ACH + 23040), 72,
                          4, mbase, wn * 80, g, q);
            __syncthreads();
            if (kc < 4) cpyL1(kc + 2, kc & 1);
        }
        // epilogue -> H1 (bf16 hi/lo)
#pragma unroll
        for (int mt = 0; mt < 2; mt++)
#pragma unroll
            for (int nt = 0; nt < 10; nt++) {
                int n0 = wn * 80 + nt * 8 + q * 2;
                int cb = n0 >> 6, off = n0 & 63;
                u16* Hh = (u16*)(sm + h1off[cb]);
                u16* Hl = Hh + h1half[cb];
                int str = h1str[cb];
                int row = mbase + mt * 16 + g;
                u32 h, l;
                splitpair(celu_f(acc1[mt][nt][0] + b1s[n0]),
                          celu_f(acc1[mt][nt][1] + b1s[n0 + 1]), h, l);
                *(u32*)(Hh + row * str + off) = h;
                *(u32*)(Hl + row * str + off) = l;
                splitpair(celu_f(acc1[mt][nt][2] + b1s[n0]),
                          celu_f(acc1[mt][nt][3] + b1s[n0 + 1]), h, l);
                *(u32*)(Hh + (row + 8) * str + off) = h;
                *(u32*)(Hl + (row + 8) * str + off) = l;
            }
        __syncthreads();

        // ================= Layer 2 (K=160, N=128) =================
        float acc2[2][8][4];
#pragma unroll
        for (int a = 0; a < 2; a++)
#pragma unroll
            for (int b = 0; b < 8; b++)
#pragma unroll
                for (int c = 0; c < 4; c++) acc2[a][b][c] = 0.f;

        auto cpyW = [&](const unsigned char* src, int bytes, u32 dstoff) {
            for (int i = tid * 16; i < bytes; i += 4096) CPA16(sb + dstoff + i, src + i);
            CPCOMMIT();
        };
        cpyW(Wb + W2OFF, 36864, WB0);
        cpyW(Wb + W2OFF + 36864, 36864, WB1);
        for (int kc = 0; kc < 3; kc++) {
            if (kc == 2) { CPWAIT(0); } else { CPWAIT(1); }
            __syncthreads();
            const unsigned char* wb = sm + ((kc & 1) ? WB1 : WB0);
            int str = (kc == 2) ? 40 : 72;
            int hl = (kc == 2) ? 5120 : 9216;          // u16 elements
            int ks = (kc == 2) ? 2 : 4;
            chunk_mma<8>(acc2,
                         (const u16*)(sm + h1off[kc]), (const u16*)(sm + h1off[kc]) + h1half[kc], h1str[kc],
                         (const u16*)wb, (const u16*)wb + hl, str,
                         ks, mbase, wn * 64, g, q);
            __syncthreads();
            if (kc == 0) cpyW(Wb + W2OFF + 73728, 20480, WB0);
        }
        // epilogue -> H2 (bf16 hi/lo @ {0, 36864})
#pragma unroll
        for (int mt = 0; mt < 2; mt++)
#pragma unroll
            for (int nt = 0; nt < 8; nt++) {
                int n0 = wn * 64 + nt * 8 + q * 2;
                int cb = n0 >> 6, off = n0 & 63;
                u16* Hh = (u16*)(sm + cb * 36864);
                u16* Hl = Hh + 9216;
                int row = mbase + mt * 16 + g;
                u32 h, l;
                splitpair(celu_f(acc2[mt][nt][0] + b2s[n0]),
                          celu_f(acc2[mt][nt][1] + b2s[n0 + 1]), h, l);
                *(u32*)(Hh + row * 72 + off) = h;
                *(u32*)(Hl + row * 72 + off) = l;
                splitpair(celu_f(acc2[mt][nt][2] + b2s[n0]),
                          celu_f(acc2[mt][nt][3] + b2s[n0 + 1]), h, l);
                *(u32*)(Hh + (row + 8) * 72 + off) = h;
                *(u32*)(Hl + (row + 8) * 72 + off) = l;
            }
        __syncthreads();

        // ================= Layer 3 (K=128, N=96) =================
        float acc3[2][6][4];
#pragma unroll
        for (int a = 0; a < 2; a++)
#pragma unroll
            for (int b = 0; b < 6; b++)
#pragma unroll
                for (int c = 0; c < 4; c++) acc3[a][b][c] = 0.f;

        cpyW(Wb + W3OFF, 27648, WB0);
        cpyW(Wb + W3OFF + 27648, 27648, WB1);
        for (int kc = 0; kc < 2; kc++) {
            if (kc == 1) { CPWAIT(0); } else { CPWAIT(1); }
            __syncthreads();
            const unsigned char* wb = sm + ((kc & 1) ? WB1 : WB0);
            chunk_mma<6>(acc3,
                         (const u16*)(sm + kc * 36864), (const u16*)(sm + kc * 36864) + 9216, 72,
                         (const u16*)wb, (const u16*)wb + 6912, 72,
                         4, mbase, wn * 48, g, q);
            __syncthreads();
        }
        // ================= fused L3-epilogue + Layer 4 =================
        {
            float p00 = 0.f, p01 = 0.f, p10 = 0.f, p11 = 0.f;
#pragma unroll
            for (int nt = 0; nt < 6; nt++) {
                int n0 = wn * 48 + nt * 8 + q * 2;
                float w0 = w4s[n0], w1 = w4s[n0 + 1];
                float bb0 = b3s[n0], bb1 = b3s[n0 + 1];
                p00 += celu_f(acc3[0][nt][0] + bb0) * w0 + celu_f(acc3[0][nt][1] + bb1) * w1;
                p01 += celu_f(acc3[0][nt][2] + bb0) * w0 + celu_f(acc3[0][nt][3] + bb1) * w1;
                p10 += celu_f(acc3[1][nt][0] + bb0) * w0 + celu_f(acc3[1][nt][1] + bb1) * w1;
                p11 += celu_f(acc3[1][nt][2] + bb0) * w0 + celu_f(acc3[1][nt][3] + bb1) * w1;
            }
            p00 += __shfl_xor_sync(0xffffffffu, p00, 1); p00 += __shfl_xor_sync(0xffffffffu, p00, 2);
            p01 += __shfl_xor_sync(0xffffffffu, p01, 1); p01 += __shfl_xor_sync(0xffffffffu, p01, 2);
            p10 += __shfl_xor_sync(0xffffffffu, p10, 1); p10 += __shfl_xor_sync(0xffffffffu, p10, 2);
            p11 += __shfl_xor_sync(0xffffffffu, p11, 1); p11 += __shfl_xor_sync(0xffffffffu, p11, 2);
            if (q == 0) {
                part[wn * 128 + mbase + g]          = p00;
                part[wn * 128 + mbase + g + 8]      = p01;
                part[wn * 128 + mbase + 16 + g]     = p10;
                part[wn * 128 + mbase + 16 + g + 8] = p11;
            }
        }
        __syncthreads();
        if (tid < 128) {
            float en = part[tid] + part[128 + tid] + b4[se];
            part[tid] = (tid < nvalid) ? en : 0.f;
        }
        __syncthreads();
        if (tid < 32) {
            float v = part[tid] + part[tid + 32] + part[tid + 64] + part[tid + 96];
            for (int o = 16; o; o >>= 1) v += __shfl_down_sync(0xffffffffu, v, o);
            if (tid == 0) blockSum += v;
        }
        __syncthreads();
    }
    if (tid == 0) g_partial[(s * NTT + t) * 4 + z] = blockSum;
}

// ---------------- final reduction ----------------
__global__ void k_reduce(float* out) {
    __shared__ double sb[256];
    int tid = threadIdx.x;
    double s = 0.0;
    for (int i = tid; i < NPART; i += 256) s += (double)g_partial[i];
    sb[tid] = s;
    __syncthreads();
    for (int st = 128; st; st >>= 1) {
        if (tid < st) sb[tid] += sb[tid + st];
        __syncthreads();
    }
    if (tid == 0) out[0] = (float)(sb[0] * (1.0 / E_));
}

// ---------------- launch ----------------
extern "C" void kernel_launch(void* const* d_in, const int* in_sizes, int n_in,
                              void* d_out, int out_size)
{
    const void*  sp  = d_in[0];
    const float* aev = (const float*)d_in[1];
    const float* W1  = (const float*)d_in[2];
    const float* b1  = (const float*)d_in[3];
    const float* W2  = (const float*)d_in[4];
    const float* b2  = (const float*)d_in[5];
    const float* W3  = (const float*)d_in[6];
    const float* b3  = (const float*)d_in[7];
    const float* W4  = (const float*)d_in[8];
    const float* b4  = (const float*)d_in[9];

    cudaFuncSetAttribute(k_main, cudaFuncAttributeMaxDynamicSharedMemorySize, SMEMB);

    k_init<<<1, 256>>>((const ull*)sp);
    k_count<<<NB, 256>>>((const int*)sp);
    k_scan<<<1, 256>>>();
    k_scatter<<<NB, 256>>>((const int*)sp);
    dim3 gw(32, 8);
    k_wprep<<<gw, 256>>>(W1, W2, W3);
    dim3 ga(NTT, S_);
    k_aprep<<<ga, 256>>>(aev);
    dim3 gm(NTT, S_, 4);
    k_main<<<gm, 256, SMEMB>>>(b1, b2, b3, W4, b4);
    k_reduce<<<1, 256>>>((float*)d_out);
}

// round 7
// speedup vs baseline: 2.7053x; 1.2744x over previous
#include <cuda_runtime.h>
#include <cuda_bf16.h>
#include <cstdint>
#include <math.h>

#define S_  4
#define E_  8
#define D_  384
#define H1_ 160
#define H2_ 128
#define H3_ 96
#define N_  40000
#define TM  128
#define NTT 313
#define NB  ((N_ + 255) / 256)
#define NPART (NTT * S_ * 4)
#define MAXT 320
#define THREADS 512

typedef unsigned long long ull;
typedef uint32_t u32;
typedef unsigned short u16;

// ---------------- gmem image geometry ----------------
#define ACH   36864
#define ASE   (6 * ACH)
#define W1OFF 0
#define W2OFF 276480
#define W3OFF 370688
#define WSE   425984

__device__ int   g_is64;
__device__ int   g_blockCnt[NB * S_];
__device__ int   g_blockOff[NB * S_];
__device__ int   g_count[S_];
__device__ int   g_tbase[S_];
__device__ int   g_idx[S_ * N_];
__device__ float g_partial[NPART];
__device__ __align__(1024) unsigned char g_Wimg[(size_t)32 * WSE];
__device__ __align__(1024) unsigned char g_Aimg[(size_t)MAXT * ASE];

// ---------------- helpers ----------------
static __device__ __forceinline__ float celu_f(float x) {
    return x > 0.f ? x : 0.1f * expm1f(x * 10.f);
}
static __device__ __forceinline__ u32 s2u(const void* p) {
    u32 a;
    asm("{ .reg .u64 t; cvta.to.shared.u64 t, %1; cvt.u32.u64 %0, t; }" : "=r"(a) : "l"(p));
    return a;
}
static __device__ __forceinline__ void split2(float v, u16& h, u16& l) {
    __nv_bfloat16 hb = __float2bfloat16(v);
    float hf = __bfloat162float(hb);
    __nv_bfloat16 lb = __float2bfloat16(v - hf);
    h = __bfloat16_as_ushort(hb);
    l = __bfloat16_as_ushort(lb);
}
static __device__ __forceinline__ void splitpair(float x, float y, u32& h, u32& l) {
    u32 hh;
    asm("cvt.rn.bf16x2.f32 %0, %1, %2;" : "=r"(hh) : "f"(y), "f"(x));
    float xh = __uint_as_float(hh << 16);
    float yh = __uint_as_float(hh & 0xffff0000u);
    asm("cvt.rn.bf16x2.f32 %0, %1, %2;" : "=r"(l) : "f"(y - yh), "f"(x - xh));
    h = hh;
}
static __device__ __forceinline__ void mma16816(float* c,
        u32 a0, u32 a1, u32 a2, u32 a3, u32 b0, u32 b1) {
    asm volatile(
        "mma.sync.aligned.m16n8k16.row.col.f32.bf16.bf16.f32 "
        "{%0,%1,%2,%3},{%4,%5,%6,%7},{%8,%9},{%0,%1,%2,%3};"
        : "+f"(c[0]), "+f"(c[1]), "+f"(c[2]), "+f"(c[3])
        : "r"(a0), "r"(a1), "r"(a2), "r"(a3), "r"(b0), "r"(b1));
}
#define CPA16(d, s) asm volatile("cp.async.cg.shared.global [%0], [%1], 16;" :: "r"(d), "l"(s) : "memory")
#define CPCOMMIT()  asm volatile("cp.async.commit_group;" ::: "memory")
#define CPWAIT(n)   asm volatile("cp.async.wait_group %0;" :: "n"(n) : "memory")

// ---------------- bucketing ----------------
__global__ void k_init(const ull* spq) {
    int tid = threadIdx.x;
    for (int i = tid; i < NPART; i += 256) g_partial[i] = 0.f;
    if (tid < 32) {
        ull v = spq[tid];
        int hiNZ = ((v >> 32) != 0ull) ? 1 : 0;
        int any = __any_sync(0xffffffffu, hiNZ);
        if (tid == 0) g_is64 = any ? 0 : 1;
    }
}
__global__ void k_count(const int* sp) {
    int tid = threadIdx.x, b = blockIdx.x;
    int n = b * 256 + tid;
    int shift = g_is64;
    int spv = -1;
    if (n < N_) spv = sp[(size_t)n << shift];
    __shared__ int wc[8][4];
    if (tid < 32) wc[tid >> 2][tid & 3] = 0;
    __syncthreads();
    unsigned mm = __match_any_sync(0xffffffffu, spv);
    int lane = tid & 31, w = tid >> 5;
    if (spv >= 0 && lane == (__ffs(mm) - 1)) wc[w][spv] = __popc(mm);
    __syncthreads();
    if (tid < 4) {
        int s = 0;
        for (int ww = 0; ww < 8; ww++) s += wc[ww][tid];
        g_blockCnt[b * 4 + tid] = s;
    }
}
__global__ void k_scan() {
    __shared__ int c[NB * 4];
    __shared__ int o[NB * 4];
    int tid = threadIdx.x;
    for (int i = tid; i < NB * 4; i += 256) c[i] = g_blockCnt[i];
    __syncthreads();
    if (tid == 0) {
        int r0 = 0, r1 = 0, r2 = 0, r3 = 0;
        for (int b = 0; b < NB; b++) {
            o[b * 4 + 0] = r0; r0 += c[b * 4 + 0];
            o[b * 4 + 1] = r1; r1 += c[b * 4 + 1];
            o[b * 4 + 2] = r2; r2 += c[b * 4 + 2];
            o[b * 4 + 3] = r3; r3 += c[b * 4 + 3];
        }
        g_count[0] = r0; g_count[1] = r1; g_count[2] = r2; g_count[3] = r3;
        int tb = 0;
        g_tbase[0] = 0;  tb += (r0 + TM - 1) / TM;
        g_tbase[1] = tb; tb += (r1 + TM - 1) / TM;
        g_tbase[2] = tb; tb += (r2 + TM - 1) / TM;
        g_tbase[3] = tb;
    }
    __syncthreads();
    for (int i = tid; i < NB * 4; i += 256) g_blockOff[i] = o[i];
}
__global__ void k_scatter(const int* sp) {
    int tid = threadIdx.x, b = blockIdx.x;
    int n = b * 256 + tid;
    int shift = g_is64;
    int spv = -1;
    if (n < N_) spv = sp[(size_t)n << shift];
    __shared__ int wc[8][4];
    __shared__ int woff[8][4];
    if (tid < 32) wc[tid >> 2][tid & 3] = 0;
    __syncthreads();
    unsigned mm = __match_any_sync(0xffffffffu, spv);
    int lane = tid & 31, w = tid >> 5;
    int rank = __popc(mm & ((1u << lane) - 1u));
    if (spv >= 0 && lane == (__ffs(mm) - 1)) wc[w][spv] = __popc(mm);
    __syncthreads();
    if (tid < 4) {
        int run = g_blockOff[b * 4 + tid];
        for (int ww = 0; ww < 8; ww++) { woff[ww][tid] = run; run += wc[ww][tid]; }
    }
    __syncthreads();
    if (spv >= 0) g_idx[spv * N_ + woff[w][spv] + rank] = n;
}

// ---------------- weight image prep ----------------
__global__ void k_wprep(const float* __restrict__ W1, const float* __restrict__ W2,
                        const float* __restrict__ W3) {
    int se = blockIdx.x;
    int tid0 = threadIdx.x + blockIdx.y * 256;
    const int step = 256 * 8;
    unsigned char* base = g_Wimg + (size_t)se * WSE;
    for (int i = tid0; i < D_ * H1_; i += step) {
        int n = i % H1_, k = i / H1_;
        u16 h, l; split2(W1[((size_t)se * D_ + k) * H1_ + n], h, l);
        int c = k >> 6, kl = k & 63;
        u16* p = (u16*)(base + W1OFF + c * 46080);
        p[n * 72 + kl] = h;
        p[11520 + n * 72 + kl] = l;
    }
    for (int i = tid0; i < H1_ * H2_; i += step) {
        int n = i % H2_, k = i / H2_;
        u16 h, l; split2(W2[((size_t)se * H1_ + k) * H2_ + n], h, l);
        int c = k >> 6, kl = k & 63;
        int str = (c == 2) ? 40 : 72, hlw = (c == 2) ? 5120 : 9216;
        int coff = (c == 0) ? 0 : (c == 1 ? 36864 : 73728);
        u16* p = (u16*)(base + W2OFF + coff);
        p[n * str + kl] = h;
        p[hlw + n * str + kl] = l;
    }
    for (int i = tid0; i < H2_ * H3_; i += step) {
        int n = i % H3_, k = i / H3_;
        u16 h, l; split2(W3[((size_t)se * H2_ + k) * H3_ + n], h, l);
        int c = k >> 6, kl = k & 63;
        u16* p = (u16*)(base + W3OFF + c * 27648);
        p[n * 72 + kl] = h;
        p[6912 + n * 72 + kl] = l;
    }
}

// ---------------- A image prep ----------------
__global__ void k_aprep(const float* __restrict__ aev) {
    int t = blockIdx.x, s = blockIdx.y, tid = threadIdx.x;
    int cnt = g_count[s];
    int ntl = (cnt + TM - 1) / TM;
    if (t >= ntl) return;
    int gt = g_tbase[s] + t;
    __shared__ int sidx[TM];
    if (tid < TM) {
        int p = t * TM + tid; if (p >= cnt) p = cnt - 1;
        sidx[tid] = g_idx[s * N_ + p];
    }
    __syncthreads();
    unsigned char* base = g_Aimg + (size_t)gt * ASE;
    for (int i = tid; i < TM * (D_ / 2); i += 256) {
        int m = i / (D_ / 2), k = (i % (D_ / 2)) * 2;
        float2 v = *(const float2*)(aev + (size_t)sidx[m] * D_ + k);
        u32 h, l; splitpair(v.x, v.y, h, l);
        int c = k >> 6, kl = k & 63;
        u16* ch = (u16*)(base + c * ACH);
        *(u32*)(ch + m * 72 + kl) = h;
        *(u32*)(ch + 9216 + m * 72 + kl) = l;
    }
}

// ---------------- fragment GEMM, term-major ----------------
template<int NT>
static __device__ __forceinline__ void chunk_mma(
    float (*acc)[NT][4],
    const u16* Ah, const u16* Al, int astr,
    const u16* Wh, const u16* Wl, int wstr,
    int ksteps, int mbase, int nbase, int g, int q)
{
    for (int ks = 0; ks < ksteps; ks++) {
        const int k0 = ks * 16;
        u32 ah[2][4], al[2][4];
#pragma unroll
        for (int mt = 0; mt < 2; mt++) {
            const u16* ap = Ah + (mbase + mt * 16 + g) * astr + k0 + q * 2;
            const u16* aq = Al + (mbase + mt * 16 + g) * astr + k0 + q * 2;
            ah[mt][0] = *(const u32*)(ap);
            ah[mt][1] = *(const u32*)(ap + 8 * astr);
            ah[mt][2] = *(const u32*)(ap + 8);
            ah[mt][3] = *(const u32*)(ap + 8 * astr + 8);
            al[mt][0] = *(const u32*)(aq);
            al[mt][1] = *(const u32*)(aq + 8 * astr);
            al[mt][2] = *(const u32*)(aq + 8);
            al[mt][3] = *(const u32*)(aq + 8 * astr + 8);
        }
        u32 bh[NT][2];
#pragma unroll
        for (int nt = 0; nt < NT; nt++) {           // term 1: hi*hi
            const u16* wp = Wh + (nbase + nt * 8 + g) * wstr + k0 + q * 2;
            bh[nt][0] = *(const u32*)(wp);
            bh[nt][1] = *(const u32*)(wp + 8);
            mma16816(acc[0][nt], ah[0][0], ah[0][1], ah[0][2], ah[0][3], bh[nt][0], bh[nt][1]);
            mma16816(acc[1][nt], ah[1][0], ah[1][1], ah[1][2], ah[1][3], bh[nt][0], bh[nt][1]);
        }
#pragma unroll
        for (int nt = 0; nt < NT; nt++) {           // term 2: lo*hi
            mma16816(acc[0][nt], al[0][0], al[0][1], al[0][2], al[0][3], bh[nt][0], bh[nt][1]);
            mma16816(acc[1][nt], al[1][0], al[1][1], al[1][2], al[1][3], bh[nt][0], bh[nt][1]);
        }
#pragma unroll
        for (int nt = 0; nt < NT; nt++) {           // term 3: hi*lo
            const u16* wq = Wl + (nbase + nt * 8 + g) * wstr + k0 + q * 2;
            u32 bl0 = *(const u32*)(wq);
            u32 bl1 = *(const u32*)(wq + 8);
            mma16816(acc[0][nt], ah[0][0], ah[0][1], ah[0][2], ah[0][3], bl0, bl1);
            mma16816(acc[1][nt], ah[1][0], ah[1][1], ah[1][2], ah[1][3], bl0, bl1);
        }
    }
}

// ---------------- main kernel ----------------
#define STG1  82944
#define WB0   98304
#define WB1   135168
#define MISCO 172032
#define SMEMB (MISCO + 4096)

__global__ void __launch_bounds__(THREADS, 1) k_main(
    const float* __restrict__ b1, const float* __restrict__ b2,
    const float* __restrict__ b3, const float* __restrict__ W4,
    const float* __restrict__ b4)
{
    extern __shared__ __align__(16) unsigned char sm[];
    const int s = blockIdx.y, t = blockIdx.x, z = blockIdx.z, tid = threadIdx.x;
    const int cnt = g_count[s];
    const int ntl = (cnt + TM - 1) / TM;
    if (t >= ntl) return;
    const int nvalid = min(TM, cnt - t * TM);
    const int gt = g_tbase[s] + t;
    const int lane = tid & 31, w = tid >> 5;
    const int wm = w & 3, wn = w >> 2, g = lane >> 2, q = lane & 3;
    const int mbase = wm * 32;
    const u32 sb = s2u(sm);
    float* b1s = (float*)(sm + MISCO);
    float* b2s = b1s + 160;
    float* b3s = b2s + 128;
    float* w4s = b3s + 96;
    float* part = w4s + 96;           // 512 floats

    const unsigned char* Ab = g_Aimg + (size_t)gt * ASE;
    float blockSum = 0.f;

    const int h1off[3]  = {0, 36864, 73728};
    const int h1half[3] = {9216, 9216, 5120};
    const int h1str[3]  = {72, 72, 40};

    for (int ei = 0; ei < 2; ei++) {
        const int se = s * E_ + z * 2 + ei;
        const unsigned char* Wb = g_Wimg + (size_t)se * WSE;
        if (tid < 160) b1s[tid] = b1[se * H1_ + tid];
        if (tid < 128) b2s[tid] = b2[se * H2_ + tid];
        if (tid < 96) { b3s[tid] = b3[se * H3_ + tid]; w4s[tid] = W4[se * H3_ + tid]; }

        // ================= Layer 1 (K=384, N=160): NT=5 per warp =================
        float acc1[2][5][4];
#pragma unroll
        for (int a = 0; a < 2; a++)
#pragma unroll
            for (int b = 0; b < 5; b++)
#pragma unroll
                for (int c = 0; c < 4; c++) acc1[a][b][c] = 0.f;

        auto cpyL1 = [&](int c, int bf) {
            u32 dst = sb + (bf ? STG1 : 0);
            const unsigned char* gA = Ab + c * ACH;
            for (int i = tid * 16; i < ACH; i += THREADS * 16) CPA16(dst + i, gA + i);
            const unsigned char* gW = Wb + W1OFF + c * 46080;
            for (int i = tid * 16; i < 46080; i += THREADS * 16) CPA16(dst + ACH + i, gW + i);
            CPCOMMIT();
        };
        cpyL1(0, 0); cpyL1(1, 1);
        for (int kc = 0; kc < 6; kc++) {
            if (kc == 5) { CPWAIT(0); } else { CPWAIT(1); }
            __syncthreads();
            const unsigned char* st = sm + ((kc & 1) ? STG1 : 0);
            chunk_mma<5>(acc1, (const u16*)st, (const u16*)st + 9216, 72,
                         (const u16*)(st + ACH), (const u16*)(st + ACH + 23040), 72,
                         4, mbase, wn * 40, g, q);
            __syncthreads();
            if (kc < 4) cpyL1(kc + 2, kc & 1);
        }
        // epilogue -> H1 (bf16 hi/lo)
#pragma unroll
        for (int mt = 0; mt < 2; mt++)
#pragma unroll
            for (int nt = 0; nt < 5; nt++) {
                int n0 = wn * 40 + nt * 8 + q * 2;
                int cb = n0 >> 6, off = n0 & 63;
                u16* Hh = (u16*)(sm + h1off[cb]);
                u16* Hl = Hh + h1half[cb];
                int str = h1str[cb];
                int row = mbase + mt * 16 + g;
                u32 h, l;
                splitpair(celu_f(acc1[mt][nt][0] + b1s[n0]),
                          celu_f(acc1[mt][nt][1] + b1s[n0 + 1]), h, l);
                *(u32*)(Hh + row * str + off) = h;
                *(u32*)(Hl + row * str + off) = l;
                splitpair(celu_f(acc1[mt][nt][2] + b1s[n0]),
                          celu_f(acc1[mt][nt][3] + b1s[n0 + 1]), h, l);
                *(u32*)(Hh + (row + 8) * str + off) = h;
                *(u32*)(Hl + (row + 8) * str + off) = l;
            }
        __syncthreads();

        // ================= Layer 2 (K=160, N=128): NT=4 =================
        float acc2[2][4][4];
#pragma unroll
        for (int a = 0; a < 2; a++)
#pragma unroll
            for (int b = 0; b < 4; b++)
#pragma unroll
                for (int c = 0; c < 4; c++) acc2[a][b][c] = 0.f;

        auto cpyW = [&](const unsigned char* src, int bytes, u32 dstoff) {
            for (int i = tid * 16; i < bytes; i += THREADS * 16) CPA16(sb + dstoff + i, src + i);
            CPCOMMIT();
        };
        cpyW(Wb + W2OFF, 36864, WB0);
        cpyW(Wb + W2OFF + 36864, 36864, WB1);
        for (int kc = 0; kc < 3; kc++) {
            if (kc == 2) { CPWAIT(0); } else { CPWAIT(1); }
            __syncthreads();
            const unsigned char* wb = sm + ((kc & 1) ? WB1 : WB0);
            int str = (kc == 2) ? 40 : 72;
            int hl = (kc == 2) ? 5120 : 9216;
            int ks = (kc == 2) ? 2 : 4;
            chunk_mma<4>(acc2,
                         (const u16*)(sm + h1off[kc]), (const u16*)(sm + h1off[kc]) + h1half[kc], h1str[kc],
                         (const u16*)wb, (const u16*)wb + hl, str,
                         ks, mbase, wn * 32, g, q);
            __syncthreads();
            if (kc == 0) cpyW(Wb + W2OFF + 73728, 20480, WB0);
        }
        // epilogue -> H2
#pragma unroll
        for (int mt = 0; mt < 2; mt++)
#pragma unroll
            for (int nt = 0; nt < 4; nt++) {
                int n0 = wn * 32 + nt * 8 + q * 2;
                int cb = n0 >> 6, off = n0 & 63;
                u16* Hh = (u16*)(sm + cb * 36864);
                u16* Hl = Hh + 9216;
                int row = mbase + mt * 16 + g;
                u32 h, l;
                splitpair(celu_f(acc2[mt][nt][0] + b2s[n0]),
                          celu_f(acc2[mt][nt][1] + b2s[n0 + 1]), h, l);
                *(u32*)(Hh + row * 72 + off) = h;
                *(u32*)(Hl + row * 72 + off) = l;
                splitpair(celu_f(acc2[mt][nt][2] + b2s[n0]),
                          celu_f(acc2[mt][nt][3] + b2s[n0 + 1]), h, l);
                *(u32*)(Hh + (row + 8) * 72 + off) = h;
                *(u32*)(Hl + (row + 8) * 72 + off) = l;
            }
        __syncthreads();

        // ================= Layer 3 (K=128, N=96): NT=3 =================
        float acc3[2][3][4];
#pragma unroll
        for (int a = 0; a < 2; a++)
#pragma unroll
            for (int b = 0; b < 3; b++)
#pragma unroll
                for (int c = 0; c < 4; c++) acc3[a][b][c] = 0.f;

        cpyW(Wb + W3OFF, 27648, WB0);
        cpyW(Wb + W3OFF + 27648, 27648, WB1);
        for (int kc = 0; kc < 2; kc++) {
            if (kc == 1) { CPWAIT(0); } else { CPWAIT(1); }
            __syncthreads();
            const unsigned char* wb = sm + ((kc & 1) ? WB1 : WB0);
            chunk_mma<3>(acc3,
                         (const u16*)(sm + kc * 36864), (const u16*)(sm + kc * 36864) + 9216, 72,
                         (const u16*)wb, (const u16*)wb + 6912, 72,
                         4, mbase, wn * 24, g, q);
            __syncthreads();
        }
        // ================= fused L3-epilogue + Layer 4 =================
        {
            float p00 = 0.f, p01 = 0.f, p10 = 0.f, p11 = 0.f;
#pragma unroll
            for (int nt = 0; nt < 3; nt++) {
                int n0 = wn * 24 + nt * 8 + q * 2;
                float w0 = w4s[n0], w1 = w4s[n0 + 1];
                float bb0 = b3s[n0], bb1 = b3s[n0 + 1];
                p00 += celu_f(acc3[0][nt][0] + bb0) * w0 + celu_f(acc3[0][nt][1] + bb1) * w1;
                p01 += celu_f(acc3[0][nt][2] + bb0) * w0 + celu_f(acc3[0][nt][3] + bb1) * w1;
                p10 += celu_f(acc3[1][nt][0] + bb0) * w0 + celu_f(acc3[1][nt][1] + bb1) * w1;
                p11 += celu_f(acc3[1][nt][2] + bb0) * w0 + celu_f(acc3[1][nt][3] + bb1) * w1;
            }
            p00 += __shfl_xor_sync(0xffffffffu, p00, 1); p00 += __shfl_xor_sync(0xffffffffu, p00, 2);
            p01 += __shfl_xor_sync(0xffffffffu, p01, 1); p01 += __shfl_xor_sync(0xffffffffu, p01, 2);
            p10 += __shfl_xor_sync(0xffffffffu, p10, 1); p10 += __shfl_xor_sync(0xffffffffu, p10, 2);
            p11 += __shfl_xor_sync(0xffffffffu, p11, 1); p11 += __shfl_xor_sync(0xffffffffu, p11, 2);
            if (q == 0) {
                part[wn * 128 + mbase + g]          = p00;
                part[wn * 128 + mbase + g + 8]      = p01;
                part[wn * 128 + mbase + 16 + g]     = p10;
                part[wn * 128 + mbase + 16 + g + 8] = p11;
            }
        }
        __syncthreads();
        if (tid < 128) {
            float en = part[tid] + part[128 + tid] + part[256 + tid] + part[384 + tid] + b4[se];
            part[tid] = (tid < nvalid) ? en : 0.f;
        }
        __syncthreads();
        if (tid < 32) {
            float v = part[tid] + part[tid + 32] + part[tid + 64] + part[tid + 96];
            for (int o = 16; o; o >>= 1) v += __shfl_down_sync(0xffffffffu, v, o);
            if (tid == 0) blockSum += v;
        }
        __syncthreads();
    }
    if (tid == 0) g_partial[(s * NTT + t) * 4 + z] = blockSum;
}

// ---------------- final reduction ----------------
__global__ void k_reduce(float* out) {
    __shared__ double sb[256];
    int tid = threadIdx.x;
    double s = 0.0;
    for (int i = tid; i < NPART; i += 256) s += (double)g_partial[i];
    sb[tid] = s;
    __syncthreads();
    for (int st = 128; st; st >>= 1) {
        if (tid < st) sb[tid] += sb[tid + st];
        __syncthreads();
    }
    if (tid == 0) out[0] = (float)(sb[0] * (1.0 / E_));
}

// ---------------- launch ----------------
extern "C" void kernel_launch(void* const* d_in, const int* in_sizes, int n_in,
                              void* d_out, int out_size)
{
    const void*  sp  = d_in[0];
    const float* aev = (const float*)d_in[1];
    const float* W1  = (const float*)d_in[2];
    const float* b1  = (const float*)d_in[3];
    const float* W2  = (const float*)d_in[4];
    const float* b2  = (const float*)d_in[5];
    const float* W3  = (const float*)d_in[6];
    const float* b3  = (const float*)d_in[7];
    const float* W4  = (const float*)d_in[8];
    const float* b4  = (const float*)d_in[9];

    cudaFuncSetAttribute(k_main, cudaFuncAttributeMaxDynamicSharedMemorySize, SMEMB);

    k_init<<<1, 256>>>((const ull*)sp);
    k_count<<<NB, 256>>>((const int*)sp);
    k_scan<<<1, 256>>>();
    k_scatter<<<NB, 256>>>((const int*)sp);
    dim3 gw(32, 8);
    k_wprep<<<gw, 256>>>(W1, W2, W3);
    dim3 ga(NTT, S_);
    k_aprep<<<ga, 256>>>(aev);
    dim3 gm(NTT, S_, 4);
    k_main<<<gm, THREADS, SMEMB>>>(b1, b2, b3, W4, b4);
    k_reduce<<<1, 256>>>((float*)d_out);
}

// round 8
// speedup vs baseline: 3.0106x; 1.1128x over previous
#include <cuda_runtime.h>
#include <cuda_bf16.h>
#include <cstdint>
#include <math.h>

#define S_  4
#define E_  8
#define D_  384
#define H1_ 160
#define H2_ 128
#define H3_ 96
#define N_  40000
#define TM  128
#define NTT 313
#define NB  ((N_ + 255) / 256)
#define NPART (NTT * S_ * 4)
#define MAXT 320
#define THREADS 512

typedef unsigned long long ull;
typedef uint32_t u32;
typedef unsigned short u16;

// ---------------- gmem image geometry ----------------
#define ACH   36864
#define ASE   (6 * ACH)
#define W1OFF 0
#define W2OFF 276480
#define W3OFF 370688
#define WSE   425984

__device__ int   g_is64;
__device__ int   g_blockCnt[NB * S_];
__device__ int   g_blockOff[NB * S_];
__device__ int   g_count[S_];
__device__ int   g_tbase[S_];
__device__ int   g_idx[S_ * N_];
__device__ float g_partial[NPART];
__device__ __align__(1024) unsigned char g_Wimg[(size_t)32 * WSE];
__device__ __align__(1024) unsigned char g_Aimg[(size_t)MAXT * ASE];

// ---------------- helpers ----------------
static __device__ __forceinline__ float celu_f(float x) {
    return x > 0.f ? x : 0.1f * (__expf(x * 10.f) - 1.f);
}
static __device__ __forceinline__ u32 s2u(const void* p) {
    u32 a;
    asm("{ .reg .u64 t; cvta.to.shared.u64 t, %1; cvt.u32.u64 %0, t; }" : "=r"(a) : "l"(p));
    return a;
}
static __device__ __forceinline__ void split2(float v, u16& h, u16& l) {
    __nv_bfloat16 hb = __float2bfloat16(v);
    float hf = __bfloat162float(hb);
    __nv_bfloat16 lb = __float2bfloat16(v - hf);
    h = __bfloat16_as_ushort(hb);
    l = __bfloat16_as_ushort(lb);
}
static __device__ __forceinline__ void splitpair(float x, float y, u32& h, u32& l) {
    u32 hh;
    asm("cvt.rn.bf16x2.f32 %0, %1, %2;" : "=r"(hh) : "f"(y), "f"(x));
    float xh = __uint_as_float(hh << 16);
    float yh = __uint_as_float(hh & 0xffff0000u);
    asm("cvt.rn.bf16x2.f32 %0, %1, %2;" : "=r"(l) : "f"(y - yh), "f"(x - xh));
    h = hh;
}
static __device__ __forceinline__ void mma16816(float* c,
        u32 a0, u32 a1, u32 a2, u32 a3, u32 b0, u32 b1) {
    asm volatile(
        "mma.sync.aligned.m16n8k16.row.col.f32.bf16.bf16.f32 "
        "{%0,%1,%2,%3},{%4,%5,%6,%7},{%8,%9},{%0,%1,%2,%3};"
        : "+f"(c[0]), "+f"(c[1]), "+f"(c[2]), "+f"(c[3])
        : "r"(a0), "r"(a1), "r"(a2), "r"(a3), "r"(b0), "r"(b1));
}
#define CPA16(d, s) asm volatile("cp.async.cg.shared.global [%0], [%1], 16;" :: "r"(d), "l"(s) : "memory")
#define CPCOMMIT()  asm volatile("cp.async.commit_group;" ::: "memory")
#define CPWAIT(n)   asm volatile("cp.async.wait_group %0;" :: "n"(n) : "memory")

// ---------------- bucketing ----------------
__global__ void k_init(const ull* spq) {
    int tid = threadIdx.x;
    for (int i = tid; i < NPART; i += 256) g_partial[i] = 0.f;
    if (tid < 32) {
        ull v = spq[tid];
        int hiNZ = ((v >> 32) != 0ull) ? 1 : 0;
        int any = __any_sync(0xffffffffu, hiNZ);
        if (tid == 0) g_is64 = any ? 0 : 1;
    }
}
__global__ void k_count(const int* sp) {
    int tid = threadIdx.x, b = blockIdx.x;
    int n = b * 256 + tid;
    int shift = g_is64;
    int spv = -1;
    if (n < N_) spv = sp[(size_t)n << shift];
    __shared__ int wc[8][4];
    if (tid < 32) wc[tid >> 2][tid & 3] = 0;
    __syncthreads();
    unsigned mm = __match_any_sync(0xffffffffu, spv);
    int lane = tid & 31, w = tid >> 5;
    if (spv >= 0 && lane == (__ffs(mm) - 1)) wc[w][spv] = __popc(mm);
    __syncthreads();
    if (tid < 4) {
        int s = 0;
        for (int ww = 0; ww < 8; ww++) s += wc[ww][tid];
        g_blockCnt[b * 4 + tid] = s;
    }
}
__global__ void k_scan() {
    __shared__ int c[NB * 4];
    __shared__ int o[NB * 4];
    int tid = threadIdx.x;
    for (int i = tid; i < NB * 4; i += 256) c[i] = g_blockCnt[i];
    __syncthreads();
    if (tid == 0) {
        int r0 = 0, r1 = 0, r2 = 0, r3 = 0;
        for (int b = 0; b < NB; b++) {
            o[b * 4 + 0] = r0; r0 += c[b * 4 + 0];
            o[b * 4 + 1] = r1; r1 += c[b * 4 + 1];
            o[b * 4 + 2] = r2; r2 += c[b * 4 + 2];
            o[b * 4 + 3] = r3; r3 += c[b * 4 + 3];
        }
        g_count[0] = r0; g_count[1] = r1; g_count[2] = r2; g_count[3] = r3;
        int tb = 0;
        g_tbase[0] = 0;  tb += (r0 + TM - 1) / TM;
        g_tbase[1] = tb; tb += (r1 + TM - 1) / TM;
        g_tbase[2] = tb; tb += (r2 + TM - 1) / TM;
        g_tbase[3] = tb;
    }
    __syncthreads();
    for (int i = tid; i < NB * 4; i += 256) g_blockOff[i] = o[i];
}
__global__ void k_scatter(const int* sp) {
    int tid = threadIdx.x, b = blockIdx.x;
    int n = b * 256 + tid;
    int shift = g_is64;
    int spv = -1;
    if (n < N_) spv = sp[(size_t)n << shift];
    __shared__ int wc[8][4];
    __shared__ int woff[8][4];
    if (tid < 32) wc[tid >> 2][tid & 3] = 0;
    __syncthreads();
    unsigned mm = __match_any_sync(0xffffffffu, spv);
    int lane = tid & 31, w = tid >> 5;
    int rank = __popc(mm & ((1u << lane) - 1u));
    if (spv >= 0 && lane == (__ffs(mm) - 1)) wc[w][spv] = __popc(mm);
    __syncthreads();
    if (tid < 4) {
        int run = g_blockOff[b * 4 + tid];
        for (int ww = 0; ww < 8; ww++) { woff[ww][tid] = run; run += wc[ww][tid]; }
    }
    __syncthreads();
    if (spv >= 0) g_idx[spv * N_ + woff[w][spv] + rank] = n;
}

// ---------------- weight image prep ----------------
__global__ void k_wprep(const float* __restrict__ W1, const float* __restrict__ W2,
                        const float* __restrict__ W3) {
    int se = blockIdx.x;
    int tid0 = threadIdx.x + blockIdx.y * 256;
    const int step = 256 * 8;
    unsigned char* base = g_Wimg + (size_t)se * WSE;
    for (int i = tid0; i < D_ * H1_; i += step) {
        int n = i % H1_, k = i / H1_;
        u16 h, l; split2(W1[((size_t)se * D_ + k) * H1_ + n], h, l);
        int c = k >> 6, kl = k & 63;
        u16* p = (u16*)(base + W1OFF + c * 46080);
        p[n * 72 + kl] = h;
        p[11520 + n * 72 + kl] = l;
    }
    for (int i = tid0; i < H1_ * H2_; i += step) {
        int n = i % H2_, k = i / H2_;
        u16 h, l; split2(W2[((size_t)se * H1_ + k) * H2_ + n], h, l);
        int c = k >> 6, kl = k & 63;
        int str = (c == 2) ? 40 : 72, hlw = (c == 2) ? 5120 : 9216;
        int coff = (c == 0) ? 0 : (c == 1 ? 36864 : 73728);
        u16* p = (u16*)(base + W2OFF + coff);
        p[n * str + kl] = h;
        p[hlw + n * str + kl] = l;
    }
    for (int i = tid0; i < H2_ * H3_; i += step) {
        int n = i % H3_, k = i / H3_;
        u16 h, l; split2(W3[((size_t)se * H2_ + k) * H3_ + n], h, l);
        int c = k >> 6, kl = k & 63;
        u16* p = (u16*)(base + W3OFF + c * 27648);
        p[n * 72 + kl] = h;
        p[6912 + n * 72 + kl] = l;
    }
}

// ---------------- A image prep ----------------
__global__ void k_aprep(const float* __restrict__ aev) {
    int t = blockIdx.x, s = blockIdx.y, tid = threadIdx.x;
    int cnt = g_count[s];
    int ntl = (cnt + TM - 1) / TM;
    if (t >= ntl) return;
    int gt = g_tbase[s] + t;
    __shared__ int sidx[TM];
    if (tid < TM) {
        int p = t * TM + tid; if (p >= cnt) p = cnt - 1;
        sidx[tid] = g_idx[s * N_ + p];
    }
    __syncthreads();
    unsigned char* base = g_Aimg + (size_t)gt * ASE;
    for (int i = tid; i < TM * (D_ / 2); i += 256) {
        int m = i / (D_ / 2), k = (i % (D_ / 2)) * 2;
        float2 v = *(const float2*)(aev + (size_t)sidx[m] * D_ + k);
        u32 h, l; splitpair(v.x, v.y, h, l);
        int c = k >> 6, kl = k & 63;
        u16* ch = (u16*)(base + c * ACH);
        *(u32*)(ch + m * 72 + kl) = h;
        *(u32*)(ch + 9216 + m * 72 + kl) = l;
    }
}

// ---------------- fragment GEMM, term-major ----------------
template<int NT>
static __device__ __forceinline__ void chunk_mma(
    float (*acc)[NT][4],
    const u16* Ah, const u16* Al, int astr,
    const u16* Wh, const u16* Wl, int wstr,
    int ksteps, int mbase, int nbase, int g, int q)
{
    for (int ks = 0; ks < ksteps; ks++) {
        const int k0 = ks * 16;
        u32 ah[2][4], al[2][4];
#pragma unroll
        for (int mt = 0; mt < 2; mt++) {
            const u16* ap = Ah + (mbase + mt * 16 + g) * astr + k0 + q * 2;
            const u16* aq = Al + (mbase + mt * 16 + g) * astr + k0 + q * 2;
            ah[mt][0] = *(const u32*)(ap);
            ah[mt][1] = *(const u32*)(ap + 8 * astr);
            ah[mt][2] = *(const u32*)(ap + 8);
            ah[mt][3] = *(const u32*)(ap + 8 * astr + 8);
            al[mt][0] = *(const u32*)(aq);
            al[mt][1] = *(const u32*)(aq + 8 * astr);
            al[mt][2] = *(const u32*)(aq + 8);
            al[mt][3] = *(const u32*)(aq + 8 * astr + 8);
        }
        u32 bh[NT][2];
#pragma unroll
        for (int nt = 0; nt < NT; nt++) {           // term 1: hi*hi
            const u16* wp = Wh + (nbase + nt * 8 + g) * wstr + k0 + q * 2;
            bh[nt][0] = *(const u32*)(wp);
            bh[nt][1] = *(const u32*)(wp + 8);
            mma16816(acc[0][nt], ah[0][0], ah[0][1], ah[0][2], ah[0][3], bh[nt][0], bh[nt][1]);
            mma16816(acc[1][nt], ah[1][0], ah[1][1], ah[1][2], ah[1][3], bh[nt][0], bh[nt][1]);
        }
#pragma unroll
        for (int nt = 0; nt < NT; nt++) {           // term 2: lo*hi
            mma16816(acc[0][nt], al[0][0], al[0][1], al[0][2], al[0][3], bh[nt][0], bh[nt][1]);
            mma16816(acc[1][nt], al[1][0], al[1][1], al[1][2], al[1][3], bh[nt][0], bh[nt][1]);
        }
#pragma unroll
        for (int nt = 0; nt < NT; nt++) {           // term 3: hi*lo
            const u16* wq = Wl + (nbase + nt * 8 + g) * wstr + k0 + q * 2;
            u32 bl0 = *(const u32*)(wq);
            u32 bl1 = *(const u32*)(wq + 8);
            mma16816(acc[0][nt], ah[0][0], ah[0][1], ah[0][2], ah[0][3], bl0, bl1);
            mma16816(acc[1][nt], ah[1][0], ah[1][1], ah[1][2], ah[1][3], bl0, bl1);
        }
    }
}

// ---------------- main kernel ----------------
// SMEM: L1 stages @0 (2 x 82944). H1 image 0..94208. WB0 @98304, WB1 @135168.
// H2 image @ {0, 36864}. misc @172032.
#define STG1  82944
#define WB0   98304
#define WB1   135168
#define MISCO 172032
#define SMEMB (MISCO + 4096)

__global__ void __launch_bounds__(THREADS, 1) k_main(
    const float* __restrict__ b1, const float* __restrict__ b2,
    const float* __restrict__ b3, const float* __restrict__ W4,
    const float* __restrict__ b4)
{
    extern __shared__ __align__(16) unsigned char sm[];
    const int s = blockIdx.y, t = blockIdx.x, z = blockIdx.z, tid = threadIdx.x;
    const int cnt = g_count[s];
    const int ntl = (cnt + TM - 1) / TM;
    if (t >= ntl) return;
    const int nvalid = min(TM, cnt - t * TM);
    const int gt = g_tbase[s] + t;
    const int lane = tid & 31, w = tid >> 5;
    const int wm = w & 3, wn = w >> 2, g = lane >> 2, q = lane & 3;
    const int mbase = wm * 32;
    const u32 sb = s2u(sm);
    float* b1s = (float*)(sm + MISCO);
    float* b2s = b1s + 160;
    float* b3s = b2s + 128;
    float* w4s = b3s + 96;
    float* part = w4s + 96;

    const unsigned char* Ab = g_Aimg + (size_t)gt * ASE;
    float blockSum = 0.f;

    const int h1off[3]  = {0, 36864, 73728};
    const int h1half[3] = {9216, 9216, 5120};
    const int h1str[3]  = {72, 72, 40};

    for (int ei = 0; ei < 2; ei++) {
        const int se = s * E_ + z * 2 + ei;
        const unsigned char* Wb = g_Wimg + (size_t)se * WSE;
        if (tid < 160) b1s[tid] = b1[se * H1_ + tid];
        if (tid < 128) b2s[tid] = b2[se * H2_ + tid];
        if (tid < 96) { b3s[tid] = b3[se * H3_ + tid]; w4s[tid] = W4[se * H3_ + tid]; }

        auto cpyW = [&](const unsigned char* src, int bytes, u32 dstoff) {
            for (int i = tid * 16; i < bytes; i += THREADS * 16) CPA16(sb + dstoff + i, src + i);
            CPCOMMIT();
        };

        // ================= Layer 1 (K=384, N=160): NT=5 per warp =================
        float acc1[2][5][4];
#pragma unroll
        for (int a = 0; a < 2; a++)
#pragma unroll
            for (int b = 0; b < 5; b++)
#pragma unroll
                for (int c = 0; c < 4; c++) acc1[a][b][c] = 0.f;

        auto cpyL1 = [&](int c, int bf) {
            u32 dst = sb + (bf ? STG1 : 0);
            const unsigned char* gA = Ab + c * ACH;
            for (int i = tid * 16; i < ACH; i += THREADS * 16) CPA16(dst + i, gA + i);
            const unsigned char* gW = Wb + W1OFF + c * 46080;
            for (int i = tid * 16; i < 46080; i += THREADS * 16) CPA16(dst + ACH + i, gW + i);
            CPCOMMIT();
        };
        cpyL1(0, 0); cpyL1(1, 1);
        for (int kc = 0; kc < 6; kc++) {
            if (kc == 5) { CPWAIT(0); } else { CPWAIT(1); }
            __syncthreads();
            const unsigned char* st = sm + ((kc & 1) ? STG1 : 0);
            chunk_mma<5>(acc1, (const u16*)st, (const u16*)st + 9216, 72,
                         (const u16*)(st + ACH), (const u16*)(st + ACH + 23040), 72,
                         4, mbase, wn * 40, g, q);
            __syncthreads();
            if (kc < 4) cpyL1(kc + 2, kc & 1);
        }
        // prefetch W2 chunks 0,1 — overlaps with L1 epilogue below
        // (WB regions only alias L1 stage-1, whose last consumer finished at the
        //  kc=5 trailing barrier; H1 image ends at 94208 < WB0)
        cpyW(Wb + W2OFF, 36864, WB0);
        cpyW(Wb + W2OFF + 36864, 36864, WB1);

        // epilogue -> H1 (bf16 hi/lo)
#pragma unroll
        for (int mt = 0; mt < 2; mt++)
#pragma unroll
            for (int nt = 0; nt < 5; nt++) {
                int n0 = wn * 40 + nt * 8 + q * 2;
                int cb = n0 >> 6, off = n0 & 63;
                u16* Hh = (u16*)(sm + h1off[cb]);
                u16* Hl = Hh + h1half[cb];
                int str = h1str[cb];
                int row = mbase + mt * 16 + g;
                u32 h, l;
                splitpair(celu_f(acc1[mt][nt][0] + b1s[n0]),
                          celu_f(acc1[mt][nt][1] + b1s[n0 + 1]), h, l);
                *(u32*)(Hh + row * str + off) = h;
                *(u32*)(Hl + row * str + off) = l;
                splitpair(celu_f(acc1[mt][nt][2] + b1s[n0]),
                          celu_f(acc1[mt][nt][3] + b1s[n0 + 1]), h, l);
                *(u32*)(Hh + (row + 8) * str + off) = h;
                *(u32*)(Hl + (row + 8) * str + off) = l;
            }
        __syncthreads();

        // ================= Layer 2 (K=160, N=128): NT=4 =================
        float acc2[2][4][4];
#pragma unroll
        for (int a = 0; a < 2; a++)
#pragma unroll
            for (int b = 0; b < 4; b++)
#pragma unroll
                for (int c = 0; c < 4; c++) acc2[a][b][c] = 0.f;

        for (int kc = 0; kc < 3; kc++) {
            if (kc == 2) { CPWAIT(0); } else { CPWAIT(1); }
            __syncthreads();
            const unsigned char* wb = sm + ((kc & 1) ? WB1 : WB0);
            int str = (kc == 2) ? 40 : 72;
            int hl = (kc == 2) ? 5120 : 9216;
            int ks = (kc == 2) ? 2 : 4;
            chunk_mma<4>(acc2,
                         (const u16*)(sm + h1off[kc]), (const u16*)(sm + h1off[kc]) + h1half[kc], h1str[kc],
                         (const u16*)wb, (const u16*)wb + hl, str,
                         ks, mbase, wn * 32, g, q);
            __syncthreads();
            if (kc == 0) cpyW(Wb + W2OFF + 73728, 20480, WB0);
        }
        // prefetch W3 chunks 0,1 — overlaps with L2 epilogue (WB0's last
        // consumer was the kc=2 compute, barrier passed; H2 image < WB0)
        cpyW(Wb + W3OFF, 27648, WB0);
        cpyW(Wb + W3OFF + 27648, 27648, WB1);

        // epilogue -> H2
#pragma unroll
        for (int mt = 0; mt < 2; mt++)
#pragma unroll
            for (int nt = 0; nt < 4; nt++) {
                int n0 = wn * 32 + nt * 8 + q * 2;
                int cb = n0 >> 6, off = n0 & 63;
                u16* Hh = (u16*)(sm + cb * 36864);
                u16* Hl = Hh + 9216;
                int row = mbase + mt * 16 + g;
                u32 h, l;
                splitpair(celu_f(acc2[mt][nt][0] + b2s[n0]),
                          celu_f(acc2[mt][nt][1] + b2s[n0 + 1]), h, l);
                *(u32*)(Hh + row * 72 + off) = h;
                *(u32*)(Hl + row * 72 + off) = l;
                splitpair(celu_f(acc2[mt][nt][2] + b2s[n0]),
                          celu_f(acc2[mt][nt][3] + b2s[n0 + 1]), h, l);
                *(u32*)(Hh + (row + 8) * 72 + off) = h;
                *(u32*)(Hl + (row + 8) * 72 + off) = l;
            }
        __syncthreads();

        // ================= Layer 3 (K=128, N=96): NT=3 =================
        float acc3[2][3][4];
#pragma unroll
        for (int a = 0; a < 2; a++)
#pragma unroll
            for (int b = 0; b < 3; b++)
#pragma unroll
                for (int c = 0; c < 4; c++) acc3[a][b][c] = 0.f;

        for (int kc = 0; kc < 2; kc++) {
            if (kc == 1) { CPWAIT(0); } else { CPWAIT(1); }
            __syncthreads();
            const unsigned char* wb = sm + ((kc & 1) ? WB1 : WB0);
            chunk_mma<3>(acc3,
                         (const u16*)(sm + kc * 36864), (const u16*)(sm + kc * 36864) + 9216, 72,
                         (const u16*)wb, (const u16*)wb + 6912, 72,
                         4, mbase, wn * 24, g, q);
            __syncthreads();
        }
        // ================= fused L3-epilogue + Layer 4 =================
        {
            float p00 = 0.f, p01 = 0.f, p10 = 0.f, p11 = 0.f;
#pragma unroll
            for (int nt = 0; nt < 3; nt++) {
                int n0 = wn * 24 + nt * 8 + q * 2;
                float w0 = w4s[n0], w1 = w4s[n0 + 1];
                float bb0 = b3s[n0], bb1 = b3s[n0 + 1];
                p00 += celu_f(acc3[0][nt][0] + bb0) * w0 + celu_f(acc3[0][nt][1] + bb1) * w1;
                p01 += celu_f(acc3[0][nt][2] + bb0) * w0 + celu_f(acc3[0][nt][3] + bb1) * w1;
                p10 += celu_f(acc3[1][nt][0] + bb0) * w0 + celu_f(acc3[1][nt][1] + bb1) * w1;
                p11 += celu_f(acc3[1][nt][2] + bb0) * w0 + celu_f(acc3[1][nt][3] + bb1) * w1;
            }
            p00 += __shfl_xor_sync(0xffffffffu, p00, 1); p00 += __shfl_xor_sync(0xffffffffu, p00, 2);
            p01 += __shfl_xor_sync(0xffffffffu, p01, 1); p01 += __shfl_xor_sync(0xffffffffu, p01, 2);
            p10 += __shfl_xor_sync(0xffffffffu, p10, 1); p10 += __shfl_xor_sync(0xffffffffu, p10, 2);
            p11 += __shfl_xor_sync(0xffffffffu, p11, 1); p11 += __shfl_xor_sync(0xffffffffu, p11, 2);
            if (q == 0) {
                part[wn * 128 + mbase + g]          = p00;
                part[wn * 128 + mbase + g + 8]      = p01;
                part[wn * 128 + mbase + 16 + g]     = p10;
                part[wn * 128 + mbase + 16 + g + 8] = p11;
            }
        }
        __syncthreads();
        if (tid < 128) {
            float en = part[tid] + part[128 + tid] + part[256 + tid] + part[384 + tid] + b4[se];
            part[tid] = (tid < nvalid) ? en : 0.f;
        }
        __syncthreads();
        if (tid < 32) {
            float v = part[tid] + part[tid + 32] + part[tid + 64] + part[tid + 96];
            for (int o = 16; o; o >>= 1) v += __shfl_down_sync(0xffffffffu, v, o);
            if (tid == 0) blockSum += v;
        }
        __syncthreads();
    }
    if (tid == 0) g_partial[(s * NTT + t) * 4 + z] = blockSum;
}

// ---------------- final reduction ----------------
__global__ void k_reduce(float* out) {
    __shared__ double sb[256];
    int tid = threadIdx.x;
    double s = 0.0;
    for (int i = tid; i < NPART; i += 256) s += (double)g_partial[i];
    sb[tid] = s;
    __syncthreads();
    for (int st = 128; st; st >>= 1) {
        if (tid < st) sb[tid] += sb[tid + st];
        __syncthreads();
    }
    if (tid == 0) out[0] = (float)(sb[0] * (1.0 / E_));
}

// ---------------- launch ----------------
extern "C" void kernel_launch(void* const* d_in, const int* in_sizes, int n_in,
                              void* d_out, int out_size)
{
    const void*  sp  = d_in[0];
    const float* aev = (const float*)d_in[1];
    const float* W1  = (const float*)d_in[2];
    const float* b1  = (const float*)d_in[3];
    const float* W2  = (const float*)d_in[4];
    const float* b2  = (const float*)d_in[5];
    const float* W3  = (const float*)d_in[6];
    const float* b3  = (const float*)d_in[7];
    const float* W4  = (const float*)d_in[8];
    const float* b4  = (const float*)d_in[9];

    cudaFuncSetAttribute(k_main, cudaFuncAttributeMaxDynamicSharedMemorySize, SMEMB);

    k_init<<<1, 256>>>((const ull*)sp);
    k_count<<<NB, 256>>>((const int*)sp);
    k_scan<<<1, 256>>>();
    k_scatter<<<NB, 256>>>((const int*)sp);
    dim3 gw(32, 8);
    k_wprep<<<gw, 256>>>(W1, W2, W3);
    dim3 ga(NTT, S_);
    k_aprep<<<ga, 256>>>(aev);
    dim3 gm(NTT, S_, 4);
    k_main<<<gm, THREADS, SMEMB>>>(b1, b2, b3, W4, b4);
    k_reduce<<<1, 256>>>((float*)d_out);
}

// round 10
// speedup vs baseline: 3.4912x; 1.1596x over previous
#include <cuda_runtime.h>
#include <cuda_bf16.h>
#include <cuda_fp16.h>
#include <cstdint>
#include <math.h>

#define S_  4
#define E_  8
#define D_  384
#define H1_ 160
#define H2_ 128
#define H3_ 96
#define N_  40000
#define TM  128
#define NTT 313
#define NB  ((N_ + 255) / 256)
#define NPART (NTT * S_ * 4)
#define MAXT 320
#define THREADS 512

typedef unsigned long long ull;
typedef uint32_t u32;
typedef unsigned short u16;

// ---------------- gmem image geometry ----------------
// A tiles: 6 chunks x (Ah [128][72] f16 18432 B | Al 18432 B)
#define ACH   36864
#define ASE   (6 * ACH)
// Weights per (s,e):
//  W1 @0:      6 chunks x 23040, single fp16 [160][72]   (region 0..138240; gap to 276480)
//  W2 @276480: bf16 hi/lo; c0/c1 [128][72] (hi|lo 18432), c2 [128][40] (hi|lo 10240)
//  W3 @370688: bf16 hi/lo; 2 chunks x 27648 (hi|lo 13824), [96][72]
#define W1OFF 0
#define W2OFF 276480
#define W3OFF 370688
#define WSE   425984

__device__ int   g_is64;
__device__ int   g_blockCnt[NB * S_];
__device__ int   g_blockOff[NB * S_];
__device__ int   g_count[S_];
__device__ int   g_tbase[S_];
__device__ int   g_idx[S_ * N_];
__device__ float g_partial[NPART];
__device__ __align__(1024) unsigned char g_Wimg[(size_t)32 * WSE];
__device__ __align__(1024) unsigned char g_Aimg[(size_t)MAXT * ASE];

// ---------------- helpers ----------------
static __device__ __forceinline__ float celu_f(float x) {
    return x > 0.f ? x : 0.1f * (__expf(x * 10.f) - 1.f);
}
static __device__ __forceinline__ u32 s2u(const void* p) {
    u32 a;
    asm("{ .reg .u64 t; cvta.to.shared.u64 t, %1; cvt.u32.u64 %0, t; }" : "=r"(a) : "l"(p));
    return a;
}
static __device__ __forceinline__ void split2(float v, u16& h, u16& l) {
    __nv_bfloat16 hb = __float2bfloat16(v);
    float hf = __bfloat162float(hb);
    __nv_bfloat16 lb = __float2bfloat16(v - hf);
    h = __bfloat16_as_ushort(hb);
    l = __bfloat16_as_ushort(lb);
}
// fp32 pair -> packed bf16x2 hi + residual bf16x2 lo (x low half, y high half)
static __device__ __forceinline__ void splitpair(float x, float y, u32& h, u32& l) {
    u32 hh;
    asm("cvt.rn.bf16x2.f32 %0, %1, %2;" : "=r"(hh) : "f"(y), "f"(x));
    float xh = __uint_as_float(hh << 16);
    float yh = __uint_as_float(hh & 0xffff0000u);
    asm("cvt.rn.bf16x2.f32 %0, %1, %2;" : "=r"(l) : "f"(y - yh), "f"(x - xh));
    h = hh;
}
// fp32 pair -> packed f16x2 hi + f16x2 residual
static __device__ __forceinline__ void splitpairh(float x, float y, u32& h, u32& l) {
    u32 hh;
    asm("cvt.rn.f16x2.f32 %0, %1, %2;" : "=r"(hh) : "f"(y), "f"(x));
    float xh, yh;
    asm("{ .reg .f16 lo, hi; mov.b32 {lo, hi}, %2; cvt.f32.f16 %0, lo; cvt.f32.f16 %1, hi; }"
        : "=f"(xh), "=f"(yh) : "r"(hh));
    asm("cvt.rn.f16x2.f32 %0, %1, %2;" : "=r"(l) : "f"(y - yh), "f"(x - xh));
    h = hh;
}
static __device__ __forceinline__ void mma_bf(float* c,
        u32 a0, u32 a1, u32 a2, u32 a3, u32 b0, u32 b1) {
    asm volatile(
        "mma.sync.aligned.m16n8k16.row.col.f32.bf16.bf16.f32 "
        "{%0,%1,%2,%3},{%4,%5,%6,%7},{%8,%9},{%0,%1,%2,%3};"
        : "+f"(c[0]), "+f"(c[1]), "+f"(c[2]), "+f"(c[3])
        : "r"(a0), "r"(a1), "r"(a2), "r"(a3), "r"(b0), "r"(b1));
}
static __device__ __forceinline__ void mma_fp(float* c,
        u32 a0, u32 a1, u32 a2, u32 a3, u32 b0, u32 b1) {
    asm volatile(
        "mma.sync.aligned.m16n8k16.row.col.f32.f16.f16.f32 "
        "{%0,%1,%2,%3},{%4,%5,%6,%7},{%8,%9},{%0,%1,%2,%3};"
        : "+f"(c[0]), "+f"(c[1]), "+f"(c[2]), "+f"(c[3])
        : "r"(a0), "r"(a1), "r"(a2), "r"(a3), "r"(b0), "r"(b1));
}
#define CPA16(d, s) asm volatile("cp.async.cg.shared.global [%0], [%1], 16;" :: "r"(d), "l"(s) : "memory")
#define CPCOMMIT()  asm volatile("cp.async.commit_group;" ::: "memory")
#define CPWAIT(n)   asm volatile("cp.async.wait_group %0;" :: "n"(n) : "memory")

// ---------------- bucketing ----------------
__global__ void k_init(const ull* spq) {
    int tid = threadIdx.x;
    for (int i = tid; i < NPART; i += 256) g_partial[i] = 0.f;
    if (tid < 32) {
        ull v = spq[tid];
        int hiNZ = ((v >> 32) != 0ull) ? 1 : 0;
        int any = __any_sync(0xffffffffu, hiNZ);
        if (tid == 0) g_is64 = any ? 0 : 1;
    }
}
__global__ void k_count(const int* sp) {
    int tid = threadIdx.x, b = blockIdx.x;
    int n = b * 256 + tid;
    int shift = g_is64;
    int spv = -1;
    if (n < N_) spv = sp[(size_t)n << shift];
    __shared__ int wc[8][4];
    if (tid < 32) wc[tid >> 2][tid & 3] = 0;
    __syncthreads();
    unsigned mm = __match_any_sync(0xffffffffu, spv);
    int lane = tid & 31, w = tid >> 5;
    if (spv >= 0 && lane == (__ffs(mm) - 1)) wc[w][spv] = __popc(mm);
    __syncthreads();
    if (tid < 4) {
        int s = 0;
        for (int ww = 0; ww < 8; ww++) s += wc[ww][tid];
        g_blockCnt[b * 4 + tid] = s;
    }
}
__global__ void k_scan() {
    __shared__ int c[NB * 4];
    __shared__ int o[NB * 4];
    int tid = threadIdx.x;
    for (int i = tid; i < NB * 4; i += 256) c[i] = g_blockCnt[i];
    __syncthreads();
    if (tid == 0) {
        int r0 = 0, r1 = 0, r2 = 0, r3 = 0;
        for (int b = 0; b < NB; b++) {
            o[b * 4 + 0] = r0; r0 += c[b * 4 + 0];
            o[b * 4 + 1] = r1; r1 += c[b * 4 + 1];
            o[b * 4 + 2] = r2; r2 += c[b * 4 + 2];
            o[b * 4 + 3] = r3; r3 += c[b * 4 + 3];
        }
        g_count[0] = r0; g_count[1] = r1; g_count[2] = r2; g_count[3] = r3;
        int tb = 0;
        g_tbase[0] = 0;  tb += (r0 + TM - 1) / TM;
        g_tbase[1] = tb; tb += (r1 + TM - 1) / TM;
        g_tbase[2] = tb; tb += (r2 + TM - 1) / TM;
        g_tbase[3] = tb;
    }
    __syncthreads();
    for (int i = tid; i < NB * 4; i += 256) g_blockOff[i] = o[i];
}
__global__ void k_scatter(const int* sp) {
    int tid = threadIdx.x, b = blockIdx.x;
    int n = b * 256 + tid;
    int shift = g_is64;
    int spv = -1;
    if (n < N_) spv = sp[(size_t)n << shift];
    __shared__ int wc[8][4];
    __shared__ int woff[8][4];
    if (tid < 32) wc[tid >> 2][tid & 3] = 0;
    __syncthreads();
    unsigned mm = __match_any_sync(0xffffffffu, spv);
    int lane = tid & 31, w = tid >> 5;
    int rank = __popc(mm & ((1u << lane) - 1u));
    if (spv >= 0 && lane == (__ffs(mm) - 1)) wc[w][spv] = __popc(mm);
    __syncthreads();
    if (tid < 4) {
        int run = g_blockOff[b * 4 + tid];
        for (int ww = 0; ww < 8; ww++) { woff[ww][tid] = run; run += wc[ww][tid]; }
    }
    __syncthreads();
    if (spv >= 0) g_idx[spv * N_ + woff[w][spv] + rank] = n;
}

// ---------------- weight image prep ----------------
__global__ void k_wprep(const float* __restrict__ W1, const float* __restrict__ W2,
                        const float* __restrict__ W3) {
    int se = blockIdx.x;
    int tid0 = threadIdx.x + blockIdx.y * 256;
    const int step = 256 * 8;
    unsigned char* base = g_Wimg + (size_t)se * WSE;
    for (int i = tid0; i < D_ * H1_; i += step) {           // W1: single fp16
        int n = i % H1_, k = i / H1_;
        u16 h = __half_as_ushort(__float2half_rn(W1[((size_t)se * D_ + k) * H1_ + n]));
        int c = k >> 6, kl = k & 63;
        ((u16*)(base + W1OFF + c * 23040))[n * 72 + kl] = h;
    }
    for (int i = tid0; i < H1_ * H2_; i += step) {          // W2: bf16 hi/lo
        int n = i % H2_, k = i / H2_;
        u16 h, l; split2(W2[((size_t)se * H1_ + k) * H2_ + n], h, l);
        int c = k >> 6, kl = k & 63;
        int str = (c == 2) ? 40 : 72, hlw = (c == 2) ? 5120 : 9216;
        int coff = (c == 0) ? 0 : (c == 1 ? 36864 : 73728);
        u16* p = (u16*)(base + W2OFF + coff);
        p[n * str + kl] = h;
        p[hlw + n * str + kl] = l;
    }
    for (int i = tid0; i < H2_ * H3_; i += step) {          // W3: bf16 hi/lo
        int n = i % H3_, k = i / H3_;
        u16 h, l; split2(W3[((size_t)se * H2_ + k) * H3_ + n], h, l);
        int c = k >> 6, kl = k & 63;
        u16* p = (u16*)(base + W3OFF + c * 27648);
        p[n * 72 + kl] = h;
        p[6912 + n * 72 + kl] = l;
    }
}

// ---------------- A image prep: gather + fp16 hi/lo split ----------------
__global__ void k_aprep(const float* __restrict__ aev) {
    int t = blockIdx.x, s = blockIdx.y, tid = threadIdx.x;
    int cnt = g_count[s];
    int ntl = (cnt + TM - 1) / TM;
    if (t >= ntl) return;
    int gt = g_tbase[s] + t;
    __shared__ int sidx[TM];
    if (tid < TM) {
        int p = t * TM + tid; if (p >= cnt) p = cnt - 1;
        sidx[tid] = g_idx[s * N_ + p];
    }
    __syncthreads();
    unsigned char* base = g_Aimg + (size_t)gt * ASE;
    for (int i = tid; i < TM * (D_ / 2); i += 256) {
        int m = i / (D_ / 2), k = (i % (D_ / 2)) * 2;
        float2 v = *(const float2*)(aev + (size_t)sidx[m] * D_ + k);
        u32 h, l; splitpairh(v.x, v.y, h, l);
        int c = k >> 6, kl = k & 63;
        u16* ch = (u16*)(base + c * ACH);
        *(u32*)(ch + m * 72 + kl) = h;
        *(u32*)(ch + 9216 + m * 72 + kl) = l;
    }
}

// ---------------- bf16 3-term fragment GEMM, term-major ----------------
template<int NT>
static __device__ __forceinline__ void chunk_mma3(
    float (*acc)[NT][4],
    const u16* Ah, const u16* Al, int astr,
    const u16* Wh, const u16* Wl, int wstr,
    int ksteps, int mbase, int nbase, int g, int q)
{
    for (int ks = 0; ks < ksteps; ks++) {
        const int k0 = ks * 16;
        u32 ah[2][4], al[2][4];
#pragma unroll
        for (int mt = 0; mt < 2; mt++) {
            const u16* ap = Ah + (mbase + mt * 16 + g) * astr + k0 + q * 2;
            const u16* aq = Al + (mbase + mt * 16 + g) * astr + k0 + q * 2;
            ah[mt][0] = *(const u32*)(ap);
            ah[mt][1] = *(const u32*)(ap + 8 * astr);
            ah[mt][2] = *(const u32*)(ap + 8);
            ah[mt][3] = *(const u32*)(ap + 8 * astr + 8);
            al[mt][0] = *(const u32*)(aq);
            al[mt][1] = *(const u32*)(aq + 8 * astr);
            al[mt][2] = *(const u32*)(aq + 8);
            al[mt][3] = *(const u32*)(aq + 8 * astr + 8);
        }
        u32 bh[NT][2];
#pragma unroll
        for (int nt = 0; nt < NT; nt++) {           // term 1: hi*hi
            const u16* wp = Wh + (nbase + nt * 8 + g) * wstr + k0 + q * 2;
            bh[nt][0] = *(const u32*)(wp);
            bh[nt][1] = *(const u32*)(wp + 8);
            mma_bf(acc[0][nt], ah[0][0], ah[0][1], ah[0][2], ah[0][3], bh[nt][0], bh[nt][1]);
            mma_bf(acc[1][nt], ah[1][0], ah[1][1], ah[1][2], ah[1][3], bh[nt][0], bh[nt][1]);
        }
#pragma unroll
        for (int nt = 0; nt < NT; nt++) {           // term 2: lo*hi
            mma_bf(acc[0][nt], al[0][0], al[0][1], al[0][2], al[0][3], bh[nt][0], bh[nt][1]);
            mma_bf(acc[1][nt], al[1][0], al[1][1], al[1][2], al[1][3], bh[nt][0], bh[nt][1]);
        }
#pragma unroll
        for (int nt = 0; nt < NT; nt++) {           // term 3: hi*lo
            const u16* wq = Wl + (nbase + nt * 8 + g) * wstr + k0 + q * 2;
            u32 bl0 = *(const u32*)(wq);
            u32 bl1 = *(const u32*)(wq + 8);
            mma_bf(acc[0][nt], ah[0][0], ah[0][1], ah[0][2], ah[0][3], bl0, bl1);
            mma_bf(acc[1][nt], ah[1][0], ah[1][1], ah[1][2], ah[1][3], bl0, bl1);
        }
    }
}

// ---------------- fp16 2-term fragment GEMM (L1), term-major ----------------
template<int NT>
static __device__ __forceinline__ void chunk_mma2(
    float (*acc)[NT][4],
    const u16* Ah, const u16* Al, int astr,
    const u16* Wh, int wstr,
    int ksteps, int mbase, int nbase, int g, int q)
{
    for (int ks = 0; ks < ksteps; ks++) {
        const int k0 = ks * 16;
        u32 ah[2][4], al[2][4];
#pragma unroll
        for (int mt = 0; mt < 2; mt++) {
            const u16* ap = Ah + (mbase + mt * 16 + g) * astr + k0 + q * 2;
            const u16* aq = Al + (mbase + mt * 16 + g) * astr + k0 + q * 2;
            ah[mt][0] = *(const u32*)(ap);
            ah[mt][1] = *(const u32*)(ap + 8 * astr);
            ah[mt][2] = *(const u32*)(ap + 8);
            ah[mt][3] = *(const u32*)(ap + 8 * astr + 8);
            al[mt][0] = *(const u32*)(aq);
            al[mt][1] = *(const u32*)(aq + 8 * astr);
            al[mt][2] = *(const u32*)(aq + 8);
            al[mt][3] = *(const u32*)(aq + 8 * astr + 8);
        }
        u32 bh[NT][2];
#pragma unroll
        for (int nt = 0; nt < NT; nt++) {           // term 1: ah * w
            const u16* wp = Wh + (nbase + nt * 8 + g) * wstr + k0 + q * 2;
            bh[nt][0] = *(const u32*)(wp);
            bh[nt][1] = *(const u32*)(wp + 8);
            mma_fp(acc[0][nt], ah[0][0], ah[0][1], ah[0][2], ah[0][3], bh[nt][0], bh[nt][1]);
            mma_fp(acc[1][nt], ah[1][0], ah[1][1], ah[1][2], ah[1][3], bh[nt][0], bh[nt][1]);
        }
#pragma unroll
        for (int nt = 0; nt < NT; nt++) {           // term 2: al * w (w cached)
            mma_fp(acc[0][nt], al[0][0], al[0][1], al[0][2], al[0][3], bh[nt][0], bh[nt][1]);
            mma_fp(acc[1][nt], al[1][0], al[1][1], al[1][2], al[1][3], bh[nt][0], bh[nt][1]);
        }
    }
}

// ---------------- main kernel ----------------
// SMEM: L1 stages @0, @59904 (A 36864 | W1 23040 each; dead before H1 writes).
// H1 image 0..94208 (bf16 hi/lo). WB0 @98304, WB1 @135168 (bf16 W2/W3 stages).
// H2 image @ {0, 36864}. misc @172032.
#define SSTG  59904
#define WB0   98304
#define WB1   135168
#define MISCO 172032
#define SMEMB (MISCO + 4096)

__global__ void __launch_bounds__(THREADS, 1) k_main(
    const float* __restrict__ b1, const float* __restrict__ b2,
    const float* __restrict__ b3, const float* __restrict__ W4,
    const float* __restrict__ b4)
{
    extern __shared__ __align__(16) unsigned char sm[];
    const int s = blockIdx.y, t = blockIdx.x, z = blockIdx.z, tid = threadIdx.x;
    const int cnt = g_count[s];
    const int ntl = (cnt + TM - 1) / TM;
    if (t >= ntl) return;
    const int nvalid = min(TM, cnt - t * TM);
    const int gt = g_tbase[s] + t;
    const int lane = tid & 31, w = tid >> 5;
    const int wm = w & 3, wn = w >> 2, g = lane >> 2, q = lane & 3;
    const int mbase = wm * 32;
    const u32 sb = s2u(sm);
    float* b1s = (float*)(sm + MISCO);
    float* b2s = b1s + 160;
    float* b3s = b2s + 128;
    float* w4s = b3s + 96;
    float* part = w4s + 96;

    const unsigned char* Ab = g_Aimg + (size_t)gt * ASE;
    float blockSum = 0.f;

    const int h1off[3]  = {0, 36864, 73728};
    const int h1half[3] = {9216, 9216, 5120};
    const int h1str[3]  = {72, 72, 40};

    for (int ei = 0; ei < 2; ei++) {
        const int se = s * E_ + z * 2 + ei;
        const unsigned char* Wb = g_Wimg + (size_t)se * WSE;
        if (tid < 160) b1s[tid] = b1[se * H1_ + tid];
        if (tid < 128) b2s[tid] = b2[se * H2_ + tid];
        if (tid < 96) { b3s[tid] = b3[se * H3_ + tid]; w4s[tid] = W4[se * H3_ + tid]; }

        auto cpyW = [&](const unsigned char* src, int bytes, u32 dstoff) {
            for (int i = tid * 16; i < bytes; i += THREADS * 16) CPA16(sb + dstoff + i, src + i);
            CPCOMMIT();
        };

        // ========= Layer 1 (K=384, N=160): fp16 2-term, NT=5 per warp =========
        float acc1[2][5][4];
#pragma unroll
        for (int a = 0; a < 2; a++)
#pragma unroll
            for (int b = 0; b < 5; b++)
#pragma unroll
                for (int c = 0; c < 4; c++) acc1[a][b][c] = 0.f;

        auto cpyL1 = [&](int c, int bf) {
            u32 dst = sb + (bf ? SSTG : 0);
            const unsigned char* gA = Ab + c * ACH;
            for (int i = tid * 16; i < ACH; i += THREADS * 16) CPA16(dst + i, gA + i);
            const unsigned char* gW = Wb + W1OFF + c * 23040;
            for (int i = tid * 16; i < 23040; i += THREADS * 16) CPA16(dst + ACH + i, gW + i);
            CPCOMMIT();
        };
        cpyL1(0, 0); cpyL1(1, 1);
        for (int kc = 0; kc < 6; kc++) {
            if (kc == 5) { CPWAIT(0); } else { CPWAIT(1); }
            __syncthreads();
            const unsigned char* st = sm + ((kc & 1) ? SSTG : 0);
            chunk_mma2<5>(acc1, (const u16*)st, (const u16*)st + 9216, 72,
                          (const u16*)(st + ACH), 72,
                          4, mbase, wn * 40, g, q);
            __syncthreads();
            if (kc < 4) cpyL1(kc + 2, kc & 1);
        }
        // prefetch W2 chunks 0,1 — overlaps with L1 epilogue (stages dead)
        cpyW(Wb + W2OFF, 36864, WB0);
        cpyW(Wb + W2OFF + 36864, 36864, WB1);

        // epilogue -> H1 (bf16 hi/lo)
#pragma unroll
        for (int mt = 0; mt < 2; mt++)
#pragma unroll
            for (int nt = 0; nt < 5; nt++) {
                int n0 = wn * 40 + nt * 8 + q * 2;
                int cb = n0 >> 6, off = n0 & 63;
                u16* Hh = (u16*)(sm + h1off[cb]);
                u16* Hl = Hh + h1half[cb];
                int str = h1str[cb];
                int row = mbase + mt * 16 + g;
                u32 h, l;
                splitpair(celu_f(acc1[mt][nt][0] + b1s[n0]),
                          celu_f(acc1[mt][nt][1] + b1s[n0 + 1]), h, l);
                *(u32*)(Hh + row * str + off) = h;
                *(u32*)(Hl + row * str + off) = l;
                splitpair(celu_f(acc1[mt][nt][2] + b1s[n0]),
                          celu_f(acc1[mt][nt][3] + b1s[n0 + 1]), h, l);
                *(u32*)(Hh + (row + 8) * str + off) = h;
                *(u32*)(Hl + (row + 8) * str + off) = l;
            }
        __syncthreads();

        // ========= Layer 2 (K=160, N=128): bf16 3-term, NT=4 =========
        float acc2[2][4][4];
#pragma unroll
        for (int a = 0; a < 2; a++)
#pragma unroll
            for (int b = 0; b < 4; b++)
#pragma unroll
                for (int c = 0; c < 4; c++) acc2[a][b][c] = 0.f;

        for (int kc = 0; kc < 3; kc++) {
            if (kc == 2) { CPWAIT(0); } else { CPWAIT(1); }
            __syncthreads();
            const unsigned char* wb = sm + ((kc & 1) ? WB1 : WB0);
            int str = (kc == 2) ? 40 : 72;
            int hl = (kc == 2) ? 5120 : 9216;
            int ks = (kc == 2) ? 2 : 4;
            chunk_mma3<4>(acc2,
                          (const u16*)(sm + h1off[kc]), (const u16*)(sm + h1off[kc]) + h1half[kc], h1str[kc],
                          (const u16*)wb, (const u16*)wb + hl, str,
                          ks, mbase, wn * 32, g, q);
            __syncthreads();
            if (kc == 0) cpyW(Wb + W2OFF + 73728, 20480, WB0);
        }
        // prefetch W3 chunks 0,1 — overlaps with L2 epilogue
        cpyW(Wb + W3OFF, 27648, WB0);
        cpyW(Wb + W3OFF + 27648, 27648, WB1);

        // epilogue -> H2 (bf16 hi/lo @ {0, 36864})
#pragma unroll
        for (int mt = 0; mt < 2; mt++)
#pragma unroll
            for (int nt = 0; nt < 4; nt++) {
                int n0 = wn * 32 + nt * 8 + q * 2;
                int cb = n0 >> 6, off = n0 & 63;
                u16* Hh = (u16*)(sm + cb * 36864);
                u16* Hl = Hh + 9216;
                int row = mbase + mt * 16 + g;
                u32 h, l;
                splitpair(celu_f(acc2[mt][nt][0] + b2s[n0]),
                          celu_f(acc2[mt][nt][1] + b2s[n0 + 1]), h, l);
                *(u32*)(Hh + row * 72 + off) = h;
                *(u32*)(Hl + row * 72 + off) = l;
                splitpair(celu_f(acc2[mt][nt][2] + b2s[n0]),
                          celu_f(acc2[mt][nt][3] + b2s[n0 + 1]), h, l);
                *(u32*)(Hh + (row + 8) * 72 + off) = h;
                *(u32*)(Hl + (row + 8) * 72 + off) = l;
            }
        __syncthreads();

        // ========= Layer 3 (K=128, N=96): bf16 3-term, NT=3 =========
        float acc3[2][3][4];
#pragma unroll
        for (int a = 0; a < 2; a++)
#pragma unroll
            for (int b = 0; b < 3; b++)
#pragma unroll
                for (int c = 0; c < 4; c++) acc3[a][b][c] = 0.f;

        for (int kc = 0; kc < 2; kc++) {
            if (kc == 1) { CPWAIT(0); } else { CPWAIT(1); }
            __syncthreads();
            const unsigned char* wb = sm + ((kc & 1) ? WB1 : WB0);
            chunk_mma3<3>(acc3,
                          (const u16*)(sm + kc * 36864), (const u16*)(sm + kc * 36864) + 9216, 72,
                          (const u16*)wb, (const u16*)wb + 6912, 72,
                          4, mbase, wn * 24, g, q);
            __syncthreads();
        }
        // ========= fused L3-epilogue + Layer 4 =========
        {
            float p00 = 0.f, p01 = 0.f, p10 = 0.f, p11 = 0.f;
#pragma unroll
            for (int nt = 0; nt < 3; nt++) {
                int n0 = wn * 24 + nt * 8 + q * 2;
                float w0 = w4s[n0], w1 = w4s[n0 + 1];
                float bb0 = b3s[n0], bb1 = b3s[n0 + 1];
                p00 += celu_f(acc3[0][nt][0] + bb0) * w0 + celu_f(acc3[0][nt][1] + bb1) * w1;
                p01 += celu_f(acc3[0][nt][2] + bb0) * w0 + celu_f(acc3[0][nt][3] + bb1) * w1;
                p10 += celu_f(acc3[1][nt][0] + bb0) * w0 + celu_f(acc3[1][nt][1] + bb1) * w1;
                p11 += celu_f(acc3[1][nt][2] + bb0) * w0 + celu_f(acc3[1][nt][3] + bb1) * w1;
            }
            p00 += __shfl_xor_sync(0xffffffffu, p00, 1); p00 += __shfl_xor_sync(0xffffffffu, p00, 2);
            p01 += __shfl_xor_sync(0xffffffffu, p01, 1); p01 += __shfl_xor_sync(0xffffffffu, p01, 2);
            p10 += __shfl_xor_sync(0xffffffffu, p10, 1); p10 += __shfl_xor_sync(0xffffffffu, p10, 2);
            p11 += __shfl_xor_sync(0xffffffffu, p11, 1); p11 += __shfl_xor_sync(0xffffffffu, p11, 2);
            if (q == 0) {
                part[wn * 128 + mbase + g]          = p00;
                part[wn * 128 + mbase + g + 8]      = p01;
                part[wn * 128 + mbase + 16 + g]     = p10;
                part[wn * 128 + mbase + 16 + g + 8] = p11;
            }
        }
        __syncthreads();
        if (tid < 128) {
            float en = part[tid] + part[128 + tid] + part[256 + tid] + part[384 + tid] + b4[se];
            part[tid] = (tid < nvalid) ? en : 0.f;
        }
        __syncthreads();
        if (tid < 32) {
            float v = part[tid] + part[tid + 32] + part[tid + 64] + part[tid + 96];
            for (int o = 16; o; o >>= 1) v += __shfl_down_sync(0xffffffffu, v, o);
            if (tid == 0) blockSum += v;
        }
        __syncthreads();
    }
    if (tid == 0) g_partial[(s * NTT + t) * 4 + z] = blockSum;
}

// ---------------- final reduction ----------------
__global__ void k_reduce(float* out) {
    __shared__ double sb[256];
    int tid = threadIdx.x;
    double s = 0.0;
    for (int i = tid; i < NPART; i += 256) s += (double)g_partial[i];
    sb[tid] = s;
    __syncthreads();
    for (int st = 128; st; st >>= 1) {
        if (tid < st) sb[tid] += sb[tid + st];
        __syncthreads();
    }
    if (tid == 0) out[0] = (float)(sb[0] * (1.0 / E_));
}

// ---------------- launch ----------------
extern "C" void kernel_launch(void* const* d_in, const int* in_sizes, int n_in,
                              void* d_out, int out_size)
{
    const void*  sp  = d_in[0];
    const float* aev = (const float*)d_in[1];
    const float* W1  = (const float*)d_in[2];
    const float* b1  = (const float*)d_in[3];
    const float* W2  = (const float*)d_in[4];
    const float* b2  = (const float*)d_in[5];
    const float* W3  = (const float*)d_in[6];
    const float* b3  = (const float*)d_in[7];
    const float* W4  = (const float*)d_in[8];
    const float* b4  = (const float*)d_in[9];

    cudaFuncSetAttribute(k_main, cudaFuncAttributeMaxDynamicSharedMemorySize, SMEMB);

    k_init<<<1, 256>>>((const ull*)sp);
    k_count<<<NB, 256>>>((const int*)sp);
    k_scan<<<1, 256>>>();
    k_scatter<<<NB, 256>>>((const int*)sp);
    dim3 gw(32, 8);
    k_wprep<<<gw, 256>>>(W1, W2, W3);
    dim3 ga(NTT, S_);
    k_aprep<<<ga, 256>>>(aev);
    dim3 gm(NTT, S_, 4);
    k_main<<<gm, THREADS, SMEMB>>>(b1, b2, b3, W4, b4);
    k_reduce<<<1, 256>>>((float*)d_out);
}

// round 11
// speedup vs baseline: 3.6648x; 1.0497x over previous
#include <cuda_runtime.h>
#include <cuda_bf16.h>
#include <cuda_fp16.h>
#include <cstdint>
#include <math.h>

#define S_  4
#define E_  8
#define D_  384
#define H1_ 160
#define H2_ 128
#define H3_ 96
#define N_  40000
#define TM  128
#define NTT 313
#define NB  ((N_ + 255) / 256)
#define NPART (NTT * S_ * 4)
#define MAXT 320
#define THREADS 512

typedef unsigned long long ull;
typedef uint32_t u32;
typedef unsigned short u16;

// ---------------- gmem image geometry ----------------
// A tiles: 6 chunks x (Ah [128][72] f16 18432 B | Al 18432 B)
#define ACH   36864
#define ASE   (6 * ACH)
// Weights per (s,e):
//  W1 @0:      6 chunks x 23040, single fp16 [160][72]
//  W2 @276480: single fp16; c0@+0 18432 [128][72], c1@+18432 18432, c2@+36864 10240 [128][40]
//  W3 @370688: bf16 hi/lo; 2 chunks x 27648 (hi|lo 13824), [96][72]
#define W1OFF 0
#define W2OFF 276480
#define W3OFF 370688
#define WSE   425984

__device__ int   g_is64;
__device__ int   g_blockCnt[NB * S_];
__device__ int   g_blockOff[NB * S_];
__device__ int   g_count[S_];
__device__ int   g_tbase[S_];
__device__ int   g_idx[S_ * N_];
__device__ float g_partial[NPART];
__device__ __align__(1024) unsigned char g_Wimg[(size_t)32 * WSE];
__device__ __align__(1024) unsigned char g_Aimg[(size_t)MAXT * ASE];

// ---------------- helpers ----------------
static __device__ __forceinline__ float celu_f(float x) {
    return x > 0.f ? x : 0.1f * (__expf(x * 10.f) - 1.f);
}
static __device__ __forceinline__ u32 s2u(const void* p) {
    u32 a;
    asm("{ .reg .u64 t; cvta.to.shared.u64 t, %1; cvt.u32.u64 %0, t; }" : "=r"(a) : "l"(p));
    return a;
}
static __device__ __forceinline__ void split2(float v, u16& h, u16& l) {
    __nv_bfloat16 hb = __float2bfloat16(v);
    float hf = __bfloat162float(hb);
    __nv_bfloat16 lb = __float2bfloat16(v - hf);
    h = __bfloat16_as_ushort(hb);
    l = __bfloat16_as_ushort(lb);
}
// fp32 pair -> packed bf16x2 hi + residual bf16x2 lo
static __device__ __forceinline__ void splitpair(float x, float y, u32& h, u32& l) {
    u32 hh;
    asm("cvt.rn.bf16x2.f32 %0, %1, %2;" : "=r"(hh) : "f"(y), "f"(x));
    float xh = __uint_as_float(hh << 16);
    float yh = __uint_as_float(hh & 0xffff0000u);
    asm("cvt.rn.bf16x2.f32 %0, %1, %2;" : "=r"(l) : "f"(y - yh), "f"(x - xh));
    h = hh;
}
// fp32 pair -> packed f16x2 hi + f16x2 residual
static __device__ __forceinline__ void splitpairh(float x, float y, u32& h, u32& l) {
    u32 hh;
    asm("cvt.rn.f16x2.f32 %0, %1, %2;" : "=r"(hh) : "f"(y), "f"(x));
    float xh, yh;
    asm("{ .reg .f16 lo, hi; mov.b32 {lo, hi}, %2; cvt.f32.f16 %0, lo; cvt.f32.f16 %1, hi; }"
        : "=f"(xh), "=f"(yh) : "r"(hh));
    asm("cvt.rn.f16x2.f32 %0, %1, %2;" : "=r"(l) : "f"(y - yh), "f"(x - xh));
    h = hh;
}
static __device__ __forceinline__ void mma_bf(float* c,
        u32 a0, u32 a1, u32 a2, u32 a3, u32 b0, u32 b1) {
    asm volatile(
        "mma.sync.aligned.m16n8k16.row.col.f32.bf16.bf16.f32 "
        "{%0,%1,%2,%3},{%4,%5,%6,%7},{%8,%9},{%0,%1,%2,%3};"
        : "+f"(c[0]), "+f"(c[1]), "+f"(c[2]), "+f"(c[3])
        : "r"(a0), "r"(a1), "r"(a2), "r"(a3), "r"(b0), "r"(b1));
}
static __device__ __forceinline__ void mma_fp(float* c,
        u32 a0, u32 a1, u32 a2, u32 a3, u32 b0, u32 b1) {
    asm volatile(
        "mma.sync.aligned.m16n8k16.row.col.f32.f16.f16.f32 "
        "{%0,%1,%2,%3},{%4,%5,%6,%7},{%8,%9},{%0,%1,%2,%3};"
        : "+f"(c[0]), "+f"(c[1]), "+f"(c[2]), "+f"(c[3])
        : "r"(a0), "r"(a1), "r"(a2), "r"(a3), "r"(b0), "r"(b1));
}
#define CPA16(d, s) asm volatile("cp.async.cg.shared.global [%0], [%1], 16;" :: "r"(d), "l"(s) : "memory")
#define CPCOMMIT()  asm volatile("cp.async.commit_group;" ::: "memory")
#define CPWAIT(n)   asm volatile("cp.async.wait_group %0;" :: "n"(n) : "memory")

// ---------------- bucketing ----------------
__global__ void k_init(const ull* spq) {
    int tid = threadIdx.x;
    for (int i = tid; i < NPART; i += 256) g_partial[i] = 0.f;
    if (tid < 32) {
        ull v = spq[tid];
        int hiNZ = ((v >> 32) != 0ull) ? 1 : 0;
        int any = __any_sync(0xffffffffu, hiNZ);
        if (tid == 0) g_is64 = any ? 0 : 1;
    }
}
__global__ void k_count(const int* sp) {
    int tid = threadIdx.x, b = blockIdx.x;
    int n = b * 256 + tid;
    int shift = g_is64;
    int spv = -1;
    if (n < N_) spv = sp[(size_t)n << shift];
    __shared__ int wc[8][4];
    if (tid < 32) wc[tid >> 2][tid & 3] = 0;
    __syncthreads();
    unsigned mm = __match_any_sync(0xffffffffu, spv);
    int lane = tid & 31, w = tid >> 5;
    if (spv >= 0 && lane == (__ffs(mm) - 1)) wc[w][spv] = __popc(mm);
    __syncthreads();
    if (tid < 4) {
        int s = 0;
        for (int ww = 0; ww < 8; ww++) s += wc[ww][tid];
        g_blockCnt[b * 4 + tid] = s;
    }
}
__global__ void k_scan() {
    __shared__ int c[NB * 4];
    __shared__ int o[NB * 4];
    int tid = threadIdx.x;
    for (int i = tid; i < NB * 4; i += 256) c[i] = g_blockCnt[i];
    __syncthreads();
    if (tid == 0) {
        int r0 = 0, r1 = 0, r2 = 0, r3 = 0;
        for (int b = 0; b < NB; b++) {
            o[b * 4 + 0] = r0; r0 += c[b * 4 + 0];
            o[b * 4 + 1] = r1; r1 += c[b * 4 + 1];
            o[b * 4 + 2] = r2; r2 += c[b * 4 + 2];
            o[b * 4 + 3] = r3; r3 += c[b * 4 + 3];
        }
        g_count[0] = r0; g_count[1] = r1; g_count[2] = r2; g_count[3] = r3;
        int tb = 0;
        g_tbase[0] = 0;  tb += (r0 + TM - 1) / TM;
        g_tbase[1] = tb; tb += (r1 + TM - 1) / TM;
        g_tbase[2] = tb; tb += (r2 + TM - 1) / TM;
        g_tbase[3] = tb;
    }
    __syncthreads();
    for (int i = tid; i < NB * 4; i += 256) g_blockOff[i] = o[i];
}
__global__ void k_scatter(const int* sp) {
    int tid = threadIdx.x, b = blockIdx.x;
    int n = b * 256 + tid;
    int shift = g_is64;
    int spv = -1;
    if (n < N_) spv = sp[(size_t)n << shift];
    __shared__ int wc[8][4];
    __shared__ int woff[8][4];
    if (tid < 32) wc[tid >> 2][tid & 3] = 0;
    __syncthreads();
    unsigned mm = __match_any_sync(0xffffffffu, spv);
    int lane = tid & 31, w = tid >> 5;
    int rank = __popc(mm & ((1u << lane) - 1u));
    if (spv >= 0 && lane == (__ffs(mm) - 1)) wc[w][spv] = __popc(mm);
    __syncthreads();
    if (tid < 4) {
        int run = g_blockOff[b * 4 + tid];
        for (int ww = 0; ww < 8; ww++) { woff[ww][tid] = run; run += wc[ww][tid]; }
    }
    __syncthreads();
    if (spv >= 0) g_idx[spv * N_ + woff[w][spv] + rank] = n;
}

// ---------------- weight image prep ----------------
__global__ void k_wprep(const float* __restrict__ W1, const float* __restrict__ W2,
                        const float* __restrict__ W3) {
    int se = blockIdx.x;
    int tid0 = threadIdx.x + blockIdx.y * 256;
    const int step = 256 * 8;
    unsigned char* base = g_Wimg + (size_t)se * WSE;
    for (int i = tid0; i < D_ * H1_; i += step) {           // W1: single fp16
        int n = i % H1_, k = i / H1_;
        u16 h = __half_as_ushort(__float2half_rn(W1[((size_t)se * D_ + k) * H1_ + n]));
        int c = k >> 6, kl = k & 63;
        ((u16*)(base + W1OFF + c * 23040))[n * 72 + kl] = h;
    }
    for (int i = tid0; i < H1_ * H2_; i += step) {          // W2: single fp16
        int n = i % H2_, k = i / H2_;
        u16 h = __half_as_ushort(__float2half_rn(W2[((size_t)se * H1_ + k) * H2_ + n]));
        int c = k >> 6, kl = k & 63;
        int str = (c == 2) ? 40 : 72;
        int coff = (c == 0) ? 0 : (c == 1 ? 18432 : 36864);
        ((u16*)(base + W2OFF + coff))[n * str + kl] = h;
    }
    for (int i = tid0; i < H2_ * H3_; i += step) {          // W3: bf16 hi/lo
        int n = i % H3_, k = i / H3_;
        u16 h, l; split2(W3[((size_t)se * H2_ + k) * H3_ + n], h, l);
        int c = k >> 6, kl = k & 63;
        u16* p = (u16*)(base + W3OFF + c * 27648);
        p[n * 72 + kl] = h;
        p[6912 + n * 72 + kl] = l;
    }
}

// ---------------- A image prep: gather + fp16 hi/lo split ----------------
__global__ void k_aprep(const float* __restrict__ aev) {
    int t = blockIdx.x, s = blockIdx.y, tid = threadIdx.x;
    int cnt = g_count[s];
    int ntl = (cnt + TM - 1) / TM;
    if (t >= ntl) return;
    int gt = g_tbase[s] + t;
    __shared__ int sidx[TM];
    if (tid < TM) {
        int p = t * TM + tid; if (p >= cnt) p = cnt - 1;
        sidx[tid] = g_idx[s * N_ + p];
    }
    __syncthreads();
    unsigned char* base = g_Aimg + (size_t)gt * ASE;
    for (int i = tid; i < TM * (D_ / 2); i += 256) {
        int m = i / (D_ / 2), k = (i % (D_ / 2)) * 2;
        float2 v = *(const float2*)(aev + (size_t)sidx[m] * D_ + k);
        u32 h, l; splitpairh(v.x, v.y, h, l);
        int c = k >> 6, kl = k & 63;
        u16* ch = (u16*)(base + c * ACH);
        *(u32*)(ch + m * 72 + kl) = h;
        *(u32*)(ch + 9216 + m * 72 + kl) = l;
    }
}

// ---------------- bf16 3-term fragment GEMM, term-major ----------------
template<int NT>
static __device__ __forceinline__ void chunk_mma3(
    float (*acc)[NT][4],
    const u16* Ah, const u16* Al, int astr,
    const u16* Wh, const u16* Wl, int wstr,
    int ksteps, int mbase, int nbase, int g, int q)
{
    for (int ks = 0; ks < ksteps; ks++) {
        const int k0 = ks * 16;
        u32 ah[2][4], al[2][4];
#pragma unroll
        for (int mt = 0; mt < 2; mt++) {
            const u16* ap = Ah + (mbase + mt * 16 + g) * astr + k0 + q * 2;
            const u16* aq = Al + (mbase + mt * 16 + g) * astr + k0 + q * 2;
            ah[mt][0] = *(const u32*)(ap);
            ah[mt][1] = *(const u32*)(ap + 8 * astr);
            ah[mt][2] = *(const u32*)(ap + 8);
            ah[mt][3] = *(const u32*)(ap + 8 * astr + 8);
            al[mt][0] = *(const u32*)(aq);
            al[mt][1] = *(const u32*)(aq + 8 * astr);
            al[mt][2] = *(const u32*)(aq + 8);
            al[mt][3] = *(const u32*)(aq + 8 * astr + 8);
        }
        u32 bh[NT][2];
#pragma unroll
        for (int nt = 0; nt < NT; nt++) {           // term 1: hi*hi
            const u16* wp = Wh + (nbase + nt * 8 + g) * wstr + k0 + q * 2;
            bh[nt][0] = *(const u32*)(wp);
            bh[nt][1] = *(const u32*)(wp + 8);
            mma_bf(acc[0][nt], ah[0][0], ah[0][1], ah[0][2], ah[0][3], bh[nt][0], bh[nt][1]);
            mma_bf(acc[1][nt], ah[1][0], ah[1][1], ah[1][2], ah[1][3], bh[nt][0], bh[nt][1]);
        }
#pragma unroll
        for (int nt = 0; nt < NT; nt++) {           // term 2: lo*hi
            mma_bf(acc[0][nt], al[0][0], al[0][1], al[0][2], al[0][3], bh[nt][0], bh[nt][1]);
            mma_bf(acc[1][nt], al[1][0], al[1][1], al[1][2], al[1][3], bh[nt][0], bh[nt][1]);
        }
#pragma unroll
        for (int nt = 0; nt < NT; nt++) {           // term 3: hi*lo
            const u16* wq = Wl + (nbase + nt * 8 + g) * wstr + k0 + q * 2;
            u32 bl0 = *(const u32*)(wq);
            u32 bl1 = *(const u32*)(wq + 8);
            mma_bf(acc[0][nt], ah[0][0], ah[0][1], ah[0][2], ah[0][3], bl0, bl1);
            mma_bf(acc[1][nt], ah[1][0], ah[1][1], ah[1][2], ah[1][3], bl0, bl1);
        }
    }
}

// ---------------- fp16 2-term fragment GEMM, term-major ----------------
template<int NT>
static __device__ __forceinline__ void chunk_mma2(
    float (*acc)[NT][4],
    const u16* Ah, const u16* Al, int astr,
    const u16* Wh, int wstr,
    int ksteps, int mbase, int nbase, int g, int q)
{
    for (int ks = 0; ks < ksteps; ks++) {
        const int k0 = ks * 16;
        u32 ah[2][4], al[2][4];
#pragma unroll
        for (int mt = 0; mt < 2; mt++) {
            const u16* ap = Ah + (mbase + mt * 16 + g) * astr + k0 + q * 2;
            const u16* aq = Al + (mbase + mt * 16 + g) * astr + k0 + q * 2;
            ah[mt][0] = *(const u32*)(ap);
            ah[mt][1] = *(const u32*)(ap + 8 * astr);
            ah[mt][2] = *(const u32*)(ap + 8);
            ah[mt][3] = *(const u32*)(ap + 8 * astr + 8);
            al[mt][0] = *(const u32*)(aq);
            al[mt][1] = *(const u32*)(aq + 8 * astr);
            al[mt][2] = *(const u32*)(aq + 8);
            al[mt][3] = *(const u32*)(aq + 8 * astr + 8);
        }
        u32 bh[NT][2];
#pragma unroll
        for (int nt = 0; nt < NT; nt++) {           // term 1: ah * w
            const u16* wp = Wh + (nbase + nt * 8 + g) * wstr + k0 + q * 2;
            bh[nt][0] = *(const u32*)(wp);
            bh[nt][1] = *(const u32*)(wp + 8);
            mma_fp(acc[0][nt], ah[0][0], ah[0][1], ah[0][2], ah[0][3], bh[nt][0], bh[nt][1]);
            mma_fp(acc[1][nt], ah[1][0], ah[1][1], ah[1][2], ah[1][3], bh[nt][0], bh[nt][1]);
        }
#pragma unroll
        for (int nt = 0; nt < NT; nt++) {           // term 2: al * w (w cached)
            mma_fp(acc[0][nt], al[0][0], al[0][1], al[0][2], al[0][3], bh[nt][0], bh[nt][1]);
            mma_fp(acc[1][nt], al[1][0], al[1][1], al[1][2], al[1][3], bh[nt][0], bh[nt][1]);
        }
    }
}

// ---------------- main kernel ----------------
// SMEM: L1 stages @0, @59904 (A 36864 | W1 23040 each; dead before H1 writes).
// H1 image 0..94208 (fp16 hi/lo). WB0 @98304, WB1 @135168. H2 image @ {0, 36864}
// (bf16 hi/lo). misc @172032.
#define SSTG  59904
#define WB0   98304
#define WB1   135168
#define MISCO 172032
#define SMEMB (MISCO + 4096)

__global__ void __launch_bounds__(THREADS, 1) k_main(
    const float* __restrict__ b1, const float* __restrict__ b2,
    const float* __restrict__ b3, const float* __restrict__ W4,
    const float* __restrict__ b4)
{
    extern __shared__ __align__(16) unsigned char sm[];
    const int s = blockIdx.y, t = blockIdx.x, z = blockIdx.z, tid = threadIdx.x;
    const int cnt = g_count[s];
    const int ntl = (cnt + TM - 1) / TM;
    if (t >= ntl) return;
    const int nvalid = min(TM, cnt - t * TM);
    const int gt = g_tbase[s] + t;
    const int lane = tid & 31, w = tid >> 5;
    const int wm = w & 3, wn = w >> 2, g = lane >> 2, q = lane & 3;
    const int mbase = wm * 32;
    const u32 sb = s2u(sm);
    float* b1s = (float*)(sm + MISCO);
    float* b2s = b1s + 160;
    float* b3s = b2s + 128;
    float* w4s = b3s + 96;
    float* part = w4s + 96;

    const unsigned char* Ab = g_Aimg + (size_t)gt * ASE;
    float blockSum = 0.f;

    const int h1off[3]  = {0, 36864, 73728};
    const int h1half[3] = {9216, 9216, 5120};
    const int h1str[3]  = {72, 72, 40};

    for (int ei = 0; ei < 2; ei++) {
        const int se = s * E_ + z * 2 + ei;
        const unsigned char* Wb = g_Wimg + (size_t)se * WSE;
        if (tid < 160) b1s[tid] = b1[se * H1_ + tid];
        if (tid < 128) b2s[tid] = b2[se * H2_ + tid];
        if (tid < 96) { b3s[tid] = b3[se * H3_ + tid]; w4s[tid] = W4[se * H3_ + tid]; }

        auto cpyW = [&](const unsigned char* src, int bytes, u32 dstoff) {
            for (int i = tid * 16; i < bytes; i += THREADS * 16) CPA16(sb + dstoff + i, src + i);
            CPCOMMIT();
        };

        // ========= Layer 1 (K=384, N=160): fp16 2-term, NT=5 per warp =========
        float acc1[2][5][4];
#pragma unroll
        for (int a = 0; a < 2; a++)
#pragma unroll
            for (int b = 0; b < 5; b++)
#pragma unroll
                for (int c = 0; c < 4; c++) acc1[a][b][c] = 0.f;

        auto cpyL1 = [&](int c, int bf) {
            u32 dst = sb + (bf ? SSTG : 0);
            const unsigned char* gA = Ab + c * ACH;
            for (int i = tid * 16; i < ACH; i += THREADS * 16) CPA16(dst + i, gA + i);
            const unsigned char* gW = Wb + W1OFF + c * 23040;
            for (int i = tid * 16; i < 23040; i += THREADS * 16) CPA16(dst + ACH + i, gW + i);
            CPCOMMIT();
        };
        cpyL1(0, 0); cpyL1(1, 1);
        for (int kc = 0; kc < 6; kc++) {
            if (kc == 5) { CPWAIT(0); } else { CPWAIT(1); }
            __syncthreads();
            const unsigned char* st = sm + ((kc & 1) ? SSTG : 0);
            chunk_mma2<5>(acc1, (const u16*)st, (const u16*)st + 9216, 72,
                          (const u16*)(st + ACH), 72,
                          4, mbase, wn * 40, g, q);
            __syncthreads();
            if (kc < 4) cpyL1(kc + 2, kc & 1);
        }
        // prefetch W2 chunks 0,1 (fp16) — overlaps with L1 epilogue
        cpyW(Wb + W2OFF, 18432, WB0);
        cpyW(Wb + W2OFF + 18432, 18432, WB1);

        // epilogue -> H1 (fp16 hi/lo)
#pragma unroll
        for (int mt = 0; mt < 2; mt++)
#pragma unroll
            for (int nt = 0; nt < 5; nt++) {
                int n0 = wn * 40 + nt * 8 + q * 2;
                int cb = n0 >> 6, off = n0 & 63;
                u16* Hh = (u16*)(sm + h1off[cb]);
                u16* Hl = Hh + h1half[cb];
                int str = h1str[cb];
                int row = mbase + mt * 16 + g;
                u32 h, l;
                splitpairh(celu_f(acc1[mt][nt][0] + b1s[n0]),
                           celu_f(acc1[mt][nt][1] + b1s[n0 + 1]), h, l);
                *(u32*)(Hh + row * str + off) = h;
                *(u32*)(Hl + row * str + off) = l;
                splitpairh(celu_f(acc1[mt][nt][2] + b1s[n0]),
                           celu_f(acc1[mt][nt][3] + b1s[n0 + 1]), h, l);
                *(u32*)(Hh + (row + 8) * str + off) = h;
                *(u32*)(Hl + (row + 8) * str + off) = l;
            }
        __syncthreads();

        // ========= Layer 2 (K=160, N=128): fp16 2-term, NT=4 =========
        float acc2[2][4][4];
#pragma unroll
        for (int a = 0; a < 2; a++)
#pragma unroll
            for (int b = 0; b < 4; b++)
#pragma unroll
                for (int c = 0; c < 4; c++) acc2[a][b][c] = 0.f;

        for (int kc = 0; kc < 3; kc++) {
            if (kc == 2) { CPWAIT(0); } else { CPWAIT(1); }
            __syncthreads();
            const unsigned char* wb = sm + ((kc & 1) ? WB1 : WB0);
            int str = (kc == 2) ? 40 : 72;
            int ks = (kc == 2) ? 2 : 4;
            chunk_mma2<4>(acc2,
                          (const u16*)(sm + h1off[kc]), (const u16*)(sm + h1off[kc]) + h1half[kc], h1str[kc],
                          (const u16*)wb, str,
                          ks, mbase, wn * 32, g, q);
            __syncthreads();
            if (kc == 0) cpyW(Wb + W2OFF + 36864, 10240, WB0);
        }
        // prefetch W3 chunks 0,1 (bf16 hi/lo) — overlaps with L2 epilogue
        cpyW(Wb + W3OFF, 27648, WB0);
        cpyW(Wb + W3OFF + 27648, 27648, WB1);

        // epilogue -> H2 (bf16 hi/lo @ {0, 36864})
#pragma unroll
        for (int mt = 0; mt < 2; mt++)
#pragma unroll
            for (int nt = 0; nt < 4; nt++) {
                int n0 = wn * 32 + nt * 8 + q * 2;
                int cb = n0 >> 6, off = n0 & 63;
                u16* Hh = (u16*)(sm + cb * 36864);
                u16* Hl = Hh + 9216;
                int row = mbase + mt * 16 + g;
                u32 h, l;
                splitpair(celu_f(acc2[mt][nt][0] + b2s[n0]),
                          celu_f(acc2[mt][nt][1] + b2s[n0 + 1]), h, l);
                *(u32*)(Hh + row * 72 + off) = h;
                *(u32*)(Hl + row * 72 + off) = l;
                splitpair(celu_f(acc2[mt][nt][2] + b2s[n0]),
                          celu_f(acc2[mt][nt][3] + b2s[n0 + 1]), h, l);
                *(u32*)(Hh + (row + 8) * 72 + off) = h;
                *(u32*)(Hl + (row + 8) * 72 + off) = l;
            }
        __syncthreads();

        // ========= Layer 3 (K=128, N=96): bf16 3-term, NT=3 =========
        float acc3[2][3][4];
#pragma unroll
        for (int a = 0; a < 2; a++)
#pragma unroll
            for (int b = 0; b < 3; b++)
#pragma unroll
                for (int c = 0; c < 4; c++) acc3[a][b][c] = 0.f;

        for (int kc = 0; kc < 2; kc++) {
            if (kc == 1) { CPWAIT(0); } else { CPWAIT(1); }
            __syncthreads();
            const unsigned char* wb = sm + ((kc & 1) ? WB1 : WB0);
            chunk_mma3<3>(acc3,
                          (const u16*)(sm + kc * 36864), (const u16*)(sm + kc * 36864) + 9216, 72,
                          (const u16*)wb, (const u16*)wb + 6912, 72,
                          4, mbase, wn * 24, g, q);
            __syncthreads();
        }
        // ========= fused L3-epilogue + Layer 4 =========
        {
            float p00 = 0.f, p01 = 0.f, p10 = 0.f, p11 = 0.f;
#pragma unroll
            for (int nt = 0; nt < 3; nt++) {
                int n0 = wn * 24 + nt * 8 + q * 2;
                float w0 = w4s[n0], w1 = w4s[n0 + 1];
                float bb0 = b3s[n0], bb1 = b3s[n0 + 1];
                p00 += celu_f(acc3[0][nt][0] + bb0) * w0 + celu_f(acc3[0][nt][1] + bb1) * w1;
                p01 += celu_f(acc3[0][nt][2] + bb0) * w0 + celu_f(acc3[0][nt][3] + bb1) * w1;
                p10 += celu_f(acc3[1][nt][0] + bb0) * w0 + celu_f(acc3[1][nt][1] + bb1) * w1;
                p11 += celu_f(acc3[1][nt][2] + bb0) * w0 + celu_f(acc3[1][nt][3] + bb1) * w1;
            }
            p00 += __shfl_xor_sync(0xffffffffu, p00, 1); p00 += __shfl_xor_sync(0xffffffffu, p00, 2);
            p01 += __shfl_xor_sync(0xffffffffu, p01, 1); p01 += __shfl_xor_sync(0xffffffffu, p01, 2);
            p10 += __shfl_xor_sync(0xffffffffu, p10, 1); p10 += __shfl_xor_sync(0xffffffffu, p10, 2);
            p11 += __shfl_xor_sync(0xffffffffu, p11, 1); p11 += __shfl_xor_sync(0xffffffffu, p11, 2);
            if (q == 0) {
                part[wn * 128 + mbase + g]          = p00;
                part[wn * 128 + mbase + g + 8]      = p01;
                part[wn * 128 + mbase + 16 + g]     = p10;
                part[wn * 128 + mbase + 16 + g + 8] = p11;
            }
        }
        __syncthreads();
        if (tid < 128) {
            float en = part[tid] + part[128 + tid] + part[256 + tid] + part[384 + tid] + b4[se];
            part[tid] = (tid < nvalid) ? en : 0.f;
        }
        __syncthreads();
        if (tid < 32) {
            float v = part[tid] + part[tid + 32] + part[tid + 64] + part[tid + 96];
            for (int o = 16; o; o >>= 1) v += __shfl_down_sync(0xffffffffu, v, o);
            if (tid == 0) blockSum += v;
        }
        __syncthreads();
    }
    if (tid == 0) g_partial[(s * NTT + t) * 4 + z] = blockSum;
}

// ---------------- final reduction ----------------
__global__ void k_reduce(float* out) {
    __shared__ double sb[256];
    int tid = threadIdx.x;
    double s = 0.0;
    for (int i = tid; i < NPART; i += 256) s += (double)g_partial[i];
    sb[tid] = s;
    __syncthreads();
    for (int st = 128; st; st >>= 1) {
        if (tid < st) sb[tid] += sb[tid + st];
        __syncthreads();
    }
    if (tid == 0) out[0] = (float)(sb[0] * (1.0 / E_));
}

// ---------------- launch ----------------
extern "C" void kernel_launch(void* const* d_in, const int* in_sizes, int n_in,
                              void* d_out, int out_size)
{
    const void*  sp  = d_in[0];
    const float* aev = (const float*)d_in[1];
    const float* W1  = (const float*)d_in[2];
    const float* b1  = (const float*)d_in[3];
    const float* W2  = (const float*)d_in[4];
    const float* b2  = (const float*)d_in[5];
    const float* W3  = (const float*)d_in[6];
    const float* b3  = (const float*)d_in[7];
    const float* W4  = (const float*)d_in[8];
    const float* b4  = (const float*)d_in[9];

    cudaFuncSetAttribute(k_main, cudaFuncAttributeMaxDynamicSharedMemorySize, SMEMB);

    k_init<<<1, 256>>>((const ull*)sp);
    k_count<<<NB, 256>>>((const int*)sp);
    k_scan<<<1, 256>>>();
    k_scatter<<<NB, 256>>>((const int*)sp);
    dim3 gw(32, 8);
    k_wprep<<<gw, 256>>>(W1, W2, W3);
    dim3 ga(NTT, S_);
    k_aprep<<<ga, 256>>>(aev);
    dim3 gm(NTT, S_, 4);
    k_main<<<gm, THREADS, SMEMB>>>(b1, b2, b3, W4, b4);
    k_reduce<<<1, 256>>>((float*)d_out);
}

// round 12
// speedup vs baseline: 4.3906x; 1.1980x over previous
#include <cuda_runtime.h>
#include <cuda_bf16.h>
#include <cuda_fp16.h>
#include <cstdint>
#include <math.h>

#define S_  4
#define E_  8
#define D_  384
#define H1_ 160
#define H2_ 128
#define H3_ 96
#define N_  40000
#define TM  128
#define NTT 313
#define NB  ((N_ + 255) / 256)
#define NPART (NTT * S_ * 4)
#define MAXT 320
#define THREADS 512

typedef unsigned long long ull;
typedef uint32_t u32;
typedef unsigned short u16;

// ---------------- gmem image geometry ----------------
// A tiles: 6 chunks x (Ah [128][72] f16 18432 B | (lo half unused))
#define ACH   36864
#define ASE   (6 * ACH)
// Weights per (s,e):
//  W1 @0:      6 chunks x 23040, single fp16 [160][72]
//  W2 @276480: single fp16; c0@+0 18432 [128][72], c1@+18432 18432, c2@+36864 10240 [128][40]
//  W3 @370688: bf16 hi/lo; 2 chunks x 27648 (hi|lo 13824), [96][72]
#define W1OFF 0
#define W2OFF 276480
#define W3OFF 370688
#define WSE   425984

__device__ int   g_is64;
__device__ int   g_blockCnt[NB * S_];
__device__ int   g_blockOff[NB * S_];
__device__ int   g_count[S_];
__device__ int   g_tbase[S_];
__device__ int   g_idx[S_ * N_];
__device__ float g_partial[NPART];
__device__ __align__(1024) unsigned char g_Wimg[(size_t)32 * WSE];
__device__ __align__(1024) unsigned char g_Aimg[(size_t)MAXT * ASE];

// ---------------- helpers ----------------
static __device__ __forceinline__ float celu_f(float x) {
    return x > 0.f ? x : 0.1f * (__expf(x * 10.f) - 1.f);
}
static __device__ __forceinline__ u32 s2u(const void* p) {
    u32 a;
    asm("{ .reg .u64 t; cvta.to.shared.u64 t, %1; cvt.u32.u64 %0, t; }" : "=r"(a) : "l"(p));
    return a;
}
static __device__ __forceinline__ void split2(float v, u16& h, u16& l) {
    __nv_bfloat16 hb = __float2bfloat16(v);
    float hf = __bfloat162float(hb);
    __nv_bfloat16 lb = __float2bfloat16(v - hf);
    h = __bfloat16_as_ushort(hb);
    l = __bfloat16_as_ushort(lb);
}
// fp32 pair -> packed bf16x2 hi + residual bf16x2 lo
static __device__ __forceinline__ void splitpair(float x, float y, u32& h, u32& l) {
    u32 hh;
    asm("cvt.rn.bf16x2.f32 %0, %1, %2;" : "=r"(hh) : "f"(y), "f"(x));
    float xh = __uint_as_float(hh << 16);
    float yh = __uint_as_float(hh & 0xffff0000u);
    asm("cvt.rn.bf16x2.f32 %0, %1, %2;" : "=r"(l) : "f"(y - yh), "f"(x - xh));
    h = hh;
}
// fp32 pair -> packed f16x2 hi + f16x2 residual
static __device__ __forceinline__ void splitpairh(float x, float y, u32& h, u32& l) {
    u32 hh;
    asm("cvt.rn.f16x2.f32 %0, %1, %2;" : "=r"(hh) : "f"(y), "f"(x));
    float xh, yh;
    asm("{ .reg .f16 lo, hi; mov.b32 {lo, hi}, %2; cvt.f32.f16 %0, lo; cvt.f32.f16 %1, hi; }"
        : "=f"(xh), "=f"(yh) : "r"(hh));
    asm("cvt.rn.f16x2.f32 %0, %1, %2;" : "=r"(l) : "f"(y - yh), "f"(x - xh));
    h = hh;
}
// fp32 pair -> packed f16x2 (hi only)
static __device__ __forceinline__ u32 packh(float x, float y) {
    u32 hh;
    asm("cvt.rn.f16x2.f32 %0, %1, %2;" : "=r"(hh) : "f"(y), "f"(x));
    return hh;
}
static __device__ __forceinline__ void mma_bf(float* c,
        u32 a0, u32 a1, u32 a2, u32 a3, u32 b0, u32 b1) {
    asm volatile(
        "mma.sync.aligned.m16n8k16.row.col.f32.bf16.bf16.f32 "
        "{%0,%1,%2,%3},{%4,%5,%6,%7},{%8,%9},{%0,%1,%2,%3};"
        : "+f"(c[0]), "+f"(c[1]), "+f"(c[2]), "+f"(c[3])
        : "r"(a0), "r"(a1), "r"(a2), "r"(a3), "r"(b0), "r"(b1));
}
static __device__ __forceinline__ void mma_fp(float* c,
        u32 a0, u32 a1, u32 a2, u32 a3, u32 b0, u32 b1) {
    asm volatile(
        "mma.sync.aligned.m16n8k16.row.col.f32.f16.f16.f32 "
        "{%0,%1,%2,%3},{%4,%5,%6,%7},{%8,%9},{%0,%1,%2,%3};"
        : "+f"(c[0]), "+f"(c[1]), "+f"(c[2]), "+f"(c[3])
        : "r"(a0), "r"(a1), "r"(a2), "r"(a3), "r"(b0), "r"(b1));
}
#define CPA16(d, s) asm volatile("cp.async.cg.shared.global [%0], [%1], 16;" :: "r"(d), "l"(s) : "memory")
#define CPCOMMIT()  asm volatile("cp.async.commit_group;" ::: "memory")
#define CPWAIT(n)   asm volatile("cp.async.wait_group %0;" :: "n"(n) : "memory")

// ---------------- bucketing ----------------
__global__ void k_init(const ull* spq) {
    int tid = threadIdx.x;
    for (int i = tid; i < NPART; i += 256) g_partial[i] = 0.f;
    if (tid < 32) {
        ull v = spq[tid];
        int hiNZ = ((v >> 32) != 0ull) ? 1 : 0;
        int any = __any_sync(0xffffffffu, hiNZ);
        if (tid == 0) g_is64 = any ? 0 : 1;
    }
}
__global__ void k_count(const int* sp) {
    int tid = threadIdx.x, b = blockIdx.x;
    int n = b * 256 + tid;
    int shift = g_is64;
    int spv = -1;
    if (n < N_) spv = sp[(size_t)n << shift];
    __shared__ int wc[8][4];
    if (tid < 32) wc[tid >> 2][tid & 3] = 0;
    __syncthreads();
    unsigned mm = __match_any_sync(0xffffffffu, spv);
    int lane = tid & 31, w = tid >> 5;
    if (spv >= 0 && lane == (__ffs(mm) - 1)) wc[w][spv] = __popc(mm);
    __syncthreads();
    if (tid < 4) {
        int s = 0;
        for (int ww = 0; ww < 8; ww++) s += wc[ww][tid];
        g_blockCnt[b * 4 + tid] = s;
    }
}
__global__ void k_scan() {
    __shared__ int c[NB * 4];
    __shared__ int o[NB * 4];
    int tid = threadIdx.x;
    for (int i = tid; i < NB * 4; i += 256) c[i] = g_blockCnt[i];
    __syncthreads();
    if (tid == 0) {
        int r0 = 0, r1 = 0, r2 = 0, r3 = 0;
        for (int b = 0; b < NB; b++) {
            o[b * 4 + 0] = r0; r0 += c[b * 4 + 0];
            o[b * 4 + 1] = r1; r1 += c[b * 4 + 1];
            o[b * 4 + 2] = r2; r2 += c[b * 4 + 2];
            o[b * 4 + 3] = r3; r3 += c[b * 4 + 3];
        }
        g_count[0] = r0; g_count[1] = r1; g_count[2] = r2; g_count[3] = r3;
        int tb = 0;
        g_tbase[0] = 0;  tb += (r0 + TM - 1) / TM;
        g_tbase[1] = tb; tb += (r1 + TM - 1) / TM;
        g_tbase[2] = tb; tb += (r2 + TM - 1) / TM;
        g_tbase[3] = tb;
    }
    __syncthreads();
    for (int i = tid; i < NB * 4; i += 256) g_blockOff[i] = o[i];
}
__global__ void k_scatter(const int* sp) {
    int tid = threadIdx.x, b = blockIdx.x;
    int n = b * 256 + tid;
    int shift = g_is64;
    int spv = -1;
    if (n < N_) spv = sp[(size_t)n << shift];
    __shared__ int wc[8][4];
    __shared__ int woff[8][4];
    if (tid < 32) wc[tid >> 2][tid & 3] = 0;
    __syncthreads();
    unsigned mm = __match_any_sync(0xffffffffu, spv);
    int lane = tid & 31, w = tid >> 5;
    int rank = __popc(mm & ((1u << lane) - 1u));
    if (spv >= 0 && lane == (__ffs(mm) - 1)) wc[w][spv] = __popc(mm);
    __syncthreads();
    if (tid < 4) {
        int run = g_blockOff[b * 4 + tid];
        for (int ww = 0; ww < 8; ww++) { woff[ww][tid] = run; run += wc[ww][tid]; }
    }
    __syncthreads();
    if (spv >= 0) g_idx[spv * N_ + woff[w][spv] + rank] = n;
}

// ---------------- weight image prep ----------------
__global__ void k_wprep(const float* __restrict__ W1, const float* __restrict__ W2,
                        const float* __restrict__ W3) {
    int se = blockIdx.x;
    int tid0 = threadIdx.x + blockIdx.y * 256;
    const int step = 256 * 8;
    unsigned char* base = g_Wimg + (size_t)se * WSE;
    for (int i = tid0; i < D_ * H1_; i += step) {           // W1: single fp16
        int n = i % H1_, k = i / H1_;
        u16 h = __half_as_ushort(__float2half_rn(W1[((size_t)se * D_ + k) * H1_ + n]));
        int c = k >> 6, kl = k & 63;
        ((u16*)(base + W1OFF + c * 23040))[n * 72 + kl] = h;
    }
    for (int i = tid0; i < H1_ * H2_; i += step) {          // W2: single fp16
        int n = i % H2_, k = i / H2_;
        u16 h = __half_as_ushort(__float2half_rn(W2[((size_t)se * H1_ + k) * H2_ + n]));
        int c = k >> 6, kl = k & 63;
        int str = (c == 2) ? 40 : 72;
        int coff = (c == 0) ? 0 : (c == 1 ? 18432 : 36864);
        ((u16*)(base + W2OFF + coff))[n * str + kl] = h;
    }
    for (int i = tid0; i < H2_ * H3_; i += step) {          // W3: bf16 hi/lo
        int n = i % H3_, k = i / H3_;
        u16 h, l; split2(W3[((size_t)se * H2_ + k) * H3_ + n], h, l);
        int c = k >> 6, kl = k & 63;
        u16* p = (u16*)(base + W3OFF + c * 27648);
        p[n * 72 + kl] = h;
        p[6912 + n * 72 + kl] = l;
    }
}

// ---------------- A image prep: gather + single fp16 (hi only) ----------------
__global__ void k_aprep(const float* __restrict__ aev) {
    int t = blockIdx.x, s = blockIdx.y, tid = threadIdx.x;
    int cnt = g_count[s];
    int ntl = (cnt + TM - 1) / TM;
    if (t >= ntl) return;
    int gt = g_tbase[s] + t;
    __shared__ int sidx[TM];
    if (tid < TM) {
        int p = t * TM + tid; if (p >= cnt) p = cnt - 1;
        sidx[tid] = g_idx[s * N_ + p];
    }
    __syncthreads();
    unsigned char* base = g_Aimg + (size_t)gt * ASE;
    for (int i = tid; i < TM * (D_ / 2); i += 256) {
        int m = i / (D_ / 2), k = (i % (D_ / 2)) * 2;
        float2 v = *(const float2*)(aev + (size_t)sidx[m] * D_ + k);
        u32 h = packh(v.x, v.y);
        int c = k >> 6, kl = k & 63;
        u16* ch = (u16*)(base + c * ACH);
        *(u32*)(ch + m * 72 + kl) = h;
    }
}

// ---------------- bf16 3-term fragment GEMM, term-major ----------------
template<int NT>
static __device__ __forceinline__ void chunk_mma3(
    float (*acc)[NT][4],
    const u16* Ah, const u16* Al, int astr,
    const u16* Wh, const u16* Wl, int wstr,
    int ksteps, int mbase, int nbase, int g, int q)
{
    for (int ks = 0; ks < ksteps; ks++) {
        const int k0 = ks * 16;
        u32 ah[2][4], al[2][4];
#pragma unroll
        for (int mt = 0; mt < 2; mt++) {
            const u16* ap = Ah + (mbase + mt * 16 + g) * astr + k0 + q * 2;
            const u16* aq = Al + (mbase + mt * 16 + g) * astr + k0 + q * 2;
            ah[mt][0] = *(const u32*)(ap);
            ah[mt][1] = *(const u32*)(ap + 8 * astr);
            ah[mt][2] = *(const u32*)(ap + 8);
            ah[mt][3] = *(const u32*)(ap + 8 * astr + 8);
            al[mt][0] = *(const u32*)(aq);
            al[mt][1] = *(const u32*)(aq + 8 * astr);
            al[mt][2] = *(const u32*)(aq + 8);
            al[mt][3] = *(const u32*)(aq + 8 * astr + 8);
        }
        u32 bh[NT][2];
#pragma unroll
        for (int nt = 0; nt < NT; nt++) {           // term 1: hi*hi
            const u16* wp = Wh + (nbase + nt * 8 + g) * wstr + k0 + q * 2;
            bh[nt][0] = *(const u32*)(wp);
            bh[nt][1] = *(const u32*)(wp + 8);
            mma_bf(acc[0][nt], ah[0][0], ah[0][1], ah[0][2], ah[0][3], bh[nt][0], bh[nt][1]);
            mma_bf(acc[1][nt], ah[1][0], ah[1][1], ah[1][2], ah[1][3], bh[nt][0], bh[nt][1]);
        }
#pragma unroll
        for (int nt = 0; nt < NT; nt++) {           // term 2: lo*hi
            mma_bf(acc[0][nt], al[0][0], al[0][1], al[0][2], al[0][3], bh[nt][0], bh[nt][1]);
            mma_bf(acc[1][nt], al[1][0], al[1][1], al[1][2], al[1][3], bh[nt][0], bh[nt][1]);
        }
#pragma unroll
        for (int nt = 0; nt < NT; nt++) {           // term 3: hi*lo
            const u16* wq = Wl + (nbase + nt * 8 + g) * wstr + k0 + q * 2;
            u32 bl0 = *(const u32*)(wq);
            u32 bl1 = *(const u32*)(wq + 8);
            mma_bf(acc[0][nt], ah[0][0], ah[0][1], ah[0][2], ah[0][3], bl0, bl1);
            mma_bf(acc[1][nt], ah[1][0], ah[1][1], ah[1][2], ah[1][3], bl0, bl1);
        }
    }
}

// ---------------- fp16 2-term fragment GEMM, term-major ----------------
template<int NT>
static __device__ __forceinline__ void chunk_mma2(
    float (*acc)[NT][4],
    const u16* Ah, const u16* Al, int astr,
    const u16* Wh, int wstr,
    int ksteps, int mbase, int nbase, int g, int q)
{
    for (int ks = 0; ks < ksteps; ks++) {
        const int k0 = ks * 16;
        u32 ah[2][4], al[2][4];
#pragma unroll
        for (int mt = 0; mt < 2; mt++) {
            const u16* ap = Ah + (mbase + mt * 16 + g) * astr + k0 + q * 2;
            const u16* aq = Al + (mbase + mt * 16 + g) * astr + k0 + q * 2;
            ah[mt][0] = *(const u32*)(ap);
            ah[mt][1] = *(const u32*)(ap + 8 * astr);
            ah[mt][2] = *(const u32*)(ap + 8);
            ah[mt][3] = *(const u32*)(ap + 8 * astr + 8);
            al[mt][0] = *(const u32*)(aq);
            al[mt][1] = *(const u32*)(aq + 8 * astr);
            al[mt][2] = *(const u32*)(aq + 8);
            al[mt][3] = *(const u32*)(aq + 8 * astr + 8);
        }
        u32 bh[NT][2];
#pragma unroll
        for (int nt = 0; nt < NT; nt++) {           // term 1: ah * w
            const u16* wp = Wh + (nbase + nt * 8 + g) * wstr + k0 + q * 2;
            bh[nt][0] = *(const u32*)(wp);
            bh[nt][1] = *(const u32*)(wp + 8);
            mma_fp(acc[0][nt], ah[0][0], ah[0][1], ah[0][2], ah[0][3], bh[nt][0], bh[nt][1]);
            mma_fp(acc[1][nt], ah[1][0], ah[1][1], ah[1][2], ah[1][3], bh[nt][0], bh[nt][1]);
        }
#pragma unroll
        for (int nt = 0; nt < NT; nt++) {           // term 2: al * w (w cached)
            mma_fp(acc[0][nt], al[0][0], al[0][1], al[0][2], al[0][3], bh[nt][0], bh[nt][1]);
            mma_fp(acc[1][nt], al[1][0], al[1][1], al[1][2], al[1][3], bh[nt][0], bh[nt][1]);
        }
    }
}

// ---------------- fp16 single-term fragment GEMM (L1) ----------------
template<int NT>
static __device__ __forceinline__ void chunk_mma1(
    float (*acc)[NT][4],
    const u16* Ah, int astr,
    const u16* Wh, int wstr,
    int ksteps, int mbase, int nbase, int g, int q)
{
    for (int ks = 0; ks < ksteps; ks++) {
        const int k0 = ks * 16;
        u32 ah[2][4];
#pragma unroll
        for (int mt = 0; mt < 2; mt++) {
            const u16* ap = Ah + (mbase + mt * 16 + g) * astr + k0 + q * 2;
            ah[mt][0] = *(const u32*)(ap);
            ah[mt][1] = *(const u32*)(ap + 8 * astr);
            ah[mt][2] = *(const u32*)(ap + 8);
            ah[mt][3] = *(const u32*)(ap + 8 * astr + 8);
        }
#pragma unroll
        for (int nt = 0; nt < NT; nt++) {
            const u16* wp = Wh + (nbase + nt * 8 + g) * wstr + k0 + q * 2;
            u32 b0 = *(const u32*)(wp);
            u32 b1 = *(const u32*)(wp + 8);
            mma_fp(acc[0][nt], ah[0][0], ah[0][1], ah[0][2], ah[0][3], b0, b1);
            mma_fp(acc[1][nt], ah[1][0], ah[1][1], ah[1][2], ah[1][3], b0, b1);
        }
    }
}

// ---------------- main kernel ----------------
// SMEM: L1 stages @0, @41472 (Ah 18432 | W1 23040 each; end 82944, dead before H1).
// H1 image 0..94208 (fp16 hi/lo). WB0 @98304, WB1 @135168. H2 image @ {0, 36864}
// (bf16 hi/lo). misc @172032.
#define SSTG  41472
#define WB0   98304
#define WB1   135168
#define MISCO 172032
#define SMEMB (MISCO + 4096)

__global__ void __launch_bounds__(THREADS, 1) k_main(
    const float* __restrict__ b1, const float* __restrict__ b2,
    const float* __restrict__ b3, const float* __restrict__ W4,
    const float* __restrict__ b4)
{
    extern __shared__ __align__(16) unsigned char sm[];
    const int s = blockIdx.y, t = blockIdx.x, z = blockIdx.z, tid = threadIdx.x;
    const int cnt = g_count[s];
    const int ntl = (cnt + TM - 1) / TM;
    if (t >= ntl) return;
    const int nvalid = min(TM, cnt - t * TM);
    const int gt = g_tbase[s] + t;
    const int lane = tid & 31, w = tid >> 5;
    const int wm = w & 3, wn = w >> 2, g = lane >> 2, q = lane & 3;
    const int mbase = wm * 32;
    const u32 sb = s2u(sm);
    float* b1s = (float*)(sm + MISCO);
    float* b2s = b1s + 160;
    float* b3s = b2s + 128;
    float* w4s = b3s + 96;
    float* part = w4s + 96;

    const unsigned char* Ab = g_Aimg + (size_t)gt * ASE;
    float blockSum = 0.f;

    const int h1off[3]  = {0, 36864, 73728};
    const int h1half[3] = {9216, 9216, 5120};
    const int h1str[3]  = {72, 72, 40};

    for (int ei = 0; ei < 2; ei++) {
        const int se = s * E_ + z * 2 + ei;
        const unsigned char* Wb = g_Wimg + (size_t)se * WSE;
        if (tid < 160) b1s[tid] = b1[se * H1_ + tid];
        if (tid < 128) b2s[tid] = b2[se * H2_ + tid];
        if (tid < 96) { b3s[tid] = b3[se * H3_ + tid]; w4s[tid] = W4[se * H3_ + tid]; }

        auto cpyW = [&](const unsigned char* src, int bytes, u32 dstoff) {
            for (int i = tid * 16; i < bytes; i += THREADS * 16) CPA16(sb + dstoff + i, src + i);
            CPCOMMIT();
        };

        // ========= Layer 1 (K=384, N=160): fp16 single-term, NT=5 per warp =========
        float acc1[2][5][4];
#pragma unroll
        for (int a = 0; a < 2; a++)
#pragma unroll
            for (int b = 0; b < 5; b++)
#pragma unroll
                for (int c = 0; c < 4; c++) acc1[a][b][c] = 0.f;

        auto cpyL1 = [&](int c, int bf) {
            u32 dst = sb + (bf ? SSTG : 0);
            const unsigned char* gA = Ab + c * ACH;            // hi half only
            for (int i = tid * 16; i < 18432; i += THREADS * 16) CPA16(dst + i, gA + i);
            const unsigned char* gW = Wb + W1OFF + c * 23040;
            for (int i = tid * 16; i < 23040; i += THREADS * 16) CPA16(dst + 18432 + i, gW + i);
            CPCOMMIT();
        };
        cpyL1(0, 0); cpyL1(1, 1);
        for (int kc = 0; kc < 6; kc++) {
            if (kc == 5) { CPWAIT(0); } else { CPWAIT(1); }
            __syncthreads();
            const unsigned char* st = sm + ((kc & 1) ? SSTG : 0);
            chunk_mma1<5>(acc1, (const u16*)st, 72,
                          (const u16*)(st + 18432), 72,
                          4, mbase, wn * 40, g, q);
            __syncthreads();
            if (kc < 4) cpyL1(kc + 2, kc & 1);
        }
        // prefetch W2 chunks 0,1 (fp16) — overlaps with L1 epilogue
        cpyW(Wb + W2OFF, 18432, WB0);
        cpyW(Wb + W2OFF + 18432, 18432, WB1);

        // epilogue -> H1 (fp16 hi/lo)
#pragma unroll
        for (int mt = 0; mt < 2; mt++)
#pragma unroll
            for (int nt = 0; nt < 5; nt++) {
                int n0 = wn * 40 + nt * 8 + q * 2;
                int cb = n0 >> 6, off = n0 & 63;
                u16* Hh = (u16*)(sm + h1off[cb]);
                u16* Hl = Hh + h1half[cb];
                int str = h1str[cb];
                int row = mbase + mt * 16 + g;
                u32 h, l;
                splitpairh(celu_f(acc1[mt][nt][0] + b1s[n0]),
                           celu_f(acc1[mt][nt][1] + b1s[n0 + 1]), h, l);
                *(u32*)(Hh + row * str + off) = h;
                *(u32*)(Hl + row * str + off) = l;
                splitpairh(celu_f(acc1[mt][nt][2] + b1s[n0]),
                           celu_f(acc1[mt][nt][3] + b1s[n0 + 1]), h, l);
                *(u32*)(Hh + (row + 8) * str + off) = h;
                *(u32*)(Hl + (row + 8) * str + off) = l;
            }
        __syncthreads();

        // ========= Layer 2 (K=160, N=128): fp16 2-term, NT=4 =========
        float acc2[2][4][4];
#pragma unroll
        for (int a = 0; a < 2; a++)
#pragma unroll
            for (int b = 0; b < 4; b++)
#pragma unroll
                for (int c = 0; c < 4; c++) acc2[a][b][c] = 0.f;

        for (int kc = 0; kc < 3; kc++) {
            if (kc == 2) { CPWAIT(0); } else { CPWAIT(1); }
            __syncthreads();
            const unsigned char* wb = sm + ((kc & 1) ? WB1 : WB0);
            int str = (kc == 2) ? 40 : 72;
            int ks = (kc == 2) ? 2 : 4;
            chunk_mma2<4>(acc2,
                          (const u16*)(sm + h1off[kc]), (const u16*)(sm + h1off[kc]) + h1half[kc], h1str[kc],
                          (const u16*)wb, str,
                          ks, mbase, wn * 32, g, q);
            __syncthreads();
            if (kc == 0) cpyW(Wb + W2OFF + 36864, 10240, WB0);
        }
        // prefetch W3 chunks 0,1 (bf16 hi/lo) — overlaps with L2 epilogue
        cpyW(Wb + W3OFF, 27648, WB0);
        cpyW(Wb + W3OFF + 27648, 27648, WB1);

        // epilogue -> H2 (bf16 hi/lo @ {0, 36864})
#pragma unroll
        for (int mt = 0; mt < 2; mt++)
#pragma unroll
            for (int nt = 0; nt < 4; nt++) {
                int n0 = wn * 32 + nt * 8 + q * 2;
                int cb = n0 >> 6, off = n0 & 63;
                u16* Hh = (u16*)(sm + cb * 36864);
                u16* Hl = Hh + 9216;
                int row = mbase + mt * 16 + g;
                u32 h, l;
                splitpair(celu_f(acc2[mt][nt][0] + b2s[n0]),
                          celu_f(acc2[mt][nt][1] + b2s[n0 + 1]), h, l);
                *(u32*)(Hh + row * 72 + off) = h;
                *(u32*)(Hl + row * 72 + off) = l;
                splitpair(celu_f(acc2[mt][nt][2] + b2s[n0]),
                          celu_f(acc2[mt][nt][3] + b2s[n0 + 1]), h, l);
                *(u32*)(Hh + (row + 8) * 72 + off) = h;
                *(u32*)(Hl + (row + 8) * 72 + off) = l;
            }
        __syncthreads();

        // ========= Layer 3 (K=128, N=96): bf16 3-term, NT=3 =========
        float acc3[2][3][4];
#pragma unroll
        for (int a = 0; a < 2; a++)
#pragma unroll
            for (int b = 0; b < 3; b++)
#pragma unroll
                for (int c = 0; c < 4; c++) acc3[a][b][c] = 0.f;

        for (int kc = 0; kc < 2; kc++) {
            if (kc == 1) { CPWAIT(0); } else { CPWAIT(1); }
            __syncthreads();
            const unsigned char* wb = sm + ((kc & 1) ? WB1 : WB0);
            chunk_mma3<3>(acc3,
                          (const u16*)(sm + kc * 36864), (const u16*)(sm + kc * 36864) + 9216, 72,
                          (const u16*)wb, (const u16*)wb + 6912, 72,
                          4, mbase, wn * 24, g, q);
            __syncthreads();
        }
        // ========= fused L3-epilogue + Layer 4 =========
        {
            float p00 = 0.f, p01 = 0.f, p10 = 0.f, p11 = 0.f;
#pragma unroll
            for (int nt = 0; nt < 3; nt++) {
                int n0 = wn * 24 + nt * 8 + q * 2;
                float w0 = w4s[n0], w1 = w4s[n0 + 1];
                float bb0 = b3s[n0], bb1 = b3s[n0 + 1];
                p00 += celu_f(acc3[0][nt][0] + bb0) * w0 + celu_f(acc3[0][nt][1] + bb1) * w1;
                p01 += celu_f(acc3[0][nt][2] + bb0) * w0 + celu_f(acc3[0][nt][3] + bb1) * w1;
                p10 += celu_f(acc3[1][nt][0] + bb0) * w0 + celu_f(acc3[1][nt][1] + bb1) * w1;
                p11 += celu_f(acc3[1][nt][2] + bb0) * w0 + celu_f(acc3[1][nt][3] + bb1) * w1;
            }
            p00 += __shfl_xor_sync(0xffffffffu, p00, 1); p00 += __shfl_xor_sync(0xffffffffu, p00, 2);
            p01 += __shfl_xor_sync(0xffffffffu, p01, 1); p01 += __shfl_xor_sync(0xffffffffu, p01, 2);
            p10 += __shfl_xor_sync(0xffffffffu, p10, 1); p10 += __shfl_xor_sync(0xffffffffu, p10, 2);
            p11 += __shfl_xor_sync(0xffffffffu, p11, 1); p11 += __shfl_xor_sync(0xffffffffu, p11, 2);
            if (q == 0) {
                part[wn * 128 + mbase + g]          = p00;
                part[wn * 128 + mbase + g + 8]      = p01;
                part[wn * 128 + mbase + 16 + g]     = p10;
                part[wn * 128 + mbase + 16 + g + 8] = p11;
            }
        }
        __syncthreads();
        if (tid < 128) {
            float en = part[tid] + part[128 + tid] + part[256 + tid] + part[384 + tid] + b4[se];
            part[tid] = (tid < nvalid) ? en : 0.f;
        }
        __syncthreads();
        if (tid < 32) {
            float v = part[tid] + part[tid + 32] + part[tid + 64] + part[tid + 96];
            for (int o = 16; o; o >>= 1) v += __shfl_down_sync(0xffffffffu, v, o);
            if (tid == 0) blockSum += v;
        }
        __syncthreads();
    }
    if (tid == 0) g_partial[(s * NTT + t) * 4 + z] = blockSum;
}

// ---------------- final reduction ----------------
__global__ void k_reduce(float* out) {
    __shared__ double sb[256];
    int tid = threadIdx.x;
    double s = 0.0;
    for (int i = tid; i < NPART; i += 256) s += (double)g_partial[i];
    sb[tid] = s;
    __syncthreads();
    for (int st = 128; st; st >>= 1) {
        if (tid < st) sb[tid] += sb[tid + st];
        __syncthreads();
    }
    if (tid == 0) out[0] = (float)(sb[0] * (1.0 / E_));
}

// ---------------- launch ----------------
extern "C" void kernel_launch(void* const* d_in, const int* in_sizes, int n_in,
                              void* d_out, int out_size)
{
    const void*  sp  = d_in[0];
    const float* aev = (const float*)d_in[1];
    const float* W1  = (const float*)d_in[2];
    const float* b1  = (const float*)d_in[3];
    const float* W2  = (const float*)d_in[4];
    const float* b2  = (const float*)d_in[5];
    const float* W3  = (const float*)d_in[6];
    const float* b3  = (const float*)d_in[7];
    const float* W4  = (const float*)d_in[8];
    const float* b4  = (const float*)d_in[9];

    cudaFuncSetAttribute(k_main, cudaFuncAttributeMaxDynamicSharedMemorySize, SMEMB);

    k_init<<<1, 256>>>((const ull*)sp);
    k_count<<<NB, 256>>>((const int*)sp);
    k_scan<<<1, 256>>>();
    k_scatter<<<NB, 256>>>((const int*)sp);
    dim3 gw(32, 8);
    k_wprep<<<gw, 256>>>(W1, W2, W3);
    dim3 ga(NTT, S_);
    k_aprep<<<ga, 256>>>(aev);
    dim3 gm(NTT, S_, 4);
    k_main<<<gm, THREADS, SMEMB>>>(b1, b2, b3, W4, b4);
    k_reduce<<<1, 256>>>((float*)d_out);
}

// round 13
// speedup vs baseline: 4.7968x; 1.0925x over previous
#include <cuda_runtime.h>
#include <cuda_bf16.h>
#include <cuda_fp16.h>
#include <cstdint>
#include <math.h>

#define S_  4
#define E_  8
#define D_  384
#define H1_ 160
#define H2_ 128
#define H3_ 96
#define N_  40000
#define TM  128
#define NTT 313
#define NB  ((N_ + 255) / 256)
#define NPART (NTT * S_ * 4)
#define MAXT 320
#define THREADS 512

typedef unsigned long long ull;
typedef uint32_t u32;
typedef unsigned short u16;

// ---------------- gmem image geometry ----------------
// A tiles: 6 chunks x (Ah [128][72] f16 18432 B | (lo half unused))
#define ACH   36864
#define ASE   (6 * ACH)
// Weights per (s,e):
//  W1 @0:      6 chunks x 23040, single fp16 [160][72]
//  W2 @276480: single fp16; c0@+0 18432 [128][72], c1@+18432 18432, c2@+36864 10240 [128][40]  (47104 total)
//  W3 @370688: bf16 hi/lo; 2 chunks x 27648 (hi 13824 | lo 13824), [96][72]  (55296 total)
#define W1OFF 0
#define W2OFF 276480
#define W3OFF 370688
#define WSE   425984

__device__ int   g_is64;
__device__ int   g_blockCnt[NB * S_];
__device__ int   g_blockOff[NB * S_];
__device__ int   g_count[S_];
__device__ int   g_tbase[S_];
__device__ int   g_idx[S_ * N_];
__device__ float g_partial[NPART];
__device__ __align__(1024) unsigned char g_Wimg[(size_t)32 * WSE];
__device__ __align__(1024) unsigned char g_Aimg[(size_t)MAXT * ASE];

// ---------------- helpers ----------------
static __device__ __forceinline__ float celu_f(float x) {
    return x > 0.f ? x : 0.1f * (__expf(x * 10.f) - 1.f);
}
static __device__ __forceinline__ u32 s2u(const void* p) {
    u32 a;
    asm("{ .reg .u64 t; cvta.to.shared.u64 t, %1; cvt.u32.u64 %0, t; }" : "=r"(a) : "l"(p));
    return a;
}
static __device__ __forceinline__ void split2(float v, u16& h, u16& l) {
    __nv_bfloat16 hb = __float2bfloat16(v);
    float hf = __bfloat162float(hb);
    __nv_bfloat16 lb = __float2bfloat16(v - hf);
    h = __bfloat16_as_ushort(hb);
    l = __bfloat16_as_ushort(lb);
}
// fp32 pair -> packed bf16x2 hi + residual bf16x2 lo
static __device__ __forceinline__ void splitpair(float x, float y, u32& h, u32& l) {
    u32 hh;
    asm("cvt.rn.bf16x2.f32 %0, %1, %2;" : "=r"(hh) : "f"(y), "f"(x));
    float xh = __uint_as_float(hh << 16);
    float yh = __uint_as_float(hh & 0xffff0000u);
    asm("cvt.rn.bf16x2.f32 %0, %1, %2;" : "=r"(l) : "f"(y - yh), "f"(x - xh));
    h = hh;
}
// fp32 pair -> packed f16x2 (hi only)
static __device__ __forceinline__ u32 packh(float x, float y) {
    u32 hh;
    asm("cvt.rn.f16x2.f32 %0, %1, %2;" : "=r"(hh) : "f"(y), "f"(x));
    return hh;
}
static __device__ __forceinline__ void mma_bf(float* c,
        u32 a0, u32 a1, u32 a2, u32 a3, u32 b0, u32 b1) {
    asm volatile(
        "mma.sync.aligned.m16n8k16.row.col.f32.bf16.bf16.f32 "
        "{%0,%1,%2,%3},{%4,%5,%6,%7},{%8,%9},{%0,%1,%2,%3};"
        : "+f"(c[0]), "+f"(c[1]), "+f"(c[2]), "+f"(c[3])
        : "r"(a0), "r"(a1), "r"(a2), "r"(a3), "r"(b0), "r"(b1));
}
static __device__ __forceinline__ void mma_fp(float* c,
        u32 a0, u32 a1, u32 a2, u32 a3, u32 b0, u32 b1) {
    asm volatile(
        "mma.sync.aligned.m16n8k16.row.col.f32.f16.f16.f32 "
        "{%0,%1,%2,%3},{%4,%5,%6,%7},{%8,%9},{%0,%1,%2,%3};"
        : "+f"(c[0]), "+f"(c[1]), "+f"(c[2]), "+f"(c[3])
        : "r"(a0), "r"(a1), "r"(a2), "r"(a3), "r"(b0), "r"(b1));
}
#define CPA16(d, s) asm volatile("cp.async.cg.shared.global [%0], [%1], 16;" :: "r"(d), "l"(s) : "memory")
#define CPCOMMIT()  asm volatile("cp.async.commit_group;" ::: "memory")
#define CPWAIT(n)   asm volatile("cp.async.wait_group %0;" :: "n"(n) : "memory")

// ---------------- bucketing ----------------
__global__ void k_init(const ull* spq) {
    int tid = threadIdx.x;
    for (int i = tid; i < NPART; i += 256) g_partial[i] = 0.f;
    if (tid < 32) {
        ull v = spq[tid];
        int hiNZ = ((v >> 32) != 0ull) ? 1 : 0;
        int any = __any_sync(0xffffffffu, hiNZ);
        if (tid == 0) g_is64 = any ? 0 : 1;
    }
}
__global__ void k_count(const int* sp) {
    int tid = threadIdx.x, b = blockIdx.x;
    int n = b * 256 + tid;
    int shift = g_is64;
    int spv = -1;
    if (n < N_) spv = sp[(size_t)n << shift];
    __shared__ int wc[8][4];
    if (tid < 32) wc[tid >> 2][tid & 3] = 0;
    __syncthreads();
    unsigned mm = __match_any_sync(0xffffffffu, spv);
    int lane = tid & 31, w = tid >> 5;
    if (spv >= 0 && lane == (__ffs(mm) - 1)) wc[w][spv] = __popc(mm);
    __syncthreads();
    if (tid < 4) {
        int s = 0;
        for (int ww = 0; ww < 8; ww++) s += wc[ww][tid];
        g_blockCnt[b * 4 + tid] = s;
    }
}
__global__ void k_scan() {
    __shared__ int c[NB * 4];
    __shared__ int o[NB * 4];
    int tid = threadIdx.x;
    for (int i = tid; i < NB * 4; i += 256) c[i] = g_blockCnt[i];
    __syncthreads();
    if (tid == 0) {
        int r0 = 0, r1 = 0, r2 = 0, r3 = 0;
        for (int b = 0; b < NB; b++) {
            o[b * 4 + 0] = r0; r0 += c[b * 4 + 0];
            o[b * 4 + 1] = r1; r1 += c[b * 4 + 1];
            o[b * 4 + 2] = r2; r2 += c[b * 4 + 2];
            o[b * 4 + 3] = r3; r3 += c[b * 4 + 3];
        }
        g_count[0] = r0; g_count[1] = r1; g_count[2] = r2; g_count[3] = r3;
        int tb = 0;
        g_tbase[0] = 0;  tb += (r0 + TM - 1) / TM;
        g_tbase[1] = tb; tb += (r1 + TM - 1) / TM;
        g_tbase[2] = tb; tb += (r2 + TM - 1) / TM;
        g_tbase[3] = tb;
    }
    __syncthreads();
    for (int i = tid; i < NB * 4; i += 256) g_blockOff[i] = o[i];
}
__global__ void k_scatter(const int* sp) {
    int tid = threadIdx.x, b = blockIdx.x;
    int n = b * 256 + tid;
    int shift = g_is64;
    int spv = -1;
    if (n < N_) spv = sp[(size_t)n << shift];
    __shared__ int wc[8][4];
    __shared__ int woff[8][4];
    if (tid < 32) wc[tid >> 2][tid & 3] = 0;
    __syncthreads();
    unsigned mm = __match_any_sync(0xffffffffu, spv);
    int lane = tid & 31, w = tid >> 5;
    int rank = __popc(mm & ((1u << lane) - 1u));
    if (spv >= 0 && lane == (__ffs(mm) - 1)) wc[w][spv] = __popc(mm);
    __syncthreads();
    if (tid < 4) {
        int run = g_blockOff[b * 4 + tid];
        for (int ww = 0; ww < 8; ww++) { woff[ww][tid] = run; run += wc[ww][tid]; }
    }
    __syncthreads();
    if (spv >= 0) g_idx[spv * N_ + woff[w][spv] + rank] = n;
}

// ---------------- weight image prep ----------------
__global__ void k_wprep(const float* __restrict__ W1, const float* __restrict__ W2,
                        const float* __restrict__ W3) {
    int se = blockIdx.x;
    int tid0 = threadIdx.x + blockIdx.y * 256;
    const int step = 256 * 8;
    unsigned char* base = g_Wimg + (size_t)se * WSE;
    for (int i = tid0; i < D_ * H1_; i += step) {           // W1: single fp16
        int n = i % H1_, k = i / H1_;
        u16 h = __half_as_ushort(__float2half_rn(W1[((size_t)se * D_ + k) * H1_ + n]));
        int c = k >> 6, kl = k & 63;
        ((u16*)(base + W1OFF + c * 23040))[n * 72 + kl] = h;
    }
    for (int i = tid0; i < H1_ * H2_; i += step) {          // W2: single fp16
        int n = i % H2_, k = i / H2_;
        u16 h = __half_as_ushort(__float2half_rn(W2[((size_t)se * H1_ + k) * H2_ + n]));
        int c = k >> 6, kl = k & 63;
        int str = (c == 2) ? 40 : 72;
        int coff = (c == 0) ? 0 : (c == 1 ? 18432 : 36864);
        ((u16*)(base + W2OFF + coff))[n * str + kl] = h;
    }
    for (int i = tid0; i < H2_ * H3_; i += step) {          // W3: bf16 hi/lo
        int n = i % H3_, k = i / H3_;
        u16 h, l; split2(W3[((size_t)se * H2_ + k) * H3_ + n], h, l);
        int c = k >> 6, kl = k & 63;
        u16* p = (u16*)(base + W3OFF + c * 27648);
        p[n * 72 + kl] = h;
        p[6912 + n * 72 + kl] = l;
    }
}

// ---------------- A image prep: gather + single fp16 (hi only) ----------------
__global__ void k_aprep(const float* __restrict__ aev) {
    int t = blockIdx.x, s = blockIdx.y, tid = threadIdx.x;
    int cnt = g_count[s];
    int ntl = (cnt + TM - 1) / TM;
    if (t >= ntl) return;
    int gt = g_tbase[s] + t;
    __shared__ int sidx[TM];
    if (tid < TM) {
        int p = t * TM + tid; if (p >= cnt) p = cnt - 1;
        sidx[tid] = g_idx[s * N_ + p];
    }
    __syncthreads();
    unsigned char* base = g_Aimg + (size_t)gt * ASE;
    for (int i = tid; i < TM * (D_ / 2); i += 256) {
        int m = i / (D_ / 2), k = (i % (D_ / 2)) * 2;
        float2 v = *(const float2*)(aev + (size_t)sidx[m] * D_ + k);
        u32 h = packh(v.x, v.y);
        int c = k >> 6, kl = k & 63;
        u16* ch = (u16*)(base + c * ACH);
        *(u32*)(ch + m * 72 + kl) = h;
    }
}

// ---------------- bf16 3-term fragment GEMM, term-major (L3) ----------------
template<int NT>
static __device__ __forceinline__ void chunk_mma3(
    float (*acc)[NT][4],
    const u16* Ah, const u16* Al, int astr,
    const u16* Wh, const u16* Wl, int wstr,
    int ksteps, int mbase, int nbase, int g, int q)
{
    for (int ks = 0; ks < ksteps; ks++) {
        const int k0 = ks * 16;
        u32 ah[2][4], al[2][4];
#pragma unroll
        for (int mt = 0; mt < 2; mt++) {
            const u16* ap = Ah + (mbase + mt * 16 + g) * astr + k0 + q * 2;
            const u16* aq = Al + (mbase + mt * 16 + g) * astr + k0 + q * 2;
            ah[mt][0] = *(const u32*)(ap);
            ah[mt][1] = *(const u32*)(ap + 8 * astr);
            ah[mt][2] = *(const u32*)(ap + 8);
            ah[mt][3] = *(const u32*)(ap + 8 * astr + 8);
            al[mt][0] = *(const u32*)(aq);
            al[mt][1] = *(const u32*)(aq + 8 * astr);
            al[mt][2] = *(const u32*)(aq + 8);
            al[mt][3] = *(const u32*)(aq + 8 * astr + 8);
        }
        u32 bh[NT][2];
#pragma unroll
        for (int nt = 0; nt < NT; nt++) {           // term 1: hi*hi
            const u16* wp = Wh + (nbase + nt * 8 + g) * wstr + k0 + q * 2;
            bh[nt][0] = *(const u32*)(wp);
            bh[nt][1] = *(const u32*)(wp + 8);
            mma_bf(acc[0][nt], ah[0][0], ah[0][1], ah[0][2], ah[0][3], bh[nt][0], bh[nt][1]);
            mma_bf(acc[1][nt], ah[1][0], ah[1][1], ah[1][2], ah[1][3], bh[nt][0], bh[nt][1]);
        }
#pragma unroll
        for (int nt = 0; nt < NT; nt++) {           // term 2: lo*hi
            mma_bf(acc[0][nt], al[0][0], al[0][1], al[0][2], al[0][3], bh[nt][0], bh[nt][1]);
            mma_bf(acc[1][nt], al[1][0], al[1][1], al[1][2], al[1][3], bh[nt][0], bh[nt][1]);
        }
#pragma unroll
        for (int nt = 0; nt < NT; nt++) {           // term 3: hi*lo
            const u16* wq = Wl + (nbase + nt * 8 + g) * wstr + k0 + q * 2;
            u32 bl0 = *(const u32*)(wq);
            u32 bl1 = *(const u32*)(wq + 8);
            mma_bf(acc[0][nt], ah[0][0], ah[0][1], ah[0][2], ah[0][3], bl0, bl1);
            mma_bf(acc[1][nt], ah[1][0], ah[1][1], ah[1][2], ah[1][3], bl0, bl1);
        }
    }
}

// ---------------- fp16 single-term fragment GEMM (L1, L2) ----------------
template<int NT>
static __device__ __forceinline__ void chunk_mma1(
    float (*acc)[NT][4],
    const u16* Ah, int astr,
    const u16* Wh, int wstr,
    int ksteps, int mbase, int nbase, int g, int q)
{
    for (int ks = 0; ks < ksteps; ks++) {
        const int k0 = ks * 16;
        u32 ah[2][4];
#pragma unroll
        for (int mt = 0; mt < 2; mt++) {
            const u16* ap = Ah + (mbase + mt * 16 + g) * astr + k0 + q * 2;
            ah[mt][0] = *(const u32*)(ap);
            ah[mt][1] = *(const u32*)(ap + 8 * astr);
            ah[mt][2] = *(const u32*)(ap + 8);
            ah[mt][3] = *(const u32*)(ap + 8 * astr + 8);
        }
#pragma unroll
        for (int nt = 0; nt < NT; nt++) {
            const u16* wp = Wh + (nbase + nt * 8 + g) * wstr + k0 + q * 2;
            u32 b0 = *(const u32*)(wp);
            u32 b1 = *(const u32*)(wp + 8);
            mma_fp(acc[0][nt], ah[0][0], ah[0][1], ah[0][2], ah[0][3], b0, b1);
            mma_fp(acc[1][nt], ah[1][0], ah[1][1], ah[1][2], ah[1][3], b0, b1);
        }
    }
}

// ---------------- main kernel ----------------
// SMEM: L1 stages @0, @41472 (Ah 18432 | W1 23040 each; end 82944, dead before H1).
// H1 image (fp16 hi only): chunk0 @0 [128][72], chunk1 @36864 [128][72], chunk2 @73728 [128][40].
// WB @98304 (73728 B region: W2 batch 47104 or W3 batch 55296).
// H2 image @ {0, 36864} (bf16 hi/lo). misc @172032.
#define SSTG  41472
#define WB    98304
#define MISCO 172032
#define SMEMB (MISCO + 4096)

__global__ void __launch_bounds__(THREADS, 1) k_main(
    const float* __restrict__ b1, const float* __restrict__ b2,
    const float* __restrict__ b3, const float* __restrict__ W4,
    const float* __restrict__ b4)
{
    extern __shared__ __align__(16) unsigned char sm[];
    const int s = blockIdx.y, t = blockIdx.x, z = blockIdx.z, tid = threadIdx.x;
    const int cnt = g_count[s];
    const int ntl = (cnt + TM - 1) / TM;
    if (t >= ntl) return;
    const int nvalid = min(TM, cnt - t * TM);
    const int gt = g_tbase[s] + t;
    const int lane = tid & 31, w = tid >> 5;
    const int wm = w & 3, wn = w >> 2, g = lane >> 2, q = lane & 3;
    const int mbase = wm * 32;
    const u32 sb = s2u(sm);
    float* b1s = (float*)(sm + MISCO);
    float* b2s = b1s + 160;
    float* b3s = b2s + 128;
    float* w4s = b3s + 96;
    float* part = w4s + 96;

    const unsigned char* Ab = g_Aimg + (size_t)gt * ASE;
    float blockSum = 0.f;

    const int h1off[3] = {0, 36864, 73728};
    const int h1str[3] = {72, 72, 40};
    const int w2off[3] = {0, 18432, 36864};
    const int w2str[3] = {72, 72, 40};
    const int w2ks[3]  = {4, 4, 2};

    for (int ei = 0; ei < 2; ei++) {
        const int se = s * E_ + z * 2 + ei;
        const unsigned char* Wb = g_Wimg + (size_t)se * WSE;
        if (tid < 160) b1s[tid] = b1[se * H1_ + tid];
        if (tid < 128) b2s[tid] = b2[se * H2_ + tid];
        if (tid < 96) { b3s[tid] = b3[se * H3_ + tid]; w4s[tid] = W4[se * H3_ + tid]; }

        auto cpyW = [&](const unsigned char* src, int bytes, u32 dstoff) {
            for (int i = tid * 16; i < bytes; i += THREADS * 16) CPA16(sb + dstoff + i, src + i);
            CPCOMMIT();
        };

        // ========= Layer 1 (K=384, N=160): fp16 single-term, NT=5 per warp =========
        float acc1[2][5][4];
#pragma unroll
        for (int a = 0; a < 2; a++)
#pragma unroll
            for (int b = 0; b < 5; b++)
#pragma unroll
                for (int c = 0; c < 4; c++) acc1[a][b][c] = 0.f;

        auto cpyL1 = [&](int c, int bf) {
            u32 dst = sb + (bf ? SSTG : 0);
            const unsigned char* gA = Ab + c * ACH;            // hi half only
            for (int i = tid * 16; i < 18432; i += THREADS * 16) CPA16(dst + i, gA + i);
            const unsigned char* gW = Wb + W1OFF + c * 23040;
            for (int i = tid * 16; i < 23040; i += THREADS * 16) CPA16(dst + 18432 + i, gW + i);
            CPCOMMIT();
        };
        cpyL1(0, 0); cpyL1(1, 1);
        for (int kc = 0; kc < 6; kc++) {
            if (kc == 5) { CPWAIT(0); } else { CPWAIT(1); }
            __syncthreads();
            const unsigned char* st = sm + ((kc & 1) ? SSTG : 0);
            chunk_mma1<5>(acc1, (const u16*)st, 72,
                          (const u16*)(st + 18432), 72,
                          4, mbase, wn * 40, g, q);
            __syncthreads();
            if (kc < 4) cpyL1(kc + 2, kc & 1);
        }
        // single batch copy of ALL W2 chunks (47104 B) — overlaps with L1 epilogue
        cpyW(Wb + W2OFF, 47104, WB);

        // epilogue -> H1 (fp16 hi only)
#pragma unroll
        for (int mt = 0; mt < 2; mt++)
#pragma unroll
            for (int nt = 0; nt < 5; nt++) {
                int n0 = wn * 40 + nt * 8 + q * 2;
                int cb = n0 >> 6, off = n0 & 63;
                u16* Hh = (u16*)(sm + h1off[cb]);
                int str = h1str[cb];
                int row = mbase + mt * 16 + g;
                *(u32*)(Hh + row * str + off) =
                    packh(celu_f(acc1[mt][nt][0] + b1s[n0]),
                          celu_f(acc1[mt][nt][1] + b1s[n0 + 1]));
                *(u32*)(Hh + (row + 8) * str + off) =
                    packh(celu_f(acc1[mt][nt][2] + b1s[n0]),
                          celu_f(acc1[mt][nt][3] + b1s[n0 + 1]));
            }
        CPWAIT(0);
        __syncthreads();

        // ========= Layer 2 (K=160, N=128): fp16 single-term, NT=4 =========
        float acc2[2][4][4];
#pragma unroll
        for (int a = 0; a < 2; a++)
#pragma unroll
            for (int b = 0; b < 4; b++)
#pragma unroll
                for (int c = 0; c < 4; c++) acc2[a][b][c] = 0.f;

        for (int kc = 0; kc < 3; kc++) {
            chunk_mma1<4>(acc2,
                          (const u16*)(sm + h1off[kc]), h1str[kc],
                          (const u16*)(sm + WB + w2off[kc]), w2str[kc],
                          w2ks[kc], mbase, wn * 32, g, q);
        }
        __syncthreads();
        // single batch copy of ALL W3 chunks (55296 B) — overlaps with L2 epilogue
        cpyW(Wb + W3OFF, 55296, WB);

        // epilogue -> H2 (bf16 hi/lo @ {0, 36864})
#pragma unroll
        for (int mt = 0; mt < 2; mt++)
#pragma unroll
            for (int nt = 0; nt < 4; nt++) {
                int n0 = wn * 32 + nt * 8 + q * 2;
                int cb = n0 >> 6, off = n0 & 63;
                u16* Hh = (u16*)(sm + cb * 36864);
                u16* Hl = Hh + 9216;
                int row = mbase + mt * 16 + g;
                u32 h, l;
                splitpair(celu_f(acc2[mt][nt][0] + b2s[n0]),
                          celu_f(acc2[mt][nt][1] + b2s[n0 + 1]), h, l);
                *(u32*)(Hh + row * 72 + off) = h;
                *(u32*)(Hl + row * 72 + off) = l;
                splitpair(celu_f(acc2[mt][nt][2] + b2s[n0]),
                          celu_f(acc2[mt][nt][3] + b2s[n0 + 1]), h, l);
                *(u32*)(Hh + (row + 8) * 72 + off) = h;
                *(u32*)(Hl + (row + 8) * 72 + off) = l;
            }
        CPWAIT(0);
        __syncthreads();

        // ========= Layer 3 (K=128, N=96): bf16 3-term, NT=3 =========
        float acc3[2][3][4];
#pragma unroll
        for (int a = 0; a < 2; a++)
#pragma unroll
            for (int b = 0; b < 3; b++)
#pragma unroll
                for (int c = 0; c < 4; c++) acc3[a][b][c] = 0.f;

        for (int kc = 0; kc < 2; kc++) {
            const unsigned char* wb = sm + WB + kc * 27648;
            chunk_mma3<3>(acc3,
                          (const u16*)(sm + kc * 36864), (const u16*)(sm + kc * 36864) + 9216, 72,
                          (const u16*)wb, (const u16*)wb + 6912, 72,
                          4, mbase, wn * 24, g, q);
        }
        // ========= fused L3-epilogue + Layer 4 =========
        {
            float p00 = 0.f, p01 = 0.f, p10 = 0.f, p11 = 0.f;
#pragma unroll
            for (int nt = 0; nt < 3; nt++) {
                int n0 = wn * 24 + nt * 8 + q * 2;
                float w0 = w4s[n0], w1 = w4s[n0 + 1];
                float bb0 = b3s[n0], bb1 = b3s[n0 + 1];
                p00 += celu_f(acc3[0][nt][0] + bb0) * w0 + celu_f(acc3[0][nt][1] + bb1) * w1;
                p01 += celu_f(acc3[0][nt][2] + bb0) * w0 + celu_f(acc3[0][nt][3] + bb1) * w1;
                p10 += celu_f(acc3[1][nt][0] + bb0) * w0 + celu_f(acc3[1][nt][1] + bb1) * w1;
                p11 += celu_f(acc3[1][nt][2] + bb0) * w0 + celu_f(acc3[1][nt][3] + bb1) * w1;
            }
            p00 += __shfl_xor_sync(0xffffffffu, p00, 1); p00 += __shfl_xor_sync(0xffffffffu, p00, 2);
            p01 += __shfl_xor_sync(0xffffffffu, p01, 1); p01 += __shfl_xor_sync(0xffffffffu, p01, 2);
            p10 += __shfl_xor_sync(0xffffffffu, p10, 1); p10 += __shfl_xor_sync(0xffffffffu, p10, 2);
            p11 += __shfl_xor_sync(0xffffffffu, p11, 1); p11 += __shfl_xor_sync(0xffffffffu, p11, 2);
            if (q == 0) {
                part[wn * 128 + mbase + g]          = p00;
                part[wn * 128 + mbase + g + 8]      = p01;
                part[wn * 128 + mbase + 16 + g]     = p10;
                part[wn * 128 + mbase + 16 + g + 8] = p11;
            }
        }
        __syncthreads();
        if (tid < 128) {
            float en = part[tid] + part[128 + tid] + part[256 + tid] + part[384 + tid] + b4[se];
            part[tid] = (tid < nvalid) ? en : 0.f;
        }
        __syncthreads();
        if (tid < 32) {
            float v = part[tid] + part[tid + 32] + part[tid + 64] + part[tid + 96];
            for (int o = 16; o; o >>= 1) v += __shfl_down_sync(0xffffffffu, v, o);
            if (tid == 0) blockSum += v;
        }
        __syncthreads();
    }
    if (tid == 0) g_partial[(s * NTT + t) * 4 + z] = blockSum;
}

// ---------------- final reduction ----------------
__global__ void k_reduce(float* out) {
    __shared__ double sb[256];
    int tid = threadIdx.x;
    double s = 0.0;
    for (int i = tid; i < NPART; i += 256) s += (double)g_partial[i];
    sb[tid] = s;
    __syncthreads();
    for (int st = 128; st; st >>= 1) {
        if (tid < st) sb[tid] += sb[tid + st];
        __syncthreads();
    }
    if (tid == 0) out[0] = (float)(sb[0] * (1.0 / E_));
}

// ---------------- launch ----------------
extern "C" void kernel_launch(void* const* d_in, const int* in_sizes, int n_in,
                              void* d_out, int out_size)
{
    const void*  sp  = d_in[0];
    const float* aev = (const float*)d_in[1];
    const float* W1  = (const float*)d_in[2];
    const float* b1  = (const float*)d_in[3];
    const float* W2  = (const float*)d_in[4];
    const float* b2  = (const float*)d_in[5];
    const float* W3  = (const float*)d_in[6];
    const float* b3  = (const float*)d_in[7];
    const float* W4  = (const float*)d_in[8];
    const float* b4  = (const float*)d_in[9];

    cudaFuncSetAttribute(k_main, cudaFuncAttributeMaxDynamicSharedMemorySize, SMEMB);

    k_init<<<1, 256>>>((const ull*)sp);
    k_count<<<NB, 256>>>((const int*)sp);
    k_scan<<<1, 256>>>();
    k_scatter<<<NB, 256>>>((const int*)sp);
    dim3 gw(32, 8);
    k_wprep<<<gw, 256>>>(W1, W2, W3);
    dim3 ga(NTT, S_);
    k_aprep<<<ga, 256>>>(aev);
    dim3 gm(NTT, S_, 4);
    k_main<<<gm, THREADS, SMEMB>>>(b1, b2, b3, W4, b4);
    k_reduce<<<1, 256>>>((float*)d_out);
}

// round 14
// speedup vs baseline: 5.0219x; 1.0469x over previous
#include <cuda_runtime.h>
#include <cuda_fp16.h>
#include <cstdint>
#include <math.h>

#define S_  4
#define E_  8
#define D_  384
#define H1_ 160
#define H2_ 128
#define H3_ 96
#define N_  40000
#define TM  128
#define NTT 313
#define NB  ((N_ + 255) / 256)
#define NPART (NTT * S_ * 4)
#define MAXT 320
#define THREADS 512

typedef unsigned long long ull;
typedef uint32_t u32;
typedef unsigned short u16;

// ---------------- gmem image geometry ----------------
// A tiles: 6 chunks x (Ah [128][72] f16 18432 B | (lo half unused))
#define ACH   36864
#define ASE   (6 * ACH)
// Weights per (s,e):
//  W1 @0:      6 chunks x 23040, single fp16 [160][72]
//  W2 @276480: single fp16; c0@+0 18432 [128][72], c1@+18432 18432, c2@+36864 10240 [128][40]  (47104 total)
//  W3 @370688: fp16 hi/lo; 2 chunks x 27648 (hi 13824 | lo 13824), [96][72]  (55296 total)
#define W1OFF 0
#define W2OFF 276480
#define W3OFF 370688
#define WSE   425984

__device__ int   g_is64;
__device__ int   g_blockCnt[NB * S_];
__device__ int   g_blockOff[NB * S_];
__device__ int   g_count[S_];
__device__ int   g_tbase[S_];
__device__ int   g_idx[S_ * N_];
__device__ float g_partial[NPART];
__device__ __align__(1024) unsigned char g_Wimg[(size_t)32 * WSE];
__device__ __align__(1024) unsigned char g_Aimg[(size_t)MAXT * ASE];

// ---------------- helpers ----------------
static __device__ __forceinline__ float celu_f(float x) {
    return x > 0.f ? x : 0.1f * (__expf(x * 10.f) - 1.f);
}
static __device__ __forceinline__ u32 s2u(const void* p) {
    u32 a;
    asm("{ .reg .u64 t; cvta.to.shared.u64 t, %1; cvt.u32.u64 %0, t; }" : "=r"(a) : "l"(p));
    return a;
}
// fp16 hi/lo split of a scalar
static __device__ __forceinline__ void split2h(float v, u16& h, u16& l) {
    __half hb = __float2half_rn(v);
    float hf = __half2float(hb);
    __half lb = __float2half_rn(v - hf);
    h = __half_as_ushort(hb);
    l = __half_as_ushort(lb);
}
// fp32 pair -> packed f16x2 (hi only)
static __device__ __forceinline__ u32 packh(float x, float y) {
    u32 hh;
    asm("cvt.rn.f16x2.f32 %0, %1, %2;" : "=r"(hh) : "f"(y), "f"(x));
    return hh;
}
static __device__ __forceinline__ void mma_fp(float* c,
        u32 a0, u32 a1, u32 a2, u32 a3, u32 b0, u32 b1) {
    asm volatile(
        "mma.sync.aligned.m16n8k16.row.col.f32.f16.f16.f32 "
        "{%0,%1,%2,%3},{%4,%5,%6,%7},{%8,%9},{%0,%1,%2,%3};"
        : "+f"(c[0]), "+f"(c[1]), "+f"(c[2]), "+f"(c[3])
        : "r"(a0), "r"(a1), "r"(a2), "r"(a3), "r"(b0), "r"(b1));
}
#define CPA16(d, s) asm volatile("cp.async.cg.shared.global [%0], [%1], 16;" :: "r"(d), "l"(s) : "memory")
#define CPCOMMIT()  asm volatile("cp.async.commit_group;" ::: "memory")
#define CPWAIT(n)   asm volatile("cp.async.wait_group %0;" :: "n"(n) : "memory")

// ---------------- bucketing ----------------
__global__ void k_init(const ull* spq) {
    int tid = threadIdx.x;
    for (int i = tid; i < NPART; i += 256) g_partial[i] = 0.f;
    if (tid < 32) {
        ull v = spq[tid];
        int hiNZ = ((v >> 32) != 0ull) ? 1 : 0;
        int any = __any_sync(0xffffffffu, hiNZ);
        if (tid == 0) g_is64 = any ? 0 : 1;
    }
}
__global__ void k_count(const int* sp) {
    int tid = threadIdx.x, b = blockIdx.x;
    int n = b * 256 + tid;
    int shift = g_is64;
    int spv = -1;
    if (n < N_) spv = sp[(size_t)n << shift];
    __shared__ int wc[8][4];
    if (tid < 32) wc[tid >> 2][tid & 3] = 0;
    __syncthreads();
    unsigned mm = __match_any_sync(0xffffffffu, spv);
    int lane = tid & 31, w = tid >> 5;
    if (spv >= 0 && lane == (__ffs(mm) - 1)) wc[w][spv] = __popc(mm);
    __syncthreads();
    if (tid < 4) {
        int s = 0;
        for (int ww = 0; ww < 8; ww++) s += wc[ww][tid];
        g_blockCnt[b * 4 + tid] = s;
    }
}
__global__ void k_scan() {
    __shared__ int c[NB * 4];
    __shared__ int o[NB * 4];
    int tid = threadIdx.x;
    for (int i = tid; i < NB * 4; i += 256) c[i] = g_blockCnt[i];
    __syncthreads();
    if (tid == 0) {
        int r0 = 0, r1 = 0, r2 = 0, r3 = 0;
        for (int b = 0; b < NB; b++) {
            o[b * 4 + 0] = r0; r0 += c[b * 4 + 0];
            o[b * 4 + 1] = r1; r1 += c[b * 4 + 1];
            o[b * 4 + 2] = r2; r2 += c[b * 4 + 2];
            o[b * 4 + 3] = r3; r3 += c[b * 4 + 3];
        }
        g_count[0] = r0; g_count[1] = r1; g_count[2] = r2; g_count[3] = r3;
        int tb = 0;
        g_tbase[0] = 0;  tb += (r0 + TM - 1) / TM;
        g_tbase[1] = tb; tb += (r1 + TM - 1) / TM;
        g_tbase[2] = tb; tb += (r2 + TM - 1) / TM;
        g_tbase[3] = tb;
    }
    __syncthreads();
    for (int i = tid; i < NB * 4; i += 256) g_blockOff[i] = o[i];
}
__global__ void k_scatter(const int* sp) {
    int tid = threadIdx.x, b = blockIdx.x;
    int n = b * 256 + tid;
    int shift = g_is64;
    int spv = -1;
    if (n < N_) spv = sp[(size_t)n << shift];
    __shared__ int wc[8][4];
    __shared__ int woff[8][4];
    if (tid < 32) wc[tid >> 2][tid & 3] = 0;
    __syncthreads();
    unsigned mm = __match_any_sync(0xffffffffu, spv);
    int lane = tid & 31, w = tid >> 5;
    int rank = __popc(mm & ((1u << lane) - 1u));
    if (spv >= 0 && lane == (__ffs(mm) - 1)) wc[w][spv] = __popc(mm);
    __syncthreads();
    if (tid < 4) {
        int run = g_blockOff[b * 4 + tid];
        for (int ww = 0; ww < 8; ww++) { woff[ww][tid] = run; run += wc[ww][tid]; }
    }
    __syncthreads();
    if (spv >= 0) g_idx[spv * N_ + woff[w][spv] + rank] = n;
}

// ---------------- weight image prep ----------------
__global__ void k_wprep(const float* __restrict__ W1, const float* __restrict__ W2,
                        const float* __restrict__ W3) {
    int se = blockIdx.x;
    int tid0 = threadIdx.x + blockIdx.y * 256;
    const int step = 256 * 8;
    unsigned char* base = g_Wimg + (size_t)se * WSE;
    for (int i = tid0; i < D_ * H1_; i += step) {           // W1: single fp16
        int n = i % H1_, k = i / H1_;
        u16 h = __half_as_ushort(__float2half_rn(W1[((size_t)se * D_ + k) * H1_ + n]));
        int c = k >> 6, kl = k & 63;
        ((u16*)(base + W1OFF + c * 23040))[n * 72 + kl] = h;
    }
    for (int i = tid0; i < H1_ * H2_; i += step) {          // W2: single fp16
        int n = i % H2_, k = i / H2_;
        u16 h = __half_as_ushort(__float2half_rn(W2[((size_t)se * H1_ + k) * H2_ + n]));
        int c = k >> 6, kl = k & 63;
        int str = (c == 2) ? 40 : 72;
        int coff = (c == 0) ? 0 : (c == 1 ? 18432 : 36864);
        ((u16*)(base + W2OFF + coff))[n * str + kl] = h;
    }
    for (int i = tid0; i < H2_ * H3_; i += step) {          // W3: fp16 hi/lo
        int n = i % H3_, k = i / H3_;
        u16 h, l; split2h(W3[((size_t)se * H2_ + k) * H3_ + n], h, l);
        int c = k >> 6, kl = k & 63;
        u16* p = (u16*)(base + W3OFF + c * 27648);
        p[n * 72 + kl] = h;
        p[6912 + n * 72 + kl] = l;
    }
}

// ---------------- A image prep: gather + single fp16 (hi only) ----------------
__global__ void k_aprep(const float* __restrict__ aev) {
    int t = blockIdx.x, s = blockIdx.y, tid = threadIdx.x;
    int cnt = g_count[s];
    int ntl = (cnt + TM - 1) / TM;
    if (t >= ntl) return;
    int gt = g_tbase[s] + t;
    __shared__ int sidx[TM];
    if (tid < TM) {
        int p = t * TM + tid; if (p >= cnt) p = cnt - 1;
        sidx[tid] = g_idx[s * N_ + p];
    }
    __syncthreads();
    unsigned char* base = g_Aimg + (size_t)gt * ASE;
    for (int i = tid; i < TM * (D_ / 2); i += 256) {
        int m = i / (D_ / 2), k = (i % (D_ / 2)) * 2;
        float2 v = *(const float2*)(aev + (size_t)sidx[m] * D_ + k);
        u32 h = packh(v.x, v.y);
        int c = k >> 6, kl = k & 63;
        u16* ch = (u16*)(base + c * ACH);
        *(u32*)(ch + m * 72 + kl) = h;
    }
}

// ---------------- fp16 single-term fragment GEMM (L1, L2) ----------------
template<int NT>
static __device__ __forceinline__ void chunk_mma1(
    float (*acc)[NT][4],
    const u16* Ah, int astr,
    const u16* Wh, int wstr,
    int ksteps, int mbase, int nbase, int g, int q)
{
    for (int ks = 0; ks < ksteps; ks++) {
        const int k0 = ks * 16;
        u32 ah[2][4];
#pragma unroll
        for (int mt = 0; mt < 2; mt++) {
            const u16* ap = Ah + (mbase + mt * 16 + g) * astr + k0 + q * 2;
            ah[mt][0] = *(const u32*)(ap);
            ah[mt][1] = *(const u32*)(ap + 8 * astr);
            ah[mt][2] = *(const u32*)(ap + 8);
            ah[mt][3] = *(const u32*)(ap + 8 * astr + 8);
        }
#pragma unroll
        for (int nt = 0; nt < NT; nt++) {
            const u16* wp = Wh + (nbase + nt * 8 + g) * wstr + k0 + q * 2;
            u32 b0 = *(const u32*)(wp);
            u32 b1 = *(const u32*)(wp + 8);
            mma_fp(acc[0][nt], ah[0][0], ah[0][1], ah[0][2], ah[0][3], b0, b1);
            mma_fp(acc[1][nt], ah[1][0], ah[1][1], ah[1][2], ah[1][3], b0, b1);
        }
    }
}

// ---------------- fp16 2-term-W fragment GEMM (L3): ah*wh + ah*wl ----------------
template<int NT>
static __device__ __forceinline__ void chunk_mma_w2(
    float (*acc)[NT][4],
    const u16* Ah, int astr,
    const u16* Wh, const u16* Wl, int wstr,
    int ksteps, int mbase, int nbase, int g, int q)
{
    for (int ks = 0; ks < ksteps; ks++) {
        const int k0 = ks * 16;
        u32 ah[2][4];
#pragma unroll
        for (int mt = 0; mt < 2; mt++) {
            const u16* ap = Ah + (mbase + mt * 16 + g) * astr + k0 + q * 2;
            ah[mt][0] = *(const u32*)(ap);
            ah[mt][1] = *(const u32*)(ap + 8 * astr);
            ah[mt][2] = *(const u32*)(ap + 8);
            ah[mt][3] = *(const u32*)(ap + 8 * astr + 8);
        }
#pragma unroll
        for (int nt = 0; nt < NT; nt++) {           // term 1: ah * wh
            const u16* wp = Wh + (nbase + nt * 8 + g) * wstr + k0 + q * 2;
            u32 b0 = *(const u32*)(wp);
            u32 b1 = *(const u32*)(wp + 8);
            mma_fp(acc[0][nt], ah[0][0], ah[0][1], ah[0][2], ah[0][3], b0, b1);
            mma_fp(acc[1][nt], ah[1][0], ah[1][1], ah[1][2], ah[1][3], b0, b1);
        }
#pragma unroll
        for (int nt = 0; nt < NT; nt++) {           // term 2: ah * wl (a cached)
            const u16* wq = Wl + (nbase + nt * 8 + g) * wstr + k0 + q * 2;
            u32 b0 = *(const u32*)(wq);
            u32 b1 = *(const u32*)(wq + 8);
            mma_fp(acc[0][nt], ah[0][0], ah[0][1], ah[0][2], ah[0][3], b0, b1);
            mma_fp(acc[1][nt], ah[1][0], ah[1][1], ah[1][2], ah[1][3], b0, b1);
        }
    }
}

// ---------------- main kernel ----------------
// SMEM: L1 stages @0, @41472 (Ah 18432 | W1 23040 each; end 82944, dead before H1).
// H1 image (fp16 hi only): chunk0 @0 [128][72], chunk1 @36864 [128][72], chunk2 @73728 [128][40].
// WB @98304 (73728 B region: W2 batch 47104 or W3 batch 55296).
// H2 image (fp16 hi only) @ {0, 36864}. misc @172032.
#define SSTG  41472
#define WB    98304
#define MISCO 172032
#define SMEMB (MISCO + 4096)

__global__ void __launch_bounds__(THREADS, 1) k_main(
    const float* __restrict__ b1, const float* __restrict__ b2,
    const float* __restrict__ b3, const float* __restrict__ W4,
    const float* __restrict__ b4)
{
    extern __shared__ __align__(16) unsigned char sm[];
    const int s = blockIdx.y, t = blockIdx.x, z = blockIdx.z, tid = threadIdx.x;
    const int cnt = g_count[s];
    const int ntl = (cnt + TM - 1) / TM;
    if (t >= ntl) return;
    const int nvalid = min(TM, cnt - t * TM);
    const int gt = g_tbase[s] + t;
    const int lane = tid & 31, w = tid >> 5;
    const int wm = w & 3, wn = w >> 2, g = lane >> 2, q = lane & 3;
    const int mbase = wm * 32;
    const u32 sb = s2u(sm);
    float* b1s = (float*)(sm + MISCO);
    float* b2s = b1s + 160;
    float* b3s = b2s + 128;
    float* w4s = b3s + 96;
    float* part = w4s + 96;

    const unsigned char* Ab = g_Aimg + (size_t)gt * ASE;
    float blockSum = 0.f;

    const int h1off[3] = {0, 36864, 73728};
    const int h1str[3] = {72, 72, 40};
    const int w2off[3] = {0, 18432, 36864};
    const int w2str[3] = {72, 72, 40};
    const int w2ks[3]  = {4, 4, 2};

    for (int ei = 0; ei < 2; ei++) {
        const int se = s * E_ + z * 2 + ei;
        const unsigned char* Wb = g_Wimg + (size_t)se * WSE;
        if (tid < 160) b1s[tid] = b1[se * H1_ + tid];
        if (tid < 128) b2s[tid] = b2[se * H2_ + tid];
        if (tid < 96) { b3s[tid] = b3[se * H3_ + tid]; w4s[tid] = W4[se * H3_ + tid]; }

        auto cpyW = [&](const unsigned char* src, int bytes, u32 dstoff) {
            for (int i = tid * 16; i < bytes; i += THREADS * 16) CPA16(sb + dstoff + i, src + i);
            CPCOMMIT();
        };

        // ========= Layer 1 (K=384, N=160): fp16 single-term, NT=5 per warp =========
        float acc1[2][5][4];
#pragma unroll
        for (int a = 0; a < 2; a++)
#pragma unroll
            for (int b = 0; b < 5; b++)
#pragma unroll
                for (int c = 0; c < 4; c++) acc1[a][b][c] = 0.f;

        auto cpyL1 = [&](int c, int bf) {
            u32 dst = sb + (bf ? SSTG : 0);
            const unsigned char* gA = Ab + c * ACH;            // hi half only
            for (int i = tid * 16; i < 18432; i += THREADS * 16) CPA16(dst + i, gA + i);
            const unsigned char* gW = Wb + W1OFF + c * 23040;
            for (int i = tid * 16; i < 23040; i += THREADS * 16) CPA16(dst + 18432 + i, gW + i);
            CPCOMMIT();
        };
        cpyL1(0, 0); cpyL1(1, 1);
        for (int kc = 0; kc < 6; kc++) {
            if (kc == 5) { CPWAIT(0); } else { CPWAIT(1); }
            __syncthreads();
            const unsigned char* st = sm + ((kc & 1) ? SSTG : 0);
            chunk_mma1<5>(acc1, (const u16*)st, 72,
                          (const u16*)(st + 18432), 72,
                          4, mbase, wn * 40, g, q);
            __syncthreads();
            if (kc < 4) cpyL1(kc + 2, kc & 1);
        }
        // single batch copy of ALL W2 chunks (47104 B) — overlaps with L1 epilogue
        cpyW(Wb + W2OFF, 47104, WB);

        // epilogue -> H1 (fp16 hi only)
#pragma unroll
        for (int mt = 0; mt < 2; mt++)
#pragma unroll
            for (int nt = 0; nt < 5; nt++) {
                int n0 = wn * 40 + nt * 8 + q * 2;
                int cb = n0 >> 6, off = n0 & 63;
                u16* Hh = (u16*)(sm + h1off[cb]);
                int str = h1str[cb];
                int row = mbase + mt * 16 + g;
                *(u32*)(Hh + row * str + off) =
                    packh(celu_f(acc1[mt][nt][0] + b1s[n0]),
                          celu_f(acc1[mt][nt][1] + b1s[n0 + 1]));
                *(u32*)(Hh + (row + 8) * str + off) =
                    packh(celu_f(acc1[mt][nt][2] + b1s[n0]),
                          celu_f(acc1[mt][nt][3] + b1s[n0 + 1]));
            }
        CPWAIT(0);
        __syncthreads();

        // ========= Layer 2 (K=160, N=128): fp16 single-term, NT=4 =========
        float acc2[2][4][4];
#pragma unroll
        for (int a = 0; a < 2; a++)
#pragma unroll
            for (int b = 0; b < 4; b++)
#pragma unroll
                for (int c = 0; c < 4; c++) acc2[a][b][c] = 0.f;

        for (int kc = 0; kc < 3; kc++) {
            chunk_mma1<4>(acc2,
                          (const u16*)(sm + h1off[kc]), h1str[kc],
                          (const u16*)(sm + WB + w2off[kc]), w2str[kc],
                          w2ks[kc], mbase, wn * 32, g, q);
        }
        __syncthreads();
        // single batch copy of ALL W3 chunks (55296 B) — overlaps with L2 epilogue
        cpyW(Wb + W3OFF, 55296, WB);

        // epilogue -> H2 (fp16 hi only @ {0, 36864})
#pragma unroll
        for (int mt = 0; mt < 2; mt++)
#pragma unroll
            for (int nt = 0; nt < 4; nt++) {
                int n0 = wn * 32 + nt * 8 + q * 2;
                int cb = n0 >> 6, off = n0 & 63;
                u16* Hh = (u16*)(sm + cb * 36864);
                int row = mbase + mt * 16 + g;
                *(u32*)(Hh + row * 72 + off) =
                    packh(celu_f(acc2[mt][nt][0] + b2s[n0]),
                          celu_f(acc2[mt][nt][1] + b2s[n0 + 1]));
                *(u32*)(Hh + (row + 8) * 72 + off) =
                    packh(celu_f(acc2[mt][nt][2] + b2s[n0]),
                          celu_f(acc2[mt][nt][3] + b2s[n0 + 1]));
            }
        CPWAIT(0);
        __syncthreads();

        // ========= Layer 3 (K=128, N=96): fp16 2-term-W, NT=3 =========
        float acc3[2][3][4];
#pragma unroll
        for (int a = 0; a < 2; a++)
#pragma unroll
            for (int b = 0; b < 3; b++)
#pragma unroll
                for (int c = 0; c < 4; c++) acc3[a][b][c] = 0.f;

        for (int kc = 0; kc < 2; kc++) {
            const unsigned char* wb = sm + WB + kc * 27648;
            chunk_mma_w2<3>(acc3,
                            (const u16*)(sm + kc * 36864), 72,
                            (const u16*)wb, (const u16*)wb + 6912, 72,
                            4, mbase, wn * 24, g, q);
        }
        // ========= fused L3-epilogue + Layer 4 =========
        {
            float p00 = 0.f, p01 = 0.f, p10 = 0.f, p11 = 0.f;
#pragma unroll
            for (int nt = 0; nt < 3; nt++) {
                int n0 = wn * 24 + nt * 8 + q * 2;
                float w0 = w4s[n0], w1 = w4s[n0 + 1];
                float bb0 = b3s[n0], bb1 = b3s[n0 + 1];
                p00 += celu_f(acc3[0][nt][0] + bb0) * w0 + celu_f(acc3[0][nt][1] + bb1) * w1;
                p01 += celu_f(acc3[0][nt][2] + bb0) * w0 + celu_f(acc3[0][nt][3] + bb1) * w1;
                p10 += celu_f(acc3[1][nt][0] + bb0) * w0 + celu_f(acc3[1][nt][1] + bb1) * w1;
                p11 += celu_f(acc3[1][nt][2] + bb0) * w0 + celu_f(acc3[1][nt][3] + bb1) * w1;
            }
            p00 += __shfl_xor_sync(0xffffffffu, p00, 1); p00 += __shfl_xor_sync(0xffffffffu, p00, 2);
            p01 += __shfl_xor_sync(0xffffffffu, p01, 1); p01 += __shfl_xor_sync(0xffffffffu, p01, 2);
            p10 += __shfl_xor_sync(0xffffffffu, p10, 1); p10 += __shfl_xor_sync(0xffffffffu, p10, 2);
            p11 += __shfl_xor_sync(0xffffffffu, p11, 1); p11 += __shfl_xor_sync(0xffffffffu, p11, 2);
            if (q == 0) {
                part[wn * 128 + mbase + g]          = p00;
                part[wn * 128 + mbase + g + 8]      = p01;
                part[wn * 128 + mbase + 16 + g]     = p10;
                part[wn * 128 + mbase + 16 + g + 8] = p11;
            }
        }
        __syncthreads();
        if (tid < 128) {
            float en = part[tid] + part[128 + tid] + part[256 + tid] + part[384 + tid] + b4[se];
            part[tid] = (tid < nvalid) ? en : 0.f;
        }
        __syncthreads();
        if (tid < 32) {
            float v = part[tid] + part[tid + 32] + part[tid + 64] + part[tid + 96];
            for (int o = 16; o; o >>= 1) v += __shfl_down_sync(0xffffffffu, v, o);
            if (tid == 0) blockSum += v;
        }
        __syncthreads();
    }
    if (tid == 0) g_partial[(s * NTT + t) * 4 + z] = blockSum;
}

// ---------------- final reduction ----------------
__global__ void k_reduce(float* out) {
    __shared__ double sb[256];
    int tid = threadIdx.x;
    double s = 0.0;
    for (int i = tid; i < NPART; i += 256) s += (double)g_partial[i];
    sb[tid] = s;
    __syncthreads();
    for (int st = 128; st; st >>= 1) {
        if (tid < st) sb[tid] += sb[tid + st];
        __syncthreads();
    }
    if (tid == 0) out[0] = (float)(sb[0] * (1.0 / E_));
}

// ---------------- launch ----------------
extern "C" void kernel_launch(void* const* d_in, const int* in_sizes, int n_in,
                              void* d_out, int out_size)
{
    const void*  sp  = d_in[0];
    const float* aev = (const float*)d_in[1];
    const float* W1  = (const float*)d_in[2];
    const float* b1  = (const float*)d_in[3];
    const float* W2  = (const float*)d_in[4];
    const float* b2  = (const float*)d_in[5];
    const float* W3  = (const float*)d_in[6];
    const float* b3  = (const float*)d_in[7];
    const float* W4  = (const float*)d_in[8];
    const float* b4  = (const float*)d_in[9];

    cudaFuncSetAttribute(k_main, cudaFuncAttributeMaxDynamicSharedMemorySize, SMEMB);

    k_init<<<1, 256>>>((const ull*)sp);
    k_count<<<NB, 256>>>((const int*)sp);
    k_scan<<<1, 256>>>();
    k_scatter<<<NB, 256>>>((const int*)sp);
    dim3 gw(32, 8);
    k_wprep<<<gw, 256>>>(W1, W2, W3);
    dim3 ga(NTT, S_);
    k_aprep<<<ga, 256>>>(aev);
    dim3 gm(NTT, S_, 4);
    k_main<<<gm, THREADS, SMEMB>>>(b1, b2, b3, W4, b4);
    k_reduce<<<1, 256>>>((float*)d_out);
}